// round 13
// baseline (speedup 1.0000x reference)
#include <cuda_runtime.h>
#include <cuda_fp16.h>
#include <math.h>
#include <stdint.h>

#define B_   2
#define N_   6
#define FH_  32
#define FW_  88
#define PIX  (FH_*FW_)     // 2816
#define D_   128
#define NKV  264
#define NQ1  384
#define NPX  (B_*N_*PIX)   // 33792
#define NQP  (B_*N_*4096)  // 49152
#define NTK  (B_*4096)     // 8192

// epilogue modes
#define EPI_HALF  0
#define EPI_GELU  1
#define EPI_LN    2
#define EPI_SKLN0 3
#define EPI_SKLN1 4
#define EPI_RESLN 5
#define EPI_FIN   6

// ---------------- scratch globals (no runtime allocation) -------------------
__device__ __align__(16) __half g_fph[NPX*D_];
__device__ __align__(16) __half g_flh[NPX*D_];
__device__ __align__(16) __half g_kimgh[NPX*D_];
__device__ __align__(16) __half g_xq [NQP*D_];
__device__ __align__(16) __half g_xk [NPX*D_];
__device__ __align__(16) __half g_xv [NPX*D_];
__device__ __align__(16) __half g_xq1[NTK*D_];
__device__ __align__(16) __half g_xm [NTK*D_];
__device__ __align__(16) __half g_wfold[6*D_*D_];
__device__ float  g_bfold[6*D_];
__device__ __align__(16) __half g_wafold[2*256*D_];
__device__ float  g_bafold[2*256];
__device__ __align__(16) __half g_wmbT[2*D_*256];
__device__ __align__(16) __half g_wpT[2*D_*D_];
__device__ __align__(16) __half g_wfpH[D_*D_];
__device__ __align__(16) __half g_wflH[D_*D_];
__device__ __align__(16) __half g_qh1[NQP*D_];
__device__ __align__(16) __half g_kh1[NPX*D_];
__device__ __align__(16) __half g_vh1[NPX*D_];
__device__ __align__(16) __half g_qh2[NTK*D_];
__device__ __align__(16) __half g_kh2[NPX*D_];
__device__ __align__(16) __half g_vh2[NPX*D_];
__device__ __align__(16) __half g_otok[B_*64*NQ1*D_];
__device__ __align__(16) __half g_o2[NTK*D_];
__device__ __align__(16) __half g_h[NTK*256];
__device__ __align__(16) float  g_q1[NTK*D_];
__device__ __align__(16) float  g_q2[NTK*D_];

__device__ __forceinline__ void warpRed2(float& s, float& q) {
#pragma unroll
    for (int o = 16; o; o >>= 1) {
        s += __shfl_xor_sync(0xffffffffu, s, o);
        q += __shfl_xor_sync(0xffffffffu, q, o);
    }
}

__device__ __forceinline__ void st_half4(__half* dst, float a, float b, float c, float d) {
    __half2* p = reinterpret_cast<__half2*>(dst);
    p[0] = __floats2half2_rn(a, b);
    p[1] = __floats2half2_rn(c, d);
}

__device__ __forceinline__ uint32_t packh2(float a, float b) {
    __half2 h = __floats2half2_rn(a, b);
    return *reinterpret_cast<uint32_t*>(&h);
}

__device__ __forceinline__ float geluf(float h) {
    return h * 0.5f * (1.0f + erff(h * 0.70710678118654752f));
}

__device__ __forceinline__ void mma16816(float* c, const uint32_t* a,
                                         uint32_t b0, uint32_t b1) {
    asm volatile(
        "mma.sync.aligned.m16n8k16.row.col.f32.f16.f16.f32 "
        "{%0,%1,%2,%3}, {%4,%5,%6,%7}, {%8,%9}, {%0,%1,%2,%3};\n"
        : "+f"(c[0]), "+f"(c[1]), "+f"(c[2]), "+f"(c[3])
        : "r"(a[0]), "r"(a[1]), "r"(a[2]), "r"(a[3]), "r"(b0), "r"(b1));
}

__device__ __forceinline__ void cpa16(void* smem, const void* gmem) {
    uint32_t sa = (uint32_t)__cvta_generic_to_shared(smem);
    asm volatile("cp.async.cg.shared.global [%0], [%1], 16;\n" :: "r"(sa), "l"(gmem));
}

// ---------------- merged weight prep (one launch, block-range dispatch) ------
__global__ void __launch_bounds__(256) k_wprep(
        const float* __restrict__ aln_g, const float* __restrict__ aln_b,
        const float* __restrict__ aWqkv, const float* __restrict__ abqkv,
        const float* __restrict__ pn_g, const float* __restrict__ pn_b,
        const float* __restrict__ Wma, const float* __restrict__ bma,
        const float* __restrict__ aWp, const float* __restrict__ Wmb,
        const float* __restrict__ W_fp, const float* __restrict__ W_fl) {
    __shared__ float sm[16][129];
    __shared__ float bred[16][17];
    int blk = blockIdx.x, tid = threadIdx.x;
    if (blk < 48) {
        int idx = blk >> 3, o0 = (blk & 7) * 16;
        const float* W = aWqkv + idx*16384;
        const float* g = aln_g + idx*128;
        const float* bb = aln_b + idx*128;
        for (int k = tid; k < 2048; k += 256) {
            int c = k >> 4, o = k & 15;
            sm[o][c] = g[c] * W[c*128 + o0 + o];
        }
        {
            int o = tid & 15, cg = tid >> 4;
            float part = 0.f;
#pragma unroll
            for (int cc = 0; cc < 8; cc++) {
                int c = cg*8 + cc;
                part += bb[c] * W[c*128 + o0 + o];
            }
            bred[o][cg] = part;
        }
        __syncthreads();
        for (int k = tid; k < 1024; k += 256) {
            int o = k >> 6, c2 = (k & 63)*2;
            *reinterpret_cast<__half2*>(&g_wfold[idx*16384 + (o0+o)*128 + c2]) =
                __floats2half2_rn(sm[o][c2], sm[o][c2+1]);
        }
        if (tid < 16) {
            float a = 0.f;
#pragma unroll
            for (int cg = 0; cg < 16; cg++) a += bred[tid][cg];
            g_bfold[idx*128 + o0 + tid] = a + abqkv[idx*128 + o0 + tid];
        }
    } else if (blk < 80) {
        int t = blk - 48;
        int s = t >> 4, o0 = (t & 15) * 16;
        const float* W = Wma + s*128*256;
        const float* g = pn_g + s*128;
        const float* bb = pn_b + s*128;
        for (int k = tid; k < 2048; k += 256) {
            int c = k >> 4, o = k & 15;
            sm[o][c] = g[c] * W[c*256 + o0 + o];
        }
        {
            int o = tid & 15, cg = tid >> 4;
            float part = 0.f;
#pragma unroll
            for (int cc = 0; cc < 8; cc++) {
                int c = cg*8 + cc;
                part += bb[c] * W[c*256 + o0 + o];
            }
            bred[o][cg] = part;
        }
        __syncthreads();
        for (int k = tid; k < 1024; k += 256) {
            int o = k >> 6, c2 = (k & 63)*2;
            *reinterpret_cast<__half2*>(&g_wafold[s*32768 + (o0+o)*128 + c2]) =
                __floats2half2_rn(sm[o][c2], sm[o][c2+1]);
        }
        if (tid < 16) {
            float a = 0.f;
#pragma unroll
            for (int cg = 0; cg < 16; cg++) a += bred[tid][cg];
            g_bafold[s*256 + o0 + tid] = a + bma[s*256 + o0 + tid];
        }
    } else if (blk < 176) {
        int t = blk - 80;
        const float* src; __half* dst; int R, C, bx, by;
        if (t < 16)      { src = aWp;          dst = g_wpT;          R=128; C=128; bx=t&3;      by=t>>2; }
        else if (t < 32) { src = aWp+16384;    dst = g_wpT+16384;    R=128; C=128; bx=(t-16)&3; by=(t-16)>>2; }
        else if (t < 64) { src = Wmb;          dst = g_wmbT;         R=256; C=128; bx=(t-32)&3; by=(t-32)>>2; }
        else             { src = Wmb+32768;    dst = g_wmbT+32768;   R=256; C=128; bx=(t-64)&3; by=(t-64)>>2; }
        float (*tb)[33] = reinterpret_cast<float(*)[33]>(&sm[0][0]);
        int c0 = bx*32, r0 = by*32;
        int cx = tid & 31, ry = tid >> 5;
        for (int rr = ry; rr < 32; rr += 8)
            tb[rr][cx] = src[(r0+rr)*C + c0 + cx];
        __syncthreads();
        for (int cc = ry; cc < 32; cc += 8)
            dst[(c0+cc)*R + r0 + cx] = __float2half(tb[cx][cc]);
    } else {
        int t = blk - 176;
        const float* src = (t < 64) ? W_fp : W_fl;
        __half* dst = (t < 64) ? g_wfpH : g_wflH;
        int i = (t & 63)*256 + tid;
        dst[i] = __float2half(src[i]);
    }
}

// ---------------- prep: BN-ReLU fp16 feats + image embedding -----------------
__global__ void __launch_bounds__(128) k_prep(
        const float* __restrict__ feat,
        const float* __restrict__ I_inv, const float* __restrict__ E_inv,
        const float* __restrict__ W_img, const float* __restrict__ W_cam,
        const float* __restrict__ fp_g, const float* __restrict__ fp_b,
        const float* __restrict__ fl_g, const float* __restrict__ fl_b) {
    extern __shared__ float sh[];
    float* sfp  = sh;                 // [128][33]
    float* sfl  = sh + 128*33;
    float* kimg = sh + 2*128*33;      // [32][128]
    int blk = blockIdx.x, tid = threadIdx.x;
    int bn = blk / 88, p0 = (blk % 88) * 32;
    int warp = tid >> 5, lane = tid & 31;

    const float invs = rsqrtf(1.0f + 1e-5f);
    for (int k = tid; k < 4096; k += 128) {
        int c = k >> 5, pp = k & 31;
        float f = feat[(bn*D_ + c)*PIX + p0 + pp];
        sfp[c*33+pp] = fmaxf(f * invs * fp_g[c] + fp_b[c], 0.f);
        sfl[c*33+pp] = fmaxf(f * invs * fl_g[c] + fl_b[c], 0.f);
    }
    float e3[4];
#pragma unroll
    for (int i = 0; i < 4; i++) e3[i] = E_inv[bn*16 + i*4 + 3];
    for (int it = 0; it < 8; it++) {
        int tt = it*4 + warp;
        int p = p0 + tt, fh = p / FW_, fw = p % FW_;
        float px = (float)fw * (480.0f / 87.0f);
        float py = (float)fh * (224.0f / 31.0f);
        float cam[4];
#pragma unroll
        for (int i = 0; i < 3; i++)
            cam[i] = I_inv[bn*9+i*3+0]*px + I_inv[bn*9+i*3+1]*py + I_inv[bn*9+i*3+2];
        cam[3] = 1.0f;
        float dd[4];
#pragma unroll
        for (int i = 0; i < 4; i++)
            dd[i] = E_inv[bn*16+i*4+0]*cam[0] + E_inv[bn*16+i*4+1]*cam[1]
                  + E_inv[bn*16+i*4+2]*cam[2] + E_inv[bn*16+i*4+3]*cam[3];
        int c0 = lane*4;
        float t[4]; float ssum = 0.f, dum = 0.f;
#pragma unroll
        for (int i = 0; i < 4; i++) {
            int c = c0+i;
            float de = W_img[c*4+0]*dd[0] + W_img[c*4+1]*dd[1]
                     + W_img[c*4+2]*dd[2] + W_img[c*4+3]*dd[3];
            float ce = W_cam[c*4+0]*e3[0] + W_cam[c*4+1]*e3[1]
                     + W_cam[c*4+2]*e3[2] + W_cam[c*4+3]*e3[3];
            t[i] = de - ce;
            ssum += t[i]*t[i];
        }
        warpRed2(ssum, dum);
        float inv = 1.0f / fmaxf(sqrtf(ssum), 1e-12f);
#pragma unroll
        for (int i = 0; i < 4; i++) kimg[tt*128 + c0 + i] = t[i]*inv;
    }
    __syncthreads();
    for (int pp = 0; pp < 32; pp++) {
        int row = bn*PIX + p0 + pp;
        g_fph[row*D_ + tid] = __float2half(sfp[tid*33 + pp]);
        g_flh[row*D_ + tid] = __float2half(sfl[tid*33 + pp]);
        g_kimgh[row*D_ + tid] = __float2half(kimg[pp*128 + tid]);
    }
}

// ---------------- query -> LN'd fp16 xhat, warp per pixel --------------------
__global__ void __launch_bounds__(256) k_query(
        const float* __restrict__ grid, const float* __restrict__ x,
        const float* __restrict__ W_bev, const float* __restrict__ b_bev,
        const float* __restrict__ E_inv, const float* __restrict__ W_cam) {
    int tid = threadIdx.x, warp = tid >> 5, lane = tid & 31;
    int u = blockIdx.x*8 + warp;
    int bn = u >> 12, p = u & 4095;
    int b = bn / N_;
    int c0 = lane*4;
    float e3[4];
#pragma unroll
    for (int i = 0; i < 4; i++) e3[i] = E_inv[bn*16 + i*4 + 3];
    float gx = grid[p], gy = grid[4096 + p];
    float t[4]; float ss = 0.f, dum = 0.f;
#pragma unroll
    for (int i = 0; i < 4; i++) {
        int c = c0 + i;
        float we = W_bev[c*2+0]*gx + W_bev[c*2+1]*gy + b_bev[c];
        float ce = W_cam[c*4+0]*e3[0] + W_cam[c*4+1]*e3[1]
                 + W_cam[c*4+2]*e3[2] + W_cam[c*4+3]*e3[3];
        t[i] = we - ce;
        ss += t[i]*t[i];
    }
    warpRed2(ss, dum);
    float inv = 1.0f / fmaxf(sqrtf(ss), 1e-12f);
    float q[4]; float s = 0.f, q2 = 0.f;
#pragma unroll
    for (int i = 0; i < 4; i++) {
        q[i] = t[i]*inv + x[(b*D_ + c0 + i)*4096 + p];
        s += q[i]; q2 += q[i]*q[i];
    }
    warpRed2(s, q2);
    float mean = s*(1.0f/128.0f);
    float var = fmaxf(q2*(1.0f/128.0f) - mean*mean, 0.f);
    float rstd = rsqrtf(var + 1e-5f);
    st_half4(&g_xq[u*D_ + c0],
             (q[0]-mean)*rstd, (q[1]-mean)*rstd, (q[2]-mean)*rstd, (q[3]-mean)*rstd);
}

// ---------------- device-side job table for the unified GEMM -----------------
__device__ __forceinline__ void gemm_job(
        int job, const float* extb,
        const __half*& A, const __half*& B, const float*& bias,
        __half*& oh, float*& of, const float*& aux, const __half*& auxh,
        int& epi, float& scale, int& ldC) {
    const float QS = 0.17677669529663687f;
    scale = 1.f; ldC = 128; aux = nullptr; auxh = nullptr;
    bias = nullptr; oh = nullptr; of = nullptr;
    switch (job) {
    case 0:  A=g_fph; B=g_wfpH; oh=g_xk; auxh=g_kimgh; epi=EPI_LN; break;
    case 1:  A=g_flh; B=g_wflH; oh=g_xv; epi=EPI_LN; break;
    case 2:  A=g_xq;  B=g_wfold;          bias=g_bfold;     oh=g_qh1; epi=EPI_HALF; scale=QS; break;
    case 3:  A=g_xk;  B=g_wfold+16384;    bias=g_bfold+128; oh=g_kh1; epi=EPI_HALF; break;
    case 4:  A=g_xv;  B=g_wfold+2*16384;  bias=g_bfold+256; oh=g_vh1; epi=EPI_HALF; break;
    case 5:  A=g_xk;  B=g_wfold+4*16384;  bias=g_bfold+512; oh=g_kh2; epi=EPI_HALF; break;
    case 6:  A=g_xv;  B=g_wfold+5*16384;  bias=g_bfold+640; oh=g_vh2; epi=EPI_HALF; break;
    case 7:  A=nullptr; B=g_wpT; bias=extb; of=g_q1; oh=g_xm; epi=EPI_SKLN0; break;
    case 8:  A=g_xm;  B=g_wafold;         bias=g_bafold;     oh=g_h;     epi=EPI_GELU; ldC=256; break;
    case 9:  A=g_xm;  B=g_wafold+16384;   bias=g_bafold+128; oh=g_h+128; epi=EPI_GELU; ldC=256; break;
    case 10: A=g_h;   B=g_wmbT; bias=extb; of=g_q1; oh=g_xq1; aux=g_q1; epi=EPI_RESLN; break;
    case 11: A=g_xq1; B=g_wfold+3*16384;  bias=g_bfold+384; oh=g_qh2; epi=EPI_HALF; scale=QS; break;
    case 12: A=g_o2;  B=g_wpT+16384; bias=extb; of=g_q2; oh=g_xm; aux=g_q1; epi=EPI_SKLN1; break;
    case 13: A=g_xm;  B=g_wafold+32768;        bias=g_bafold+256; oh=g_h;     epi=EPI_GELU; ldC=256; break;
    case 14: A=g_xm;  B=g_wafold+32768+16384;  bias=g_bafold+384; oh=g_h+128; epi=EPI_GELU; ldC=256; break;
    default: A=g_h;   B=g_wmbT+32768; bias=extb; aux=g_q2; epi=EPI_FIN; break;
    }
}

// ---------------- unified HMMA GEMM with fused epilogues ---------------------
// C[64][128] per block = A[64][KT*128] @ B[128][KT*128]^T (+ epilogue).
// 256 thr, 8 warps as 2(m) x 4(n); warp tile 32x32.
template<int KT>
__global__ void __launch_bounds__(256, 4) k_gemm_ep(
        int jobsel, const float* __restrict__ extb,
        const float* __restrict__ extg, const float* __restrict__ extbt,
        const float* __restrict__ extaux, float* __restrict__ extout) {
    int job, tile;
    if (jobsel < 100)       { job = jobsel; tile = blockIdx.x; }
    else if (jobsel == 100) { job = blockIdx.x / 528; tile = blockIdx.x % 528; }
    else if (jobsel == 101) {
        int bx = blockIdx.x;
        if (bx < 768) { job = 2; tile = bx; }
        else { int r = bx - 768; job = 3 + r/528; tile = r % 528; }
    }
    else if (jobsel == 102) { job = 8 + (blockIdx.x >> 7); tile = blockIdx.x & 127; }
    else                    { job = 13 + (blockIdx.x >> 7); tile = blockIdx.x & 127; }

    const __half* A; const __half* Bw; const float* bias;
    __half* oh; float* of; const float* aux; const __half* auxh;
    int epi; float scale; int ldC;
    gemm_job(job, extb, A, Bw, bias, oh, of, aux, auxh, epi, scale, ldC);
    if (epi == EPI_SKLN0) aux = extaux;

    extern __shared__ __half shh[];
    __half* As = shh;                 // [64][136]
    __half* Bs = shh + 64*136;        // [128][136]
    int tid = threadIdx.x;
    int m0 = tile * 64;
    const int KD = KT*128;
    int warp = tid >> 5, lane = tid & 31;
    int wm = (warp & 1) * 32, wn = (warp >> 1) * 32;
    int g = lane >> 2, tg = (lane & 3) * 2;
    float acc[2][4][4];
#pragma unroll
    for (int i = 0; i < 2; i++)
#pragma unroll
        for (int j = 0; j < 4; j++)
#pragma unroll
            for (int r = 0; r < 4; r++) acc[i][j][r] = 0.f;

    for (int kc = 0; kc < KT; kc++) {
        int r = tid >> 4, q = tid & 15;
        if (job == 7) {
            for (int rr = r; rr < 64; rr += 16) {
                int row = m0 + rr;
                int b = row >> 12, p = row & 4095;
                int hh_ = p >> 6, ww = p & 63;
                int l = ((hh_ >> 3) << 3) + (ww >> 3);
                const __half* src = g_otok + ((b*64 + l)*NQ1 + (hh_&7)*8 + (ww&7))*D_ + q*8;
                float s[8];
#pragma unroll
                for (int t = 0; t < 8; t++) s[t] = 0.f;
#pragma unroll
                for (int n = 0; n < 6; n++) {
                    const __half2* pp = reinterpret_cast<const __half2*>(src + n*64*D_);
#pragma unroll
                    for (int t = 0; t < 4; t++) {
                        float2 f = __half22float2(pp[t]);
                        s[t*2] += f.x; s[t*2+1] += f.y;
                    }
                }
                __half2 o[4];
#pragma unroll
                for (int t = 0; t < 4; t++)
                    o[t] = __floats2half2_rn(s[t*2]*(1.f/6.f), s[t*2+1]*(1.f/6.f));
                *reinterpret_cast<int4*>(&As[rr*136 + q*8]) = *reinterpret_cast<int4*>(o);
            }
#pragma unroll
            for (int rr = r; rr < 128; rr += 16)
                cpa16(&Bs[rr*136 + q*8], &Bw[rr*KD + q*8]);
        } else {
#pragma unroll
            for (int rr = r; rr < 64; rr += 16)
                cpa16(&As[rr*136 + q*8], &A[(m0+rr)*KD + kc*128 + q*8]);
#pragma unroll
            for (int rr = r; rr < 128; rr += 16)
                cpa16(&Bs[rr*136 + q*8], &Bw[rr*KD + kc*128 + q*8]);
        }
        asm volatile("cp.async.commit_group;\n");
        asm volatile("cp.async.wait_group 0;\n");
        __syncthreads();
#pragma unroll
        for (int ks = 0; ks < 8; ks++) {
            int k0 = ks*16;
            uint32_t a[2][4];
#pragma unroll
            for (int i = 0; i < 2; i++) {
                int mb = wm + i*16;
                a[i][0] = *reinterpret_cast<const uint32_t*>(&As[(mb+g  )*136 + k0+tg  ]);
                a[i][1] = *reinterpret_cast<const uint32_t*>(&As[(mb+8+g)*136 + k0+tg  ]);
                a[i][2] = *reinterpret_cast<const uint32_t*>(&As[(mb+g  )*136 + k0+8+tg]);
                a[i][3] = *reinterpret_cast<const uint32_t*>(&As[(mb+8+g)*136 + k0+8+tg]);
            }
#pragma unroll
            for (int j = 0; j < 4; j++) {
                uint32_t b0 = *reinterpret_cast<const uint32_t*>(&Bs[(wn+j*8+g)*136 + k0+tg  ]);
                uint32_t b1 = *reinterpret_cast<const uint32_t*>(&Bs[(wn+j*8+g)*136 + k0+8+tg]);
                mma16816(acc[0][j], a[0], b0, b1);
                mma16816(acc[1][j], a[1], b0, b1);
            }
        }
        __syncthreads();
    }

    if (epi <= EPI_GELU) {
#pragma unroll
        for (int i = 0; i < 2; i++)
#pragma unroll
        for (int j = 0; j < 4; j++) {
            int n = wn + j*8 + tg;
            float b0 = bias[n], b1 = bias[n+1];
            int r0 = m0 + wm + i*16 + g, r1 = r0 + 8;
            float v0 = acc[i][j][0]+b0, v1 = acc[i][j][1]+b1;
            float v2 = acc[i][j][2]+b0, v3 = acc[i][j][3]+b1;
            if (epi == EPI_GELU) {
                v0 = geluf(v0); v1 = geluf(v1); v2 = geluf(v2); v3 = geluf(v3);
            } else {
                v0 *= scale; v1 *= scale; v2 *= scale; v3 *= scale;
            }
            *reinterpret_cast<uint32_t*>(&oh[r0*ldC + n]) = packh2(v0, v1);
            *reinterpret_cast<uint32_t*>(&oh[r1*ldC + n]) = packh2(v2, v3);
        }
    } else {
#pragma unroll
        for (int i = 0; i < 2; i++)
#pragma unroll
        for (int j = 0; j < 4; j++) {
            int n = wn + j*8 + tg;
            int r0 = m0 + wm + i*16 + g, r1 = r0 + 8;
            if (bias) {
                float b0 = bias[n], b1 = bias[n+1];
                acc[i][j][0] += b0; acc[i][j][1] += b1;
                acc[i][j][2] += b0; acc[i][j][3] += b1;
            }
            if (auxh) {
                acc[i][j][0] += __half2float(auxh[r0*D_ + n]);
                acc[i][j][1] += __half2float(auxh[r0*D_ + n+1]);
                acc[i][j][2] += __half2float(auxh[r1*D_ + n]);
                acc[i][j][3] += __half2float(auxh[r1*D_ + n+1]);
            }
            if (aux) {
                if (epi == EPI_SKLN0) {
                    int ba = r0 >> 12, pa = r0 & 4095;
                    int bb_ = r1 >> 12, pb = r1 & 4095;
                    acc[i][j][0] += aux[(ba*D_ + n  )*4096 + pa];
                    acc[i][j][1] += aux[(ba*D_ + n+1)*4096 + pa];
                    acc[i][j][2] += aux[(bb_*D_ + n  )*4096 + pb];
                    acc[i][j][3] += aux[(bb_*D_ + n+1)*4096 + pb];
                } else {
                    acc[i][j][0] += aux[r0*D_ + n];
                    acc[i][j][1] += aux[r0*D_ + n+1];
                    acc[i][j][2] += aux[r1*D_ + n];
                    acc[i][j][3] += aux[r1*D_ + n+1];
                }
            }
            if (of) {
                of[r0*D_ + n]   = acc[i][j][0];
                of[r0*D_ + n+1] = acc[i][j][1];
                of[r1*D_ + n]   = acc[i][j][2];
                of[r1*D_ + n+1] = acc[i][j][3];
            }
        }
        float sum[2][2] = {{0,0},{0,0}}, sq[2][2] = {{0,0},{0,0}};
#pragma unroll
        for (int i = 0; i < 2; i++)
#pragma unroll
        for (int j = 0; j < 4; j++) {
            float a0 = acc[i][j][0], a1 = acc[i][j][1];
            float a2 = acc[i][j][2], a3 = acc[i][j][3];
            sum[i][0] += a0 + a1; sq[i][0] += a0*a0 + a1*a1;
            sum[i][1] += a2 + a3; sq[i][1] += a2*a2 + a3*a3;
        }
#pragma unroll
        for (int o = 1; o <= 2; o <<= 1) {
#pragma unroll
            for (int i = 0; i < 2; i++)
#pragma unroll
            for (int rh = 0; rh < 2; rh++) {
                sum[i][rh] += __shfl_xor_sync(0xffffffffu, sum[i][rh], o);
                sq[i][rh]  += __shfl_xor_sync(0xffffffffu, sq[i][rh], o);
            }
        }
        float* sred = reinterpret_cast<float*>(shh);   // [64][8]
        if ((lane & 3) == 0) {
#pragma unroll
            for (int i = 0; i < 2; i++)
#pragma unroll
            for (int rh = 0; rh < 2; rh++) {
                int row = wm + i*16 + rh*8 + g;
                sred[row*8 + (warp >> 1)*2 + 0] = sum[i][rh];
                sred[row*8 + (warp >> 1)*2 + 1] = sq[i][rh];
            }
        }
        __syncthreads();
#pragma unroll
        for (int i = 0; i < 2; i++)
#pragma unroll
        for (int rh = 0; rh < 2; rh++) {
            int row = wm + i*16 + rh*8 + g;
            float s = sred[row*8+0] + sred[row*8+2] + sred[row*8+4] + sred[row*8+6];
            float qq = sred[row*8+1] + sred[row*8+3] + sred[row*8+5] + sred[row*8+7];
            float mean = s*(1.0f/128.0f);
            float var = fmaxf(qq*(1.0f/128.0f) - mean*mean, 0.f);
            float rstd = rsqrtf(var + 1e-5f);
            if (epi == EPI_FIN) {
                int grow = m0 + row;
                int b = grow >> 12, p = grow & 4095;
#pragma unroll
                for (int j = 0; j < 4; j++) {
                    int n = wn + j*8 + tg;
                    extout[(b*D_ + n  )*4096 + p] =
                        (acc[i][j][rh*2+0]-mean)*rstd*extg[n]   + extbt[n];
                    extout[(b*D_ + n+1)*4096 + p] =
                        (acc[i][j][rh*2+1]-mean)*rstd*extg[n+1] + extbt[n+1];
                }
            } else {
#pragma unroll
                for (int j = 0; j < 4; j++) {
                    int n = wn + j*8 + tg;
                    float v0 = (acc[i][j][rh*2+0]-mean)*rstd;
                    float v1 = (acc[i][j][rh*2+1]-mean)*rstd;
                    *reinterpret_cast<uint32_t*>(&oh[(m0+row)*D_ + n]) = packh2(v0, v1);
                }
            }
        }
    }
}

// ---------------- tensor-core flash attention (fp16 in / fp16 out) -----------
// smem layout: int pixq[NQ]; int pixk[264]; then Qs/Ks/Vt halves.
template<int MT, int NW>
__global__ void __launch_bounds__(NW*32) k_attn_mma(int stage) {
    const int NQ = MT*16*NW;
    extern __shared__ __half sha[];
    int* pixq = reinterpret_cast<int*>(sha);
    int* pixk = pixq + NQ;
    __half* Qs = reinterpret_cast<__half*>(pixk + 264);   // [NQ][40]
    __half* Ks = Qs + NQ*40;                              // [264][40]
    __half* Vt = Ks + 264*40;                             // [32][274]
    int bl = blockIdx.x, hh = blockIdx.y, tid = threadIdx.x;
    int b = bl >> 6, l = bl & 63;
    const __half* qsrc; const __half* ksrc; const __half* vsrc;
    if (stage == 0) { qsrc = g_qh1; ksrc = g_kh1; vsrc = g_vh1; }
    else            { qsrc = g_qh2; ksrc = g_kh2; vsrc = g_vh2; }

    // pixel index tables (one div chain per row, not per element)
    for (int row = tid; row < NQ; row += NW*32) {
        int pix;
        if (stage == 0) {
            int n = row >> 6, ij = row & 63;
            pix = (b*N_+n)*4096 + ((l>>3)*8 + (ij>>3))*64 + (l&7)*8 + (ij&7);
        } else {
            pix = b*4096 + ((l>>3)*8 + (row>>3))*64 + (l&7)*8 + (row&7);
        }
        pixq[row] = pix;
    }
    for (int kv = tid; kv < 264; kv += NW*32) {
        int n = kv/44, f = kv%44, f1 = f/11, f2 = f%11;
        int h, w;
        if (stage == 0) { h = (l>>3)*4 + f1; w = (l&7)*11 + f2; }
        else            { h = f1*8 + (l>>3); w = f2*8 + (l&7); }
        pixk[kv] = (b*N_+n)*PIX + h*FW_ + w;
    }
    __syncthreads();
    // async 16B loads of Q and K via tables
    for (int idx = tid; idx < NQ*4; idx += NW*32) {
        int row = idx >> 2, c8 = idx & 3;
        cpa16(&Qs[row*40 + c8*8], &qsrc[pixq[row]*D_ + hh*32 + c8*8]);
    }
    for (int idx = tid; idx < 264*4; idx += NW*32) {
        int kv = idx >> 2, c8 = idx & 3;
        cpa16(&Ks[kv*40 + c8*8], &ksrc[pixk[kv]*D_ + hh*32 + c8*8]);
    }
    asm volatile("cp.async.commit_group;\n");
    // V transposed (scatter store, synchronous)
    for (int idx = tid; idx < NKV*32; idx += NW*32) {
        int kv = idx >> 5, ch = idx & 31;
        Vt[ch*274 + kv] = vsrc[pixk[kv]*D_ + hh*32 + ch];
    }
    for (int idx = tid; idx < 32*10; idx += NW*32) {
        int ch = idx / 10, c = idx % 10;
        Vt[ch*274 + 264 + c] = __half(0.f);
    }
    asm volatile("cp.async.wait_group 0;\n");
    __syncthreads();

    int warp = tid >> 5, lane = tid & 31;
    int g = lane >> 2, t4 = lane & 3;
    int row0 = warp * MT * 16;

    uint32_t af[MT][2][4];
#pragma unroll
    for (int mt = 0; mt < MT; mt++)
#pragma unroll
        for (int ks = 0; ks < 2; ks++) {
            int r = row0 + mt*16, k0 = ks*16;
            af[mt][ks][0] = *reinterpret_cast<const uint32_t*>(&Qs[(r+g  )*40 + k0 + 2*t4    ]);
            af[mt][ks][1] = *reinterpret_cast<const uint32_t*>(&Qs[(r+8+g)*40 + k0 + 2*t4    ]);
            af[mt][ks][2] = *reinterpret_cast<const uint32_t*>(&Qs[(r+g  )*40 + k0 + 8 + 2*t4]);
            af[mt][ks][3] = *reinterpret_cast<const uint32_t*>(&Qs[(r+8+g)*40 + k0 + 8 + 2*t4]);
        }

    float m[MT][2], lsum[MT][2], O[MT][4][4];
#pragma unroll
    for (int mt = 0; mt < MT; mt++) {
        m[mt][0] = -1e30f; m[mt][1] = -1e30f;
        lsum[mt][0] = 0.f; lsum[mt][1] = 0.f;
#pragma unroll
        for (int j = 0; j < 4; j++)
#pragma unroll
            for (int r = 0; r < 4; r++) O[mt][j][r] = 0.f;
    }

    for (int c = 0; c < 17; c++) {
        int kv0 = c*16;
        int nt = (c == 16) ? 1 : 2;
        uint32_t bf[2][2][2];
#pragma unroll
        for (int n = 0; n < 2; n++) {
            if (n < nt) {
#pragma unroll
                for (int ks = 0; ks < 2; ks++) {
                    bf[n][ks][0] = *reinterpret_cast<const uint32_t*>(&Ks[(kv0+n*8+g)*40 + ks*16 + 2*t4    ]);
                    bf[n][ks][1] = *reinterpret_cast<const uint32_t*>(&Ks[(kv0+n*8+g)*40 + ks*16 + 8 + 2*t4]);
                }
            }
        }
        float S[MT][2][4];
#pragma unroll
        for (int mt = 0; mt < MT; mt++)
#pragma unroll
            for (int n = 0; n < 2; n++)
#pragma unroll
                for (int r = 0; r < 4; r++) S[mt][n][r] = 0.f;
#pragma unroll
        for (int mt = 0; mt < MT; mt++)
#pragma unroll
            for (int n = 0; n < 2; n++) {
                if (n < nt) {
                    mma16816(S[mt][n], af[mt][0], bf[n][0][0], bf[n][0][1]);
                    mma16816(S[mt][n], af[mt][1], bf[n][1][0], bf[n][1][1]);
                }
            }
#pragma unroll
        for (int mt = 0; mt < MT; mt++) {
            float mx0 = fmaxf(S[mt][0][0], S[mt][0][1]);
            float mx8 = fmaxf(S[mt][0][2], S[mt][0][3]);
            if (nt == 2) {
                mx0 = fmaxf(mx0, fmaxf(S[mt][1][0], S[mt][1][1]));
                mx8 = fmaxf(mx8, fmaxf(S[mt][1][2], S[mt][1][3]));
            }
            mx0 = fmaxf(mx0, __shfl_xor_sync(0xffffffffu, mx0, 1));
            mx0 = fmaxf(mx0, __shfl_xor_sync(0xffffffffu, mx0, 2));
            mx8 = fmaxf(mx8, __shfl_xor_sync(0xffffffffu, mx8, 1));
            mx8 = fmaxf(mx8, __shfl_xor_sync(0xffffffffu, mx8, 2));
            float mn0 = fmaxf(m[mt][0], mx0), mn8 = fmaxf(m[mt][1], mx8);
            float cr0 = __expf(m[mt][0] - mn0), cr8 = __expf(m[mt][1] - mn8);
            m[mt][0] = mn0; m[mt][1] = mn8;
            uint32_t pa[4];
            float p00 = __expf(S[mt][0][0] - mn0), p01 = __expf(S[mt][0][1] - mn0);
            float p02 = __expf(S[mt][0][2] - mn8), p03 = __expf(S[mt][0][3] - mn8);
            float rs0 = p00 + p01, rs8 = p02 + p03;
            pa[0] = packh2(p00, p01);
            pa[1] = packh2(p02, p03);
            if (nt == 2) {
                float p10 = __expf(S[mt][1][0] - mn0), p11 = __expf(S[mt][1][1] - mn0);
                float p12 = __expf(S[mt][1][2] - mn8), p13 = __expf(S[mt][1][3] - mn8);
                rs0 += p10 + p11; rs8 += p12 + p13;
                pa[2] = packh2(p10, p11);
                pa[3] = packh2(p12, p13);
            } else { pa[2] = 0u; pa[3] = 0u; }
            rs0 += __shfl_xor_sync(0xffffffffu, rs0, 1);
            rs0 += __shfl_xor_sync(0xffffffffu, rs0, 2);
            rs8 += __shfl_xor_sync(0xffffffffu, rs8, 1);
            rs8 += __shfl_xor_sync(0xffffffffu, rs8, 2);
            lsum[mt][0] = lsum[mt][0]*cr0 + rs0;
            lsum[mt][1] = lsum[mt][1]*cr8 + rs8;
#pragma unroll
            for (int j = 0; j < 4; j++) {
                O[mt][j][0] *= cr0; O[mt][j][1] *= cr0;
                O[mt][j][2] *= cr8; O[mt][j][3] *= cr8;
                uint32_t vb0 = *reinterpret_cast<const uint32_t*>(&Vt[(j*8+g)*274 + kv0 + 2*t4    ]);
                uint32_t vb1 = *reinterpret_cast<const uint32_t*>(&Vt[(j*8+g)*274 + kv0 + 8 + 2*t4]);
                mma16816(O[mt][j], pa, vb0, vb1);
            }
        }
    }
#pragma unroll
    for (int mt = 0; mt < MT; mt++) {
        float i0 = 1.0f / lsum[mt][0], i8 = 1.0f / lsum[mt][1];
        int r0 = row0 + mt*16 + g;
        int r1 = r0 + 8;
        int out0, out1;
        if (stage == 0) {
            out0 = bl*NQ + r0;
            out1 = bl*NQ + r1;
        } else {
            out0 = b*4096 + ((l>>3)*8 + (r0>>3))*64 + (l&7)*8 + (r0&7);
            out1 = b*4096 + ((l>>3)*8 + (r1>>3))*64 + (l&7)*8 + (r1&7);
        }
        __half* Od = (stage == 0) ? g_otok : g_o2;
#pragma unroll
        for (int j = 0; j < 4; j++) {
            int chn = hh*32 + j*8 + 2*t4;
            *reinterpret_cast<uint32_t*>(&Od[out0*D_ + chn]) = packh2(O[mt][j][0]*i0, O[mt][j][1]*i0);
            *reinterpret_cast<uint32_t*>(&Od[out1*D_ + chn]) = packh2(O[mt][j][2]*i8, O[mt][j][3]*i8);
        }
    }
}

// ---------------------------------------------------------------------------
extern "C" void kernel_launch(void* const* d_in, const int* in_sizes, int n_in,
                              void* d_out, int out_size) {
    (void)in_sizes; (void)n_in; (void)out_size;
    const float* x        = (const float*)d_in[1];
    const float* grid     = (const float*)d_in[2];
    const float* feature  = (const float*)d_in[3];
    const float* I_inv    = (const float*)d_in[4];
    const float* E_inv    = (const float*)d_in[5];
    const float* bn_fl_g  = (const float*)d_in[6];
    const float* bn_fl_b  = (const float*)d_in[7];
    const float* W_fl     = (const float*)d_in[8];
    const float* bn_fp_g  = (const float*)d_in[9];
    const float* bn_fp_b  = (const float*)d_in[10];
    const float* W_fp     = (const float*)d_in[11];
    const float* W_bev    = (const float*)d_in[12];
    const float* b_bev    = (const float*)d_in[13];
    const float* W_img    = (const float*)d_in[14];
    const float* W_cam    = (const float*)d_in[15];
    const float* aln_g    = (const float*)d_in[16];
    const float* aln_b    = (const float*)d_in[17];
    const float* aWqkv    = (const float*)d_in[18];
    const float* abqkv    = (const float*)d_in[19];
    const float* aWp      = (const float*)d_in[20];
    const float* abp      = (const float*)d_in[21];
    const float* pn_g     = (const float*)d_in[22];
    const float* pn_b     = (const float*)d_in[23];
    const float* Wma      = (const float*)d_in[24];
    const float* bma      = (const float*)d_in[25];
    const float* Wmb      = (const float*)d_in[26];
    const float* bmb      = (const float*)d_in[27];
    const float* post_g   = (const float*)d_in[28];
    const float* post_b   = (const float*)d_in[29];
    float* out = (float*)d_out;

    const int GSM = (64*136 + 128*136) * 2;  // 52224
    const int PSM = 2*128*33*4 + 32*128*4;   // 50176
    const int A1SM = (384 + 264)*4 + (384*40 + 264*40 + 32*274) * 2;  // 71968
    const int A2SM = (64 + 264)*4 + (64*40 + 264*40 + 32*274) * 2;    // 45088
    cudaFuncSetAttribute(k_prep, cudaFuncAttributeMaxDynamicSharedMemorySize, PSM);
    cudaFuncSetAttribute(k_gemm_ep<1>, cudaFuncAttributeMaxDynamicSharedMemorySize, GSM);
    cudaFuncSetAttribute(k_gemm_ep<2>, cudaFuncAttributeMaxDynamicSharedMemorySize, GSM);
    cudaFuncSetAttribute(k_attn_mma<3,8>, cudaFuncAttributeMaxDynamicSharedMemorySize, A1SM);
    cudaFuncSetAttribute(k_attn_mma<1,4>, cudaFuncAttributeMaxDynamicSharedMemorySize, A2SM);

    // prep (weights + activations)
    k_wprep<<<304, 256>>>(aln_g, aln_b, aWqkv, abqkv, pn_g, pn_b, Wma, bma,
                          aWp, Wmb, W_fp, W_fl);
    k_prep<<<B_*N_*88, 128, PSM>>>(feature, I_inv, E_inv, W_img, W_cam,
                                   bn_fp_g, bn_fp_b, bn_fl_g, bn_fl_b);
    k_query<<<NQP/8, 256>>>(grid, x, W_bev, b_bev, E_inv, W_cam);

    // conv GEMMs (jobs 0,1) then all 5 QKV projections (jobs 2..6)
    k_gemm_ep<1><<<1056, 256, GSM>>>(100, nullptr, nullptr, nullptr, nullptr, nullptr);
    k_gemm_ep<1><<<2880, 256, GSM>>>(101, nullptr, nullptr, nullptr, nullptr, nullptr);

    // stage 1
    k_attn_mma<3,8><<<dim3(B_*64, 4), 256, A1SM>>>(0);
    k_gemm_ep<1><<<128, 256, GSM>>>(7, abp, nullptr, nullptr, x, nullptr);      // mean+proj+skip+LN
    k_gemm_ep<1><<<256, 256, GSM>>>(102, nullptr, nullptr, nullptr, nullptr, nullptr);  // gelu a,b
    k_gemm_ep<2><<<128, 256, GSM>>>(10, bmb, nullptr, nullptr, nullptr, nullptr);       // res+LN -> xq1

    // stage 2
    k_gemm_ep<1><<<128, 256, GSM>>>(11, nullptr, nullptr, nullptr, nullptr, nullptr);   // Q2
    k_attn_mma<1,4><<<dim3(B_*64, 4), 128, A2SM>>>(1);
    k_gemm_ep<1><<<128, 256, GSM>>>(12, abp + 128, nullptr, nullptr, nullptr, nullptr); // proj+skip+LN
    k_gemm_ep<1><<<256, 256, GSM>>>(103, nullptr, nullptr, nullptr, nullptr, nullptr);  // gelu a,b
    k_gemm_ep<2><<<128, 256, GSM>>>(15, bmb + 128, post_g, post_b, nullptr, out);       // res+finalLN
}

// round 14
// speedup vs baseline: 1.0302x; 1.0302x over previous
#include <cuda_runtime.h>
#include <cuda_fp16.h>
#include <math.h>
#include <stdint.h>

#define B_   2
#define N_   6
#define FH_  32
#define FW_  88
#define PIX  (FH_*FW_)     // 2816
#define D_   128
#define NKV  264
#define NQ1  384
#define NPX  (B_*N_*PIX)   // 33792
#define NQP  (B_*N_*4096)  // 49152
#define NTK  (B_*4096)     // 8192

// epilogue modes
#define EPI_HALF  0
#define EPI_GELU  1
#define EPI_LN    2
#define EPI_SKLN0 3
#define EPI_SKLN1 4
#define EPI_RESLN 5
#define EPI_FIN   6

// ---------------- scratch globals (no runtime allocation) -------------------
__device__ __align__(16) __half g_fph[NPX*D_];
__device__ __align__(16) __half g_flh[NPX*D_];
__device__ __align__(16) __half g_kimgh[NPX*D_];
__device__ __align__(16) __half g_xq [NQP*D_];
__device__ __align__(16) __half g_xk [NPX*D_];
__device__ __align__(16) __half g_xv [NPX*D_];
__device__ __align__(16) __half g_xq1[NTK*D_];
__device__ __align__(16) __half g_xm [NTK*D_];
__device__ __align__(16) __half g_wfold[6*D_*D_];
__device__ float  g_bfold[6*D_];
__device__ __align__(16) __half g_wafold[2*256*D_];
__device__ float  g_bafold[2*256];
__device__ __align__(16) __half g_wmbT[2*D_*256];
__device__ __align__(16) __half g_wpT[2*D_*D_];
__device__ __align__(16) __half g_wfpH[D_*D_];
__device__ __align__(16) __half g_wflH[D_*D_];
__device__ __align__(16) __half g_qh1[NQP*D_];
__device__ __align__(16) __half g_kh1[NPX*D_];
__device__ __align__(16) __half g_vh1[NPX*D_];
__device__ __align__(16) __half g_qh2[NTK*D_];
__device__ __align__(16) __half g_kh2[NPX*D_];
__device__ __align__(16) __half g_vh2[NPX*D_];
__device__ __align__(16) __half g_otok[B_*64*NQ1*D_];
__device__ __align__(16) __half g_o2[NTK*D_];
__device__ __align__(16) __half g_h[NTK*256];
__device__ __align__(16) float  g_q1[NTK*D_];
__device__ __align__(16) float  g_q2[NTK*D_];

__device__ __forceinline__ void warpRed2(float& s, float& q) {
#pragma unroll
    for (int o = 16; o; o >>= 1) {
        s += __shfl_xor_sync(0xffffffffu, s, o);
        q += __shfl_xor_sync(0xffffffffu, q, o);
    }
}

__device__ __forceinline__ void st_half4(__half* dst, float a, float b, float c, float d) {
    __half2* p = reinterpret_cast<__half2*>(dst);
    p[0] = __floats2half2_rn(a, b);
    p[1] = __floats2half2_rn(c, d);
}

__device__ __forceinline__ uint32_t packh2(float a, float b) {
    __half2 h = __floats2half2_rn(a, b);
    return *reinterpret_cast<uint32_t*>(&h);
}

__device__ __forceinline__ float geluf(float h) {
    return h * 0.5f * (1.0f + erff(h * 0.70710678118654752f));
}

__device__ __forceinline__ void mma16816(float* c, const uint32_t* a,
                                         uint32_t b0, uint32_t b1) {
    asm volatile(
        "mma.sync.aligned.m16n8k16.row.col.f32.f16.f16.f32 "
        "{%0,%1,%2,%3}, {%4,%5,%6,%7}, {%8,%9}, {%0,%1,%2,%3};\n"
        : "+f"(c[0]), "+f"(c[1]), "+f"(c[2]), "+f"(c[3])
        : "r"(a[0]), "r"(a[1]), "r"(a[2]), "r"(a[3]), "r"(b0), "r"(b1));
}

__device__ __forceinline__ void cpa16(void* smem, const void* gmem) {
    uint32_t sa = (uint32_t)__cvta_generic_to_shared(smem);
    asm volatile("cp.async.cg.shared.global [%0], [%1], 16;\n" :: "r"(sa), "l"(gmem));
}

// ---------------- merged weight prep (one launch, block-range dispatch) ------
__global__ void __launch_bounds__(256) k_wprep(
        const float* __restrict__ aln_g, const float* __restrict__ aln_b,
        const float* __restrict__ aWqkv, const float* __restrict__ abqkv,
        const float* __restrict__ pn_g, const float* __restrict__ pn_b,
        const float* __restrict__ Wma, const float* __restrict__ bma,
        const float* __restrict__ aWp, const float* __restrict__ Wmb,
        const float* __restrict__ W_fp, const float* __restrict__ W_fl) {
    __shared__ float sm[16][129];
    __shared__ float bred[16][17];
    int blk = blockIdx.x, tid = threadIdx.x;
    if (blk < 48) {
        int idx = blk >> 3, o0 = (blk & 7) * 16;
        const float* W = aWqkv + idx*16384;
        const float* g = aln_g + idx*128;
        const float* bb = aln_b + idx*128;
        for (int k = tid; k < 2048; k += 256) {
            int c = k >> 4, o = k & 15;
            sm[o][c] = g[c] * W[c*128 + o0 + o];
        }
        {
            int o = tid & 15, cg = tid >> 4;
            float part = 0.f;
#pragma unroll
            for (int cc = 0; cc < 8; cc++) {
                int c = cg*8 + cc;
                part += bb[c] * W[c*128 + o0 + o];
            }
            bred[o][cg] = part;
        }
        __syncthreads();
        for (int k = tid; k < 1024; k += 256) {
            int o = k >> 6, c2 = (k & 63)*2;
            *reinterpret_cast<__half2*>(&g_wfold[idx*16384 + (o0+o)*128 + c2]) =
                __floats2half2_rn(sm[o][c2], sm[o][c2+1]);
        }
        if (tid < 16) {
            float a = 0.f;
#pragma unroll
            for (int cg = 0; cg < 16; cg++) a += bred[tid][cg];
            g_bfold[idx*128 + o0 + tid] = a + abqkv[idx*128 + o0 + tid];
        }
    } else if (blk < 80) {
        int t = blk - 48;
        int s = t >> 4, o0 = (t & 15) * 16;
        const float* W = Wma + s*128*256;
        const float* g = pn_g + s*128;
        const float* bb = pn_b + s*128;
        for (int k = tid; k < 2048; k += 256) {
            int c = k >> 4, o = k & 15;
            sm[o][c] = g[c] * W[c*256 + o0 + o];
        }
        {
            int o = tid & 15, cg = tid >> 4;
            float part = 0.f;
#pragma unroll
            for (int cc = 0; cc < 8; cc++) {
                int c = cg*8 + cc;
                part += bb[c] * W[c*256 + o0 + o];
            }
            bred[o][cg] = part;
        }
        __syncthreads();
        for (int k = tid; k < 1024; k += 256) {
            int o = k >> 6, c2 = (k & 63)*2;
            *reinterpret_cast<__half2*>(&g_wafold[s*32768 + (o0+o)*128 + c2]) =
                __floats2half2_rn(sm[o][c2], sm[o][c2+1]);
        }
        if (tid < 16) {
            float a = 0.f;
#pragma unroll
            for (int cg = 0; cg < 16; cg++) a += bred[tid][cg];
            g_bafold[s*256 + o0 + tid] = a + bma[s*256 + o0 + tid];
        }
    } else if (blk < 176) {
        int t = blk - 80;
        const float* src; __half* dst; int R, C, bx, by;
        if (t < 16)      { src = aWp;          dst = g_wpT;          R=128; C=128; bx=t&3;      by=t>>2; }
        else if (t < 32) { src = aWp+16384;    dst = g_wpT+16384;    R=128; C=128; bx=(t-16)&3; by=(t-16)>>2; }
        else if (t < 64) { src = Wmb;          dst = g_wmbT;         R=256; C=128; bx=(t-32)&3; by=(t-32)>>2; }
        else             { src = Wmb+32768;    dst = g_wmbT+32768;   R=256; C=128; bx=(t-64)&3; by=(t-64)>>2; }
        float (*tb)[33] = reinterpret_cast<float(*)[33]>(&sm[0][0]);
        int c0 = bx*32, r0 = by*32;
        int cx = tid & 31, ry = tid >> 5;
        for (int rr = ry; rr < 32; rr += 8)
            tb[rr][cx] = src[(r0+rr)*C + c0 + cx];
        __syncthreads();
        for (int cc = ry; cc < 32; cc += 8)
            dst[(c0+cc)*R + r0 + cx] = __float2half(tb[cx][cc]);
    } else {
        int t = blk - 176;
        const float* src = (t < 64) ? W_fp : W_fl;
        __half* dst = (t < 64) ? g_wfpH : g_wflH;
        int i = (t & 63)*256 + tid;
        dst[i] = __float2half(src[i]);
    }
}

// ---------------- prep: BN-ReLU fp16 feats + image embedding -----------------
__global__ void __launch_bounds__(128) k_prep(
        const float* __restrict__ feat,
        const float* __restrict__ I_inv, const float* __restrict__ E_inv,
        const float* __restrict__ W_img, const float* __restrict__ W_cam,
        const float* __restrict__ fp_g, const float* __restrict__ fp_b,
        const float* __restrict__ fl_g, const float* __restrict__ fl_b) {
    extern __shared__ float sh[];
    float* sfp  = sh;                 // [128][33]
    float* sfl  = sh + 128*33;
    float* kimg = sh + 2*128*33;      // [32][128]
    int blk = blockIdx.x, tid = threadIdx.x;
    int bn = blk / 88, p0 = (blk % 88) * 32;
    int warp = tid >> 5, lane = tid & 31;

    const float invs = rsqrtf(1.0f + 1e-5f);
    for (int k = tid; k < 4096; k += 128) {
        int c = k >> 5, pp = k & 31;
        float f = feat[(bn*D_ + c)*PIX + p0 + pp];
        sfp[c*33+pp] = fmaxf(f * invs * fp_g[c] + fp_b[c], 0.f);
        sfl[c*33+pp] = fmaxf(f * invs * fl_g[c] + fl_b[c], 0.f);
    }
    float e3[4];
#pragma unroll
    for (int i = 0; i < 4; i++) e3[i] = E_inv[bn*16 + i*4 + 3];
    for (int it = 0; it < 8; it++) {
        int tt = it*4 + warp;
        int p = p0 + tt, fh = p / FW_, fw = p % FW_;
        float px = (float)fw * (480.0f / 87.0f);
        float py = (float)fh * (224.0f / 31.0f);
        float cam[4];
#pragma unroll
        for (int i = 0; i < 3; i++)
            cam[i] = I_inv[bn*9+i*3+0]*px + I_inv[bn*9+i*3+1]*py + I_inv[bn*9+i*3+2];
        cam[3] = 1.0f;
        float dd[4];
#pragma unroll
        for (int i = 0; i < 4; i++)
            dd[i] = E_inv[bn*16+i*4+0]*cam[0] + E_inv[bn*16+i*4+1]*cam[1]
                  + E_inv[bn*16+i*4+2]*cam[2] + E_inv[bn*16+i*4+3]*cam[3];
        int c0 = lane*4;
        float t[4]; float ssum = 0.f, dum = 0.f;
#pragma unroll
        for (int i = 0; i < 4; i++) {
            int c = c0+i;
            float de = W_img[c*4+0]*dd[0] + W_img[c*4+1]*dd[1]
                     + W_img[c*4+2]*dd[2] + W_img[c*4+3]*dd[3];
            float ce = W_cam[c*4+0]*e3[0] + W_cam[c*4+1]*e3[1]
                     + W_cam[c*4+2]*e3[2] + W_cam[c*4+3]*e3[3];
            t[i] = de - ce;
            ssum += t[i]*t[i];
        }
        warpRed2(ssum, dum);
        float inv = 1.0f / fmaxf(sqrtf(ssum), 1e-12f);
#pragma unroll
        for (int i = 0; i < 4; i++) kimg[tt*128 + c0 + i] = t[i]*inv;
    }
    __syncthreads();
    for (int pp = 0; pp < 32; pp++) {
        int row = bn*PIX + p0 + pp;
        g_fph[row*D_ + tid] = __float2half(sfp[tid*33 + pp]);
        g_flh[row*D_ + tid] = __float2half(sfl[tid*33 + pp]);
        g_kimgh[row*D_ + tid] = __float2half(kimg[pp*128 + tid]);
    }
}

// ---------------- query -> LN'd fp16 xhat, warp per pixel --------------------
__global__ void __launch_bounds__(256) k_query(
        const float* __restrict__ grid, const float* __restrict__ x,
        const float* __restrict__ W_bev, const float* __restrict__ b_bev,
        const float* __restrict__ E_inv, const float* __restrict__ W_cam) {
    int tid = threadIdx.x, warp = tid >> 5, lane = tid & 31;
    int u = blockIdx.x*8 + warp;
    int bn = u >> 12, p = u & 4095;
    int b = bn / N_;
    int c0 = lane*4;
    float e3[4];
#pragma unroll
    for (int i = 0; i < 4; i++) e3[i] = E_inv[bn*16 + i*4 + 3];
    float gx = grid[p], gy = grid[4096 + p];
    float t[4]; float ss = 0.f, dum = 0.f;
#pragma unroll
    for (int i = 0; i < 4; i++) {
        int c = c0 + i;
        float we = W_bev[c*2+0]*gx + W_bev[c*2+1]*gy + b_bev[c];
        float ce = W_cam[c*4+0]*e3[0] + W_cam[c*4+1]*e3[1]
                 + W_cam[c*4+2]*e3[2] + W_cam[c*4+3]*e3[3];
        t[i] = we - ce;
        ss += t[i]*t[i];
    }
    warpRed2(ss, dum);
    float inv = 1.0f / fmaxf(sqrtf(ss), 1e-12f);
    float q[4]; float s = 0.f, q2 = 0.f;
#pragma unroll
    for (int i = 0; i < 4; i++) {
        q[i] = t[i]*inv + x[(b*D_ + c0 + i)*4096 + p];
        s += q[i]; q2 += q[i]*q[i];
    }
    warpRed2(s, q2);
    float mean = s*(1.0f/128.0f);
    float var = fmaxf(q2*(1.0f/128.0f) - mean*mean, 0.f);
    float rstd = rsqrtf(var + 1e-5f);
    st_half4(&g_xq[u*D_ + c0],
             (q[0]-mean)*rstd, (q[1]-mean)*rstd, (q[2]-mean)*rstd, (q[3]-mean)*rstd);
}

// ---------------- device-side job table for the unified GEMM -----------------
__device__ __forceinline__ void gemm_job(
        int job, const float* extb,
        const __half*& A, const __half*& B, const float*& bias,
        __half*& oh, float*& of, const float*& aux, const __half*& auxh,
        int& epi, float& scale, int& ldC) {
    const float QS = 0.17677669529663687f;
    scale = 1.f; ldC = 128; aux = nullptr; auxh = nullptr;
    bias = nullptr; oh = nullptr; of = nullptr;
    switch (job) {
    case 0:  A=g_fph; B=g_wfpH; oh=g_xk; auxh=g_kimgh; epi=EPI_LN; break;
    case 1:  A=g_flh; B=g_wflH; oh=g_xv; epi=EPI_LN; break;
    case 2:  A=g_xq;  B=g_wfold;          bias=g_bfold;     oh=g_qh1; epi=EPI_HALF; scale=QS; break;
    case 3:  A=g_xk;  B=g_wfold+16384;    bias=g_bfold+128; oh=g_kh1; epi=EPI_HALF; break;
    case 4:  A=g_xv;  B=g_wfold+2*16384;  bias=g_bfold+256; oh=g_vh1; epi=EPI_HALF; break;
    case 5:  A=g_xk;  B=g_wfold+4*16384;  bias=g_bfold+512; oh=g_kh2; epi=EPI_HALF; break;
    case 6:  A=g_xv;  B=g_wfold+5*16384;  bias=g_bfold+640; oh=g_vh2; epi=EPI_HALF; break;
    case 7:  A=nullptr; B=g_wpT; bias=extb; of=g_q1; oh=g_xm; epi=EPI_SKLN0; break;
    case 8:  A=g_xm;  B=g_wafold;         bias=g_bafold;     oh=g_h;     epi=EPI_GELU; ldC=256; break;
    case 9:  A=g_xm;  B=g_wafold+16384;   bias=g_bafold+128; oh=g_h+128; epi=EPI_GELU; ldC=256; break;
    case 10: A=g_h;   B=g_wmbT; bias=extb; of=g_q1; oh=g_xq1; aux=g_q1; epi=EPI_RESLN; break;
    case 11: A=g_xq1; B=g_wfold+3*16384;  bias=g_bfold+384; oh=g_qh2; epi=EPI_HALF; scale=QS; break;
    case 12: A=g_o2;  B=g_wpT+16384; bias=extb; of=g_q2; oh=g_xm; aux=g_q1; epi=EPI_SKLN1; break;
    case 13: A=g_xm;  B=g_wafold+32768;        bias=g_bafold+256; oh=g_h;     epi=EPI_GELU; ldC=256; break;
    case 14: A=g_xm;  B=g_wafold+32768+16384;  bias=g_bafold+384; oh=g_h+128; epi=EPI_GELU; ldC=256; break;
    default: A=g_h;   B=g_wmbT+32768; bias=extb; aux=g_q2; epi=EPI_FIN; break;
    }
}

// ---------------- unified HMMA GEMM with fused epilogues ---------------------
// C[64][128] per block = A[64][KT*128] @ B[128][KT*128]^T (+ epilogue).
// 256 thr, 8 warps as 2(m) x 4(n); warp tile 32x32.
template<int KT>
__global__ void __launch_bounds__(256, 3) k_gemm_ep(
        int jobsel, const float* __restrict__ extb,
        const float* __restrict__ extg, const float* __restrict__ extbt,
        const float* __restrict__ extaux, float* __restrict__ extout) {
    int job, tile;
    if (jobsel < 100)       { job = jobsel; tile = blockIdx.x; }
    else if (jobsel == 100) { job = blockIdx.x / 528; tile = blockIdx.x % 528; }
    else if (jobsel == 101) {
        int bx = blockIdx.x;
        if (bx < 768) { job = 2; tile = bx; }
        else { int r = bx - 768; job = 3 + r/528; tile = r % 528; }
    }
    else if (jobsel == 102) { job = 8 + (blockIdx.x >> 7); tile = blockIdx.x & 127; }
    else                    { job = 13 + (blockIdx.x >> 7); tile = blockIdx.x & 127; }

    const __half* A; const __half* Bw; const float* bias;
    __half* oh; float* of; const float* aux; const __half* auxh;
    int epi; float scale; int ldC;
    gemm_job(job, extb, A, Bw, bias, oh, of, aux, auxh, epi, scale, ldC);
    if (epi == EPI_SKLN0) aux = extaux;

    extern __shared__ __half shh[];
    __half* As = shh;                 // [64][136]
    __half* Bs = shh + 64*136;        // [128][136]
    int tid = threadIdx.x;
    int m0 = tile * 64;
    const int KD = KT*128;
    int warp = tid >> 5, lane = tid & 31;
    int wm = (warp & 1) * 32, wn = (warp >> 1) * 32;
    int g = lane >> 2, tg = (lane & 3) * 2;
    float acc[2][4][4];
#pragma unroll
    for (int i = 0; i < 2; i++)
#pragma unroll
        for (int j = 0; j < 4; j++)
#pragma unroll
            for (int r = 0; r < 4; r++) acc[i][j][r] = 0.f;

    for (int kc = 0; kc < KT; kc++) {
        int r = tid >> 4, q = tid & 15;
        if (job == 7) {
            for (int rr = r; rr < 64; rr += 16) {
                int row = m0 + rr;
                int b = row >> 12, p = row & 4095;
                int hh_ = p >> 6, ww = p & 63;
                int l = ((hh_ >> 3) << 3) + (ww >> 3);
                const __half* src = g_otok + ((b*64 + l)*NQ1 + (hh_&7)*8 + (ww&7))*D_ + q*8;
                float s[8];
#pragma unroll
                for (int t = 0; t < 8; t++) s[t] = 0.f;
#pragma unroll
                for (int n = 0; n < 6; n++) {
                    const __half2* pp = reinterpret_cast<const __half2*>(src + n*64*D_);
#pragma unroll
                    for (int t = 0; t < 4; t++) {
                        float2 f = __half22float2(pp[t]);
                        s[t*2] += f.x; s[t*2+1] += f.y;
                    }
                }
                __half2 o[4];
#pragma unroll
                for (int t = 0; t < 4; t++)
                    o[t] = __floats2half2_rn(s[t*2]*(1.f/6.f), s[t*2+1]*(1.f/6.f));
                *reinterpret_cast<int4*>(&As[rr*136 + q*8]) = *reinterpret_cast<int4*>(o);
            }
#pragma unroll
            for (int rr = r; rr < 128; rr += 16)
                cpa16(&Bs[rr*136 + q*8], &Bw[rr*KD + q*8]);
        } else {
#pragma unroll
            for (int rr = r; rr < 64; rr += 16)
                cpa16(&As[rr*136 + q*8], &A[(m0+rr)*KD + kc*128 + q*8]);
#pragma unroll
            for (int rr = r; rr < 128; rr += 16)
                cpa16(&Bs[rr*136 + q*8], &Bw[rr*KD + kc*128 + q*8]);
        }
        asm volatile("cp.async.commit_group;\n");
        asm volatile("cp.async.wait_group 0;\n");
        __syncthreads();
#pragma unroll
        for (int ks = 0; ks < 8; ks++) {
            int k0 = ks*16;
            uint32_t a[2][4];
#pragma unroll
            for (int i = 0; i < 2; i++) {
                int mb = wm + i*16;
                a[i][0] = *reinterpret_cast<const uint32_t*>(&As[(mb+g  )*136 + k0+tg  ]);
                a[i][1] = *reinterpret_cast<const uint32_t*>(&As[(mb+8+g)*136 + k0+tg  ]);
                a[i][2] = *reinterpret_cast<const uint32_t*>(&As[(mb+g  )*136 + k0+8+tg]);
                a[i][3] = *reinterpret_cast<const uint32_t*>(&As[(mb+8+g)*136 + k0+8+tg]);
            }
#pragma unroll
            for (int j = 0; j < 4; j++) {
                uint32_t b0 = *reinterpret_cast<const uint32_t*>(&Bs[(wn+j*8+g)*136 + k0+tg  ]);
                uint32_t b1 = *reinterpret_cast<const uint32_t*>(&Bs[(wn+j*8+g)*136 + k0+8+tg]);
                mma16816(acc[0][j], a[0], b0, b1);
                mma16816(acc[1][j], a[1], b0, b1);
            }
        }
        __syncthreads();
    }

    if (epi <= EPI_GELU) {
#pragma unroll
        for (int i = 0; i < 2; i++)
#pragma unroll
        for (int j = 0; j < 4; j++) {
            int n = wn + j*8 + tg;
            float b0 = bias[n], b1 = bias[n+1];
            int r0 = m0 + wm + i*16 + g, r1 = r0 + 8;
            float v0 = acc[i][j][0]+b0, v1 = acc[i][j][1]+b1;
            float v2 = acc[i][j][2]+b0, v3 = acc[i][j][3]+b1;
            if (epi == EPI_GELU) {
                v0 = geluf(v0); v1 = geluf(v1); v2 = geluf(v2); v3 = geluf(v3);
            } else {
                v0 *= scale; v1 *= scale; v2 *= scale; v3 *= scale;
            }
            *reinterpret_cast<uint32_t*>(&oh[r0*ldC + n]) = packh2(v0, v1);
            *reinterpret_cast<uint32_t*>(&oh[r1*ldC + n]) = packh2(v2, v3);
        }
    } else {
#pragma unroll
        for (int i = 0; i < 2; i++)
#pragma unroll
        for (int j = 0; j < 4; j++) {
            int n = wn + j*8 + tg;
            int r0 = m0 + wm + i*16 + g, r1 = r0 + 8;
            if (bias) {
                float b0 = bias[n], b1 = bias[n+1];
                acc[i][j][0] += b0; acc[i][j][1] += b1;
                acc[i][j][2] += b0; acc[i][j][3] += b1;
            }
            if (auxh) {
                acc[i][j][0] += __half2float(auxh[r0*D_ + n]);
                acc[i][j][1] += __half2float(auxh[r0*D_ + n+1]);
                acc[i][j][2] += __half2float(auxh[r1*D_ + n]);
                acc[i][j][3] += __half2float(auxh[r1*D_ + n+1]);
            }
            if (aux) {
                if (epi == EPI_SKLN0) {
                    int ba = r0 >> 12, pa = r0 & 4095;
                    int bb_ = r1 >> 12, pb = r1 & 4095;
                    acc[i][j][0] += aux[(ba*D_ + n  )*4096 + pa];
                    acc[i][j][1] += aux[(ba*D_ + n+1)*4096 + pa];
                    acc[i][j][2] += aux[(bb_*D_ + n  )*4096 + pb];
                    acc[i][j][3] += aux[(bb_*D_ + n+1)*4096 + pb];
                } else {
                    acc[i][j][0] += aux[r0*D_ + n];
                    acc[i][j][1] += aux[r0*D_ + n+1];
                    acc[i][j][2] += aux[r1*D_ + n];
                    acc[i][j][3] += aux[r1*D_ + n+1];
                }
            }
            if (of) {
                of[r0*D_ + n]   = acc[i][j][0];
                of[r0*D_ + n+1] = acc[i][j][1];
                of[r1*D_ + n]   = acc[i][j][2];
                of[r1*D_ + n+1] = acc[i][j][3];
            }
        }
        float sum[2][2] = {{0,0},{0,0}}, sq[2][2] = {{0,0},{0,0}};
#pragma unroll
        for (int i = 0; i < 2; i++)
#pragma unroll
        for (int j = 0; j < 4; j++) {
            float a0 = acc[i][j][0], a1 = acc[i][j][1];
            float a2 = acc[i][j][2], a3 = acc[i][j][3];
            sum[i][0] += a0 + a1; sq[i][0] += a0*a0 + a1*a1;
            sum[i][1] += a2 + a3; sq[i][1] += a2*a2 + a3*a3;
        }
#pragma unroll
        for (int o = 1; o <= 2; o <<= 1) {
#pragma unroll
            for (int i = 0; i < 2; i++)
#pragma unroll
            for (int rh = 0; rh < 2; rh++) {
                sum[i][rh] += __shfl_xor_sync(0xffffffffu, sum[i][rh], o);
                sq[i][rh]  += __shfl_xor_sync(0xffffffffu, sq[i][rh], o);
            }
        }
        float* sred = reinterpret_cast<float*>(shh);   // [64][8]
        if ((lane & 3) == 0) {
#pragma unroll
            for (int i = 0; i < 2; i++)
#pragma unroll
            for (int rh = 0; rh < 2; rh++) {
                int row = wm + i*16 + rh*8 + g;
                sred[row*8 + (warp >> 1)*2 + 0] = sum[i][rh];
                sred[row*8 + (warp >> 1)*2 + 1] = sq[i][rh];
            }
        }
        __syncthreads();
#pragma unroll
        for (int i = 0; i < 2; i++)
#pragma unroll
        for (int rh = 0; rh < 2; rh++) {
            int row = wm + i*16 + rh*8 + g;
            float s = sred[row*8+0] + sred[row*8+2] + sred[row*8+4] + sred[row*8+6];
            float qq = sred[row*8+1] + sred[row*8+3] + sred[row*8+5] + sred[row*8+7];
            float mean = s*(1.0f/128.0f);
            float var = fmaxf(qq*(1.0f/128.0f) - mean*mean, 0.f);
            float rstd = rsqrtf(var + 1e-5f);
            if (epi == EPI_FIN) {
                int grow = m0 + row;
                int b = grow >> 12, p = grow & 4095;
#pragma unroll
                for (int j = 0; j < 4; j++) {
                    int n = wn + j*8 + tg;
                    extout[(b*D_ + n  )*4096 + p] =
                        (acc[i][j][rh*2+0]-mean)*rstd*extg[n]   + extbt[n];
                    extout[(b*D_ + n+1)*4096 + p] =
                        (acc[i][j][rh*2+1]-mean)*rstd*extg[n+1] + extbt[n+1];
                }
            } else {
#pragma unroll
                for (int j = 0; j < 4; j++) {
                    int n = wn + j*8 + tg;
                    float v0 = (acc[i][j][rh*2+0]-mean)*rstd;
                    float v1 = (acc[i][j][rh*2+1]-mean)*rstd;
                    *reinterpret_cast<uint32_t*>(&oh[(m0+row)*D_ + n]) = packh2(v0, v1);
                }
            }
        }
    }
}

// ---------------- tensor-core flash attention (fp16 in / fp16 out) -----------
// smem layout: int pixq[NQ]; int pixk[264]; then Qs/Ks/Vt halves.
template<int MT, int NW>
__global__ void __launch_bounds__(NW*32) k_attn_mma(int stage) {
    const int NQ = MT*16*NW;
    extern __shared__ __half sha[];
    int* pixq = reinterpret_cast<int*>(sha);
    int* pixk = pixq + NQ;
    __half* Qs = reinterpret_cast<__half*>(pixk + 264);   // [NQ][40]
    __half* Ks = Qs + NQ*40;                              // [264][40]
    __half* Vt = Ks + 264*40;                             // [32][274]
    int bl = blockIdx.x, hh = blockIdx.y, tid = threadIdx.x;
    int b = bl >> 6, l = bl & 63;
    const __half* qsrc; const __half* ksrc; const __half* vsrc;
    if (stage == 0) { qsrc = g_qh1; ksrc = g_kh1; vsrc = g_vh1; }
    else            { qsrc = g_qh2; ksrc = g_kh2; vsrc = g_vh2; }

    // pixel index tables (one div chain per row, not per element)
    for (int row = tid; row < NQ; row += NW*32) {
        int pix;
        if (stage == 0) {
            int n = row >> 6, ij = row & 63;
            pix = (b*N_+n)*4096 + ((l>>3)*8 + (ij>>3))*64 + (l&7)*8 + (ij&7);
        } else {
            pix = b*4096 + ((l>>3)*8 + (row>>3))*64 + (l&7)*8 + (row&7);
        }
        pixq[row] = pix;
    }
    for (int kv = tid; kv < 264; kv += NW*32) {
        int n = kv/44, f = kv%44, f1 = f/11, f2 = f%11;
        int h, w;
        if (stage == 0) { h = (l>>3)*4 + f1; w = (l&7)*11 + f2; }
        else            { h = f1*8 + (l>>3); w = f2*8 + (l&7); }
        pixk[kv] = (b*N_+n)*PIX + h*FW_ + w;
    }
    __syncthreads();
    // async 16B loads of Q and K via tables
    for (int idx = tid; idx < NQ*4; idx += NW*32) {
        int row = idx >> 2, c8 = idx & 3;
        cpa16(&Qs[row*40 + c8*8], &qsrc[pixq[row]*D_ + hh*32 + c8*8]);
    }
    for (int idx = tid; idx < 264*4; idx += NW*32) {
        int kv = idx >> 2, c8 = idx & 3;
        cpa16(&Ks[kv*40 + c8*8], &ksrc[pixk[kv]*D_ + hh*32 + c8*8]);
    }
    asm volatile("cp.async.commit_group;\n");
    // V transposed (scatter store, synchronous)
    for (int idx = tid; idx < NKV*32; idx += NW*32) {
        int kv = idx >> 5, ch = idx & 31;
        Vt[ch*274 + kv] = vsrc[pixk[kv]*D_ + hh*32 + ch];
    }
    for (int idx = tid; idx < 32*10; idx += NW*32) {
        int ch = idx / 10, c = idx % 10;
        Vt[ch*274 + 264 + c] = __half(0.f);
    }
    asm volatile("cp.async.wait_group 0;\n");
    __syncthreads();

    int warp = tid >> 5, lane = tid & 31;
    int g = lane >> 2, t4 = lane & 3;
    int row0 = warp * MT * 16;

    uint32_t af[MT][2][4];
#pragma unroll
    for (int mt = 0; mt < MT; mt++)
#pragma unroll
        for (int ks = 0; ks < 2; ks++) {
            int r = row0 + mt*16, k0 = ks*16;
            af[mt][ks][0] = *reinterpret_cast<const uint32_t*>(&Qs[(r+g  )*40 + k0 + 2*t4    ]);
            af[mt][ks][1] = *reinterpret_cast<const uint32_t*>(&Qs[(r+8+g)*40 + k0 + 2*t4    ]);
            af[mt][ks][2] = *reinterpret_cast<const uint32_t*>(&Qs[(r+g  )*40 + k0 + 8 + 2*t4]);
            af[mt][ks][3] = *reinterpret_cast<const uint32_t*>(&Qs[(r+8+g)*40 + k0 + 8 + 2*t4]);
        }

    float m[MT][2], lsum[MT][2], O[MT][4][4];
#pragma unroll
    for (int mt = 0; mt < MT; mt++) {
        m[mt][0] = -1e30f; m[mt][1] = -1e30f;
        lsum[mt][0] = 0.f; lsum[mt][1] = 0.f;
#pragma unroll
        for (int j = 0; j < 4; j++)
#pragma unroll
            for (int r = 0; r < 4; r++) O[mt][j][r] = 0.f;
    }

    for (int c = 0; c < 17; c++) {
        int kv0 = c*16;
        int nt = (c == 16) ? 1 : 2;
        uint32_t bf[2][2][2];
#pragma unroll
        for (int n = 0; n < 2; n++) {
            if (n < nt) {
#pragma unroll
                for (int ks = 0; ks < 2; ks++) {
                    bf[n][ks][0] = *reinterpret_cast<const uint32_t*>(&Ks[(kv0+n*8+g)*40 + ks*16 + 2*t4    ]);
                    bf[n][ks][1] = *reinterpret_cast<const uint32_t*>(&Ks[(kv0+n*8+g)*40 + ks*16 + 8 + 2*t4]);
                }
            }
        }
        float S[MT][2][4];
#pragma unroll
        for (int mt = 0; mt < MT; mt++)
#pragma unroll
            for (int n = 0; n < 2; n++)
#pragma unroll
                for (int r = 0; r < 4; r++) S[mt][n][r] = 0.f;
#pragma unroll
        for (int mt = 0; mt < MT; mt++)
#pragma unroll
            for (int n = 0; n < 2; n++) {
                if (n < nt) {
                    mma16816(S[mt][n], af[mt][0], bf[n][0][0], bf[n][0][1]);
                    mma16816(S[mt][n], af[mt][1], bf[n][1][0], bf[n][1][1]);
                }
            }
#pragma unroll
        for (int mt = 0; mt < MT; mt++) {
            float mx0 = fmaxf(S[mt][0][0], S[mt][0][1]);
            float mx8 = fmaxf(S[mt][0][2], S[mt][0][3]);
            if (nt == 2) {
                mx0 = fmaxf(mx0, fmaxf(S[mt][1][0], S[mt][1][1]));
                mx8 = fmaxf(mx8, fmaxf(S[mt][1][2], S[mt][1][3]));
            }
            mx0 = fmaxf(mx0, __shfl_xor_sync(0xffffffffu, mx0, 1));
            mx0 = fmaxf(mx0, __shfl_xor_sync(0xffffffffu, mx0, 2));
            mx8 = fmaxf(mx8, __shfl_xor_sync(0xffffffffu, mx8, 1));
            mx8 = fmaxf(mx8, __shfl_xor_sync(0xffffffffu, mx8, 2));
            float mn0 = fmaxf(m[mt][0], mx0), mn8 = fmaxf(m[mt][1], mx8);
            float cr0 = __expf(m[mt][0] - mn0), cr8 = __expf(m[mt][1] - mn8);
            m[mt][0] = mn0; m[mt][1] = mn8;
            uint32_t pa[4];
            float p00 = __expf(S[mt][0][0] - mn0), p01 = __expf(S[mt][0][1] - mn0);
            float p02 = __expf(S[mt][0][2] - mn8), p03 = __expf(S[mt][0][3] - mn8);
            float rs0 = p00 + p01, rs8 = p02 + p03;
            pa[0] = packh2(p00, p01);
            pa[1] = packh2(p02, p03);
            if (nt == 2) {
                float p10 = __expf(S[mt][1][0] - mn0), p11 = __expf(S[mt][1][1] - mn0);
                float p12 = __expf(S[mt][1][2] - mn8), p13 = __expf(S[mt][1][3] - mn8);
                rs0 += p10 + p11; rs8 += p12 + p13;
                pa[2] = packh2(p10, p11);
                pa[3] = packh2(p12, p13);
            } else { pa[2] = 0u; pa[3] = 0u; }
            rs0 += __shfl_xor_sync(0xffffffffu, rs0, 1);
            rs0 += __shfl_xor_sync(0xffffffffu, rs0, 2);
            rs8 += __shfl_xor_sync(0xffffffffu, rs8, 1);
            rs8 += __shfl_xor_sync(0xffffffffu, rs8, 2);
            lsum[mt][0] = lsum[mt][0]*cr0 + rs0;
            lsum[mt][1] = lsum[mt][1]*cr8 + rs8;
#pragma unroll
            for (int j = 0; j < 4; j++) {
                O[mt][j][0] *= cr0; O[mt][j][1] *= cr0;
                O[mt][j][2] *= cr8; O[mt][j][3] *= cr8;
                uint32_t vb0 = *reinterpret_cast<const uint32_t*>(&Vt[(j*8+g)*274 + kv0 + 2*t4    ]);
                uint32_t vb1 = *reinterpret_cast<const uint32_t*>(&Vt[(j*8+g)*274 + kv0 + 8 + 2*t4]);
                mma16816(O[mt][j], pa, vb0, vb1);
            }
        }
    }
#pragma unroll
    for (int mt = 0; mt < MT; mt++) {
        float i0 = 1.0f / lsum[mt][0], i8 = 1.0f / lsum[mt][1];
        int r0 = row0 + mt*16 + g;
        int r1 = r0 + 8;
        int out0, out1;
        if (stage == 0) {
            out0 = bl*NQ + r0;
            out1 = bl*NQ + r1;
        } else {
            out0 = b*4096 + ((l>>3)*8 + (r0>>3))*64 + (l&7)*8 + (r0&7);
            out1 = b*4096 + ((l>>3)*8 + (r1>>3))*64 + (l&7)*8 + (r1&7);
        }
        __half* Od = (stage == 0) ? g_otok : g_o2;
#pragma unroll
        for (int j = 0; j < 4; j++) {
            int chn = hh*32 + j*8 + 2*t4;
            *reinterpret_cast<uint32_t*>(&Od[out0*D_ + chn]) = packh2(O[mt][j][0]*i0, O[mt][j][1]*i0);
            *reinterpret_cast<uint32_t*>(&Od[out1*D_ + chn]) = packh2(O[mt][j][2]*i8, O[mt][j][3]*i8);
        }
    }
}

// ---------------------------------------------------------------------------
extern "C" void kernel_launch(void* const* d_in, const int* in_sizes, int n_in,
                              void* d_out, int out_size) {
    (void)in_sizes; (void)n_in; (void)out_size;
    const float* x        = (const float*)d_in[1];
    const float* grid     = (const float*)d_in[2];
    const float* feature  = (const float*)d_in[3];
    const float* I_inv    = (const float*)d_in[4];
    const float* E_inv    = (const float*)d_in[5];
    const float* bn_fl_g  = (const float*)d_in[6];
    const float* bn_fl_b  = (const float*)d_in[7];
    const float* W_fl     = (const float*)d_in[8];
    const float* bn_fp_g  = (const float*)d_in[9];
    const float* bn_fp_b  = (const float*)d_in[10];
    const float* W_fp     = (const float*)d_in[11];
    const float* W_bev    = (const float*)d_in[12];
    const float* b_bev    = (const float*)d_in[13];
    const float* W_img    = (const float*)d_in[14];
    const float* W_cam    = (const float*)d_in[15];
    const float* aln_g    = (const float*)d_in[16];
    const float* aln_b    = (const float*)d_in[17];
    const float* aWqkv    = (const float*)d_in[18];
    const float* abqkv    = (const float*)d_in[19];
    const float* aWp      = (const float*)d_in[20];
    const float* abp      = (const float*)d_in[21];
    const float* pn_g     = (const float*)d_in[22];
    const float* pn_b     = (const float*)d_in[23];
    const float* Wma      = (const float*)d_in[24];
    const float* bma      = (const float*)d_in[25];
    const float* Wmb      = (const float*)d_in[26];
    const float* bmb      = (const float*)d_in[27];
    const float* post_g   = (const float*)d_in[28];
    const float* post_b   = (const float*)d_in[29];
    float* out = (float*)d_out;

    const int GSM = (64*136 + 128*136) * 2;  // 52224
    const int PSM = 2*128*33*4 + 32*128*4;   // 50176
    const int A1SM = (384 + 264)*4 + (384*40 + 264*40 + 32*274) * 2;  // 71968
    const int A2SM = (64 + 264)*4 + (64*40 + 264*40 + 32*274) * 2;    // 45088
    cudaFuncSetAttribute(k_prep, cudaFuncAttributeMaxDynamicSharedMemorySize, PSM);
    cudaFuncSetAttribute(k_gemm_ep<1>, cudaFuncAttributeMaxDynamicSharedMemorySize, GSM);
    cudaFuncSetAttribute(k_gemm_ep<2>, cudaFuncAttributeMaxDynamicSharedMemorySize, GSM);
    cudaFuncSetAttribute(k_attn_mma<3,8>, cudaFuncAttributeMaxDynamicSharedMemorySize, A1SM);
    cudaFuncSetAttribute(k_attn_mma<1,4>, cudaFuncAttributeMaxDynamicSharedMemorySize, A2SM);

    // prep (weights + activations)
    k_wprep<<<304, 256>>>(aln_g, aln_b, aWqkv, abqkv, pn_g, pn_b, Wma, bma,
                          aWp, Wmb, W_fp, W_fl);
    k_prep<<<B_*N_*88, 128, PSM>>>(feature, I_inv, E_inv, W_img, W_cam,
                                   bn_fp_g, bn_fp_b, bn_fl_g, bn_fl_b);
    k_query<<<NQP/8, 256>>>(grid, x, W_bev, b_bev, E_inv, W_cam);

    // conv GEMMs (jobs 0,1) then all 5 QKV projections (jobs 2..6)
    k_gemm_ep<1><<<1056, 256, GSM>>>(100, nullptr, nullptr, nullptr, nullptr, nullptr);
    k_gemm_ep<1><<<2880, 256, GSM>>>(101, nullptr, nullptr, nullptr, nullptr, nullptr);

    // stage 1
    k_attn_mma<3,8><<<dim3(B_*64, 4), 256, A1SM>>>(0);
    k_gemm_ep<1><<<128, 256, GSM>>>(7, abp, nullptr, nullptr, x, nullptr);      // mean+proj+skip+LN
    k_gemm_ep<1><<<256, 256, GSM>>>(102, nullptr, nullptr, nullptr, nullptr, nullptr);  // gelu a,b
    k_gemm_ep<2><<<128, 256, GSM>>>(10, bmb, nullptr, nullptr, nullptr, nullptr);       // res+LN -> xq1

    // stage 2
    k_gemm_ep<1><<<128, 256, GSM>>>(11, nullptr, nullptr, nullptr, nullptr, nullptr);   // Q2
    k_attn_mma<1,4><<<dim3(B_*64, 4), 128, A2SM>>>(1);
    k_gemm_ep<1><<<128, 256, GSM>>>(12, abp + 128, nullptr, nullptr, nullptr, nullptr); // proj+skip+LN
    k_gemm_ep<1><<<256, 256, GSM>>>(103, nullptr, nullptr, nullptr, nullptr, nullptr);  // gelu a,b
    k_gemm_ep<2><<<128, 256, GSM>>>(15, bmb + 128, post_g, post_b, nullptr, out);       // res+finalLN
}

// round 15
// speedup vs baseline: 1.0387x; 1.0082x over previous
#include <cuda_runtime.h>
#include <cuda_fp16.h>
#include <math.h>
#include <stdint.h>

#define B_   2
#define N_   6
#define FH_  32
#define FW_  88
#define PIX  (FH_*FW_)     // 2816
#define D_   128
#define NKV  264
#define NQ1  384
#define NPX  (B_*N_*PIX)   // 33792
#define NQP  (B_*N_*4096)  // 49152
#define NTK  (B_*4096)     // 8192

// epilogue modes
#define EPI_HALF  0
#define EPI_GELU  1
#define EPI_LN    2
#define EPI_SKLN0 3
#define EPI_SKLN1 4
#define EPI_RESLN 5
#define EPI_FIN   6

// ---------------- scratch globals (no runtime allocation) -------------------
__device__ __align__(16) __half g_fph[NPX*D_];
__device__ __align__(16) __half g_flh[NPX*D_];
__device__ __align__(16) __half g_kimgh[NPX*D_];
__device__ __align__(16) __half g_xq [NQP*D_];
__device__ __align__(16) __half g_xk [NPX*D_];
__device__ __align__(16) __half g_xv [NPX*D_];
__device__ __align__(16) __half g_xq1[NTK*D_];
__device__ __align__(16) __half g_xm [NTK*D_];
__device__ __align__(16) __half g_wfold[6*D_*D_];
__device__ float  g_bfold[6*D_];
__device__ __align__(16) __half g_wafold[2*256*D_];
__device__ float  g_bafold[2*256];
__device__ __align__(16) __half g_wmbT[2*D_*256];
__device__ __align__(16) __half g_wpT[2*D_*D_];
__device__ __align__(16) __half g_wfpH[D_*D_];
__device__ __align__(16) __half g_wflH[D_*D_];
__device__ __align__(16) __half g_qh1[NQP*D_];
__device__ __align__(16) __half g_kh1[NPX*D_];
__device__ __align__(16) __half g_vh1[NPX*D_];
__device__ __align__(16) __half g_qh2[NTK*D_];
__device__ __align__(16) __half g_kh2[NPX*D_];
__device__ __align__(16) __half g_vh2[NPX*D_];
__device__ __align__(16) __half g_otok[B_*64*NQ1*D_];
__device__ __align__(16) __half g_o2[NTK*D_];
__device__ __align__(16) __half g_h[NTK*256];
__device__ __align__(16) float  g_q1[NTK*D_];
__device__ __align__(16) float  g_q2[NTK*D_];

__device__ __forceinline__ void warpRed2(float& s, float& q) {
#pragma unroll
    for (int o = 16; o; o >>= 1) {
        s += __shfl_xor_sync(0xffffffffu, s, o);
        q += __shfl_xor_sync(0xffffffffu, q, o);
    }
}

__device__ __forceinline__ void st_half4(__half* dst, float a, float b, float c, float d) {
    __half2* p = reinterpret_cast<__half2*>(dst);
    p[0] = __floats2half2_rn(a, b);
    p[1] = __floats2half2_rn(c, d);
}

__device__ __forceinline__ uint32_t packh2(float a, float b) {
    __half2 h = __floats2half2_rn(a, b);
    return *reinterpret_cast<uint32_t*>(&h);
}

__device__ __forceinline__ float geluf(float h) {
    return h * 0.5f * (1.0f + erff(h * 0.70710678118654752f));
}

__device__ __forceinline__ void mma16816(float* c, const uint32_t* a,
                                         uint32_t b0, uint32_t b1) {
    asm volatile(
        "mma.sync.aligned.m16n8k16.row.col.f32.f16.f16.f32 "
        "{%0,%1,%2,%3}, {%4,%5,%6,%7}, {%8,%9}, {%0,%1,%2,%3};\n"
        : "+f"(c[0]), "+f"(c[1]), "+f"(c[2]), "+f"(c[3])
        : "r"(a[0]), "r"(a[1]), "r"(a[2]), "r"(a[3]), "r"(b0), "r"(b1));
}

__device__ __forceinline__ void cpa16(void* smem, const void* gmem) {
    uint32_t sa = (uint32_t)__cvta_generic_to_shared(smem);
    asm volatile("cp.async.cg.shared.global [%0], [%1], 16;\n" :: "r"(sa), "l"(gmem));
}

// ---------------- merged weight prep (one launch, block-range dispatch) ------
__global__ void __launch_bounds__(256) k_wprep(
        const float* __restrict__ aln_g, const float* __restrict__ aln_b,
        const float* __restrict__ aWqkv, const float* __restrict__ abqkv,
        const float* __restrict__ pn_g, const float* __restrict__ pn_b,
        const float* __restrict__ Wma, const float* __restrict__ bma,
        const float* __restrict__ aWp, const float* __restrict__ Wmb,
        const float* __restrict__ W_fp, const float* __restrict__ W_fl) {
    __shared__ float sm[16][129];
    __shared__ float bred[16][17];
    int blk = blockIdx.x, tid = threadIdx.x;
    if (blk < 48) {
        int idx = blk >> 3, o0 = (blk & 7) * 16;
        const float* W = aWqkv + idx*16384;
        const float* g = aln_g + idx*128;
        const float* bb = aln_b + idx*128;
        for (int k = tid; k < 2048; k += 256) {
            int c = k >> 4, o = k & 15;
            sm[o][c] = g[c] * W[c*128 + o0 + o];
        }
        {
            int o = tid & 15, cg = tid >> 4;
            float part = 0.f;
#pragma unroll
            for (int cc = 0; cc < 8; cc++) {
                int c = cg*8 + cc;
                part += bb[c] * W[c*128 + o0 + o];
            }
            bred[o][cg] = part;
        }
        __syncthreads();
        for (int k = tid; k < 1024; k += 256) {
            int o = k >> 6, c2 = (k & 63)*2;
            *reinterpret_cast<__half2*>(&g_wfold[idx*16384 + (o0+o)*128 + c2]) =
                __floats2half2_rn(sm[o][c2], sm[o][c2+1]);
        }
        if (tid < 16) {
            float a = 0.f;
#pragma unroll
            for (int cg = 0; cg < 16; cg++) a += bred[tid][cg];
            g_bfold[idx*128 + o0 + tid] = a + abqkv[idx*128 + o0 + tid];
        }
    } else if (blk < 80) {
        int t = blk - 48;
        int s = t >> 4, o0 = (t & 15) * 16;
        const float* W = Wma + s*128*256;
        const float* g = pn_g + s*128;
        const float* bb = pn_b + s*128;
        for (int k = tid; k < 2048; k += 256) {
            int c = k >> 4, o = k & 15;
            sm[o][c] = g[c] * W[c*256 + o0 + o];
        }
        {
            int o = tid & 15, cg = tid >> 4;
            float part = 0.f;
#pragma unroll
            for (int cc = 0; cc < 8; cc++) {
                int c = cg*8 + cc;
                part += bb[c] * W[c*256 + o0 + o];
            }
            bred[o][cg] = part;
        }
        __syncthreads();
        for (int k = tid; k < 1024; k += 256) {
            int o = k >> 6, c2 = (k & 63)*2;
            *reinterpret_cast<__half2*>(&g_wafold[s*32768 + (o0+o)*128 + c2]) =
                __floats2half2_rn(sm[o][c2], sm[o][c2+1]);
        }
        if (tid < 16) {
            float a = 0.f;
#pragma unroll
            for (int cg = 0; cg < 16; cg++) a += bred[tid][cg];
            g_bafold[s*256 + o0 + tid] = a + bma[s*256 + o0 + tid];
        }
    } else if (blk < 176) {
        int t = blk - 80;
        const float* src; __half* dst; int R, C, bx, by;
        if (t < 16)      { src = aWp;          dst = g_wpT;          R=128; C=128; bx=t&3;      by=t>>2; }
        else if (t < 32) { src = aWp+16384;    dst = g_wpT+16384;    R=128; C=128; bx=(t-16)&3; by=(t-16)>>2; }
        else if (t < 64) { src = Wmb;          dst = g_wmbT;         R=256; C=128; bx=(t-32)&3; by=(t-32)>>2; }
        else             { src = Wmb+32768;    dst = g_wmbT+32768;   R=256; C=128; bx=(t-64)&3; by=(t-64)>>2; }
        float (*tb)[33] = reinterpret_cast<float(*)[33]>(&sm[0][0]);
        int c0 = bx*32, r0 = by*32;
        int cx = tid & 31, ry = tid >> 5;
        for (int rr = ry; rr < 32; rr += 8)
            tb[rr][cx] = src[(r0+rr)*C + c0 + cx];
        __syncthreads();
        for (int cc = ry; cc < 32; cc += 8)
            dst[(c0+cc)*R + r0 + cx] = __float2half(tb[cx][cc]);
    } else {
        int t = blk - 176;
        const float* src = (t < 64) ? W_fp : W_fl;
        __half* dst = (t < 64) ? g_wfpH : g_wflH;
        int i = (t & 63)*256 + tid;
        dst[i] = __float2half(src[i]);
    }
}

// ---------------- prep: BN-ReLU fp16 feats + image embedding -----------------
__global__ void __launch_bounds__(128) k_prep(
        const float* __restrict__ feat,
        const float* __restrict__ I_inv, const float* __restrict__ E_inv,
        const float* __restrict__ W_img, const float* __restrict__ W_cam,
        const float* __restrict__ fp_g, const float* __restrict__ fp_b,
        const float* __restrict__ fl_g, const float* __restrict__ fl_b) {
    extern __shared__ float sh[];
    float* sfp  = sh;                 // [128][33]
    float* sfl  = sh + 128*33;
    float* kimg = sh + 2*128*33;      // [32][128]
    int blk = blockIdx.x, tid = threadIdx.x;
    int bn = blk / 88, p0 = (blk % 88) * 32;
    int warp = tid >> 5, lane = tid & 31;

    const float invs = rsqrtf(1.0f + 1e-5f);
    for (int k = tid; k < 4096; k += 128) {
        int c = k >> 5, pp = k & 31;
        float f = feat[(bn*D_ + c)*PIX + p0 + pp];
        sfp[c*33+pp] = fmaxf(f * invs * fp_g[c] + fp_b[c], 0.f);
        sfl[c*33+pp] = fmaxf(f * invs * fl_g[c] + fl_b[c], 0.f);
    }
    float e3[4];
#pragma unroll
    for (int i = 0; i < 4; i++) e3[i] = E_inv[bn*16 + i*4 + 3];
    for (int it = 0; it < 8; it++) {
        int tt = it*4 + warp;
        int p = p0 + tt, fh = p / FW_, fw = p % FW_;
        float px = (float)fw * (480.0f / 87.0f);
        float py = (float)fh * (224.0f / 31.0f);
        float cam[4];
#pragma unroll
        for (int i = 0; i < 3; i++)
            cam[i] = I_inv[bn*9+i*3+0]*px + I_inv[bn*9+i*3+1]*py + I_inv[bn*9+i*3+2];
        cam[3] = 1.0f;
        float dd[4];
#pragma unroll
        for (int i = 0; i < 4; i++)
            dd[i] = E_inv[bn*16+i*4+0]*cam[0] + E_inv[bn*16+i*4+1]*cam[1]
                  + E_inv[bn*16+i*4+2]*cam[2] + E_inv[bn*16+i*4+3]*cam[3];
        int c0 = lane*4;
        float t[4]; float ssum = 0.f, dum = 0.f;
#pragma unroll
        for (int i = 0; i < 4; i++) {
            int c = c0+i;
            float de = W_img[c*4+0]*dd[0] + W_img[c*4+1]*dd[1]
                     + W_img[c*4+2]*dd[2] + W_img[c*4+3]*dd[3];
            float ce = W_cam[c*4+0]*e3[0] + W_cam[c*4+1]*e3[1]
                     + W_cam[c*4+2]*e3[2] + W_cam[c*4+3]*e3[3];
            t[i] = de - ce;
            ssum += t[i]*t[i];
        }
        warpRed2(ssum, dum);
        float inv = 1.0f / fmaxf(sqrtf(ssum), 1e-12f);
#pragma unroll
        for (int i = 0; i < 4; i++) kimg[tt*128 + c0 + i] = t[i]*inv;
    }
    __syncthreads();
    for (int pp = 0; pp < 32; pp++) {
        int row = bn*PIX + p0 + pp;
        g_fph[row*D_ + tid] = __float2half(sfp[tid*33 + pp]);
        g_flh[row*D_ + tid] = __float2half(sfl[tid*33 + pp]);
        g_kimgh[row*D_ + tid] = __float2half(kimg[pp*128 + tid]);
    }
}

// ---------------- query -> LN'd fp16 xhat, warp per pixel --------------------
__global__ void __launch_bounds__(256) k_query(
        const float* __restrict__ grid, const float* __restrict__ x,
        const float* __restrict__ W_bev, const float* __restrict__ b_bev,
        const float* __restrict__ E_inv, const float* __restrict__ W_cam) {
    int tid = threadIdx.x, warp = tid >> 5, lane = tid & 31;
    int u = blockIdx.x*8 + warp;
    int bn = u >> 12, p = u & 4095;
    int b = bn / N_;
    int c0 = lane*4;
    float e3[4];
#pragma unroll
    for (int i = 0; i < 4; i++) e3[i] = E_inv[bn*16 + i*4 + 3];
    float gx = grid[p], gy = grid[4096 + p];
    float t[4]; float ss = 0.f, dum = 0.f;
#pragma unroll
    for (int i = 0; i < 4; i++) {
        int c = c0 + i;
        float we = W_bev[c*2+0]*gx + W_bev[c*2+1]*gy + b_bev[c];
        float ce = W_cam[c*4+0]*e3[0] + W_cam[c*4+1]*e3[1]
                 + W_cam[c*4+2]*e3[2] + W_cam[c*4+3]*e3[3];
        t[i] = we - ce;
        ss += t[i]*t[i];
    }
    warpRed2(ss, dum);
    float inv = 1.0f / fmaxf(sqrtf(ss), 1e-12f);
    float q[4]; float s = 0.f, q2 = 0.f;
#pragma unroll
    for (int i = 0; i < 4; i++) {
        q[i] = t[i]*inv + x[(b*D_ + c0 + i)*4096 + p];
        s += q[i]; q2 += q[i]*q[i];
    }
    warpRed2(s, q2);
    float mean = s*(1.0f/128.0f);
    float var = fmaxf(q2*(1.0f/128.0f) - mean*mean, 0.f);
    float rstd = rsqrtf(var + 1e-5f);
    st_half4(&g_xq[u*D_ + c0],
             (q[0]-mean)*rstd, (q[1]-mean)*rstd, (q[2]-mean)*rstd, (q[3]-mean)*rstd);
}

// ---------------- device-side job table for the unified GEMM -----------------
__device__ __forceinline__ void gemm_job(
        int job, const float* extb,
        const __half*& A, const __half*& B, const float*& bias,
        __half*& oh, float*& of, const float*& aux, const __half*& auxh,
        int& epi, float& scale, int& ldC) {
    const float QS = 0.17677669529663687f;
    scale = 1.f; ldC = 128; aux = nullptr; auxh = nullptr;
    bias = nullptr; oh = nullptr; of = nullptr;
    switch (job) {
    case 0:  A=g_fph; B=g_wfpH; oh=g_xk; auxh=g_kimgh; epi=EPI_LN; break;
    case 1:  A=g_flh; B=g_wflH; oh=g_xv; epi=EPI_LN; break;
    case 2:  A=g_xq;  B=g_wfold;          bias=g_bfold;     oh=g_qh1; epi=EPI_HALF; scale=QS; break;
    case 7:  A=nullptr; B=g_wpT; bias=extb; of=g_q1; oh=g_xm; epi=EPI_SKLN0; break;
    case 8:  A=g_xm;  B=g_wafold;         bias=g_bafold;     oh=g_h;     epi=EPI_GELU; ldC=256; break;
    case 9:  A=g_xm;  B=g_wafold+16384;   bias=g_bafold+128; oh=g_h+128; epi=EPI_GELU; ldC=256; break;
    case 10: A=g_h;   B=g_wmbT; bias=extb; of=g_q1; oh=g_xq1; aux=g_q1; epi=EPI_RESLN; break;
    case 11: A=g_xq1; B=g_wfold+3*16384;  bias=g_bfold+384; oh=g_qh2; epi=EPI_HALF; scale=QS; break;
    case 12: A=g_o2;  B=g_wpT+16384; bias=extb; of=g_q2; oh=g_xm; aux=g_q1; epi=EPI_SKLN1; break;
    case 13: A=g_xm;  B=g_wafold+32768;        bias=g_bafold+256; oh=g_h;     epi=EPI_GELU; ldC=256; break;
    case 14: A=g_xm;  B=g_wafold+32768+16384;  bias=g_bafold+384; oh=g_h+128; epi=EPI_GELU; ldC=256; break;
    default: A=g_h;   B=g_wmbT+32768; bias=extb; aux=g_q2; epi=EPI_FIN; break;
    }
}

// ---------------- unified HMMA GEMM with fused epilogues ---------------------
// C[64][128] per block = A[64][KT*128] @ B[128][KT*128]^T (+ epilogue).
// 256 thr, 8 warps as 2(m) x 4(n); warp tile 32x32.
// jobs 16/17: merged K1+K2 / V1+V2 (A loaded once, two B passes).
template<int KT>
__global__ void __launch_bounds__(256, 3) k_gemm_ep(
        int jobsel, const float* __restrict__ extb,
        const float* __restrict__ extg, const float* __restrict__ extbt,
        const float* __restrict__ extaux, float* __restrict__ extout) {
    int job, tile;
    if (jobsel < 100)       { job = jobsel; tile = blockIdx.x; }
    else if (jobsel == 100) { job = blockIdx.x / 528; tile = blockIdx.x % 528; }
    else if (jobsel == 101) {
        int bx = blockIdx.x;
        if (bx < 768) { job = 2; tile = bx; }
        else { int r2 = bx - 768; job = 16 + r2/528; tile = r2 % 528; }
    }
    else if (jobsel == 102) { job = 8 + (blockIdx.x >> 7); tile = blockIdx.x & 127; }
    else                    { job = 13 + (blockIdx.x >> 7); tile = blockIdx.x & 127; }

    extern __shared__ __half shh[];
    __half* As = shh;                 // [64][136]
    __half* Bs = shh + 64*136;        // [128][136]
    int tid = threadIdx.x;
    int m0 = tile * 64;
    int warp = tid >> 5, lane = tid & 31;
    int wm = (warp & 1) * 32, wn = (warp >> 1) * 32;
    int g = lane >> 2, tg = (lane & 3) * 2;

    if (job >= 16) {
        // merged K or V projections: A once, two B passes
        const __half* Am = (job == 16) ? g_xk : g_xv;
        int r = tid >> 4, q = tid & 15;
#pragma unroll
        for (int rr = r; rr < 64; rr += 16)
            cpa16(&As[rr*136 + q*8], &Am[(m0+rr)*128 + q*8]);
#pragma unroll
        for (int pass = 0; pass < 2; pass++) {
            const __half* Bw2; const float* bias2; __half* oh2;
            if (job == 16) {
                Bw2 = pass ? g_wfold+4*16384 : g_wfold+16384;
                bias2 = pass ? g_bfold+512 : g_bfold+128;
                oh2 = pass ? g_kh2 : g_kh1;
            } else {
                Bw2 = pass ? g_wfold+5*16384 : g_wfold+2*16384;
                bias2 = pass ? g_bfold+640 : g_bfold+256;
                oh2 = pass ? g_vh2 : g_vh1;
            }
#pragma unroll
            for (int rr = r; rr < 128; rr += 16)
                cpa16(&Bs[rr*136 + q*8], &Bw2[rr*128 + q*8]);
            asm volatile("cp.async.commit_group;\n");
            asm volatile("cp.async.wait_group 0;\n");
            __syncthreads();
            float acc[2][4][4];
#pragma unroll
            for (int i = 0; i < 2; i++)
#pragma unroll
                for (int j = 0; j < 4; j++)
#pragma unroll
                    for (int rr2 = 0; rr2 < 4; rr2++) acc[i][j][rr2] = 0.f;
#pragma unroll
            for (int ks = 0; ks < 8; ks++) {
                int k0 = ks*16;
                uint32_t a[2][4];
#pragma unroll
                for (int i = 0; i < 2; i++) {
                    int mb = wm + i*16;
                    a[i][0] = *reinterpret_cast<const uint32_t*>(&As[(mb+g  )*136 + k0+tg  ]);
                    a[i][1] = *reinterpret_cast<const uint32_t*>(&As[(mb+8+g)*136 + k0+tg  ]);
                    a[i][2] = *reinterpret_cast<const uint32_t*>(&As[(mb+g  )*136 + k0+8+tg]);
                    a[i][3] = *reinterpret_cast<const uint32_t*>(&As[(mb+8+g)*136 + k0+8+tg]);
                }
#pragma unroll
                for (int j = 0; j < 4; j++) {
                    uint32_t b0 = *reinterpret_cast<const uint32_t*>(&Bs[(wn+j*8+g)*136 + k0+tg  ]);
                    uint32_t b1 = *reinterpret_cast<const uint32_t*>(&Bs[(wn+j*8+g)*136 + k0+8+tg]);
                    mma16816(acc[0][j], a[0], b0, b1);
                    mma16816(acc[1][j], a[1], b0, b1);
                }
            }
            __syncthreads();
#pragma unroll
            for (int i = 0; i < 2; i++)
#pragma unroll
            for (int j = 0; j < 4; j++) {
                int n = wn + j*8 + tg;
                float b0 = bias2[n], b1 = bias2[n+1];
                int r0 = m0 + wm + i*16 + g, r1 = r0 + 8;
                *reinterpret_cast<uint32_t*>(&oh2[r0*128 + n]) =
                    packh2(acc[i][j][0]+b0, acc[i][j][1]+b1);
                *reinterpret_cast<uint32_t*>(&oh2[r1*128 + n]) =
                    packh2(acc[i][j][2]+b0, acc[i][j][3]+b1);
            }
        }
        return;
    }

    const __half* A; const __half* Bw; const float* bias;
    __half* oh; float* of; const float* aux; const __half* auxh;
    int epi; float scale; int ldC;
    gemm_job(job, extb, A, Bw, bias, oh, of, aux, auxh, epi, scale, ldC);
    if (epi == EPI_SKLN0) aux = extaux;

    const int KD = KT*128;
    float acc[2][4][4];
#pragma unroll
    for (int i = 0; i < 2; i++)
#pragma unroll
        for (int j = 0; j < 4; j++)
#pragma unroll
            for (int r = 0; r < 4; r++) acc[i][j][r] = 0.f;

    for (int kc = 0; kc < KT; kc++) {
        int r = tid >> 4, q = tid & 15;
        if (job == 7) {
            for (int rr = r; rr < 64; rr += 16) {
                int row = m0 + rr;
                int b = row >> 12, p = row & 4095;
                int hh_ = p >> 6, ww = p & 63;
                int l = ((hh_ >> 3) << 3) + (ww >> 3);
                const __half* src = g_otok + ((b*64 + l)*NQ1 + (hh_&7)*8 + (ww&7))*D_ + q*8;
                float s[8];
#pragma unroll
                for (int t = 0; t < 8; t++) s[t] = 0.f;
#pragma unroll
                for (int n = 0; n < 6; n++) {
                    const __half2* pp = reinterpret_cast<const __half2*>(src + n*64*D_);
#pragma unroll
                    for (int t = 0; t < 4; t++) {
                        float2 f = __half22float2(pp[t]);
                        s[t*2] += f.x; s[t*2+1] += f.y;
                    }
                }
                __half2 o[4];
#pragma unroll
                for (int t = 0; t < 4; t++)
                    o[t] = __floats2half2_rn(s[t*2]*(1.f/6.f), s[t*2+1]*(1.f/6.f));
                *reinterpret_cast<int4*>(&As[rr*136 + q*8]) = *reinterpret_cast<int4*>(o);
            }
#pragma unroll
            for (int rr = r; rr < 128; rr += 16)
                cpa16(&Bs[rr*136 + q*8], &Bw[rr*KD + q*8]);
        } else {
#pragma unroll
            for (int rr = r; rr < 64; rr += 16)
                cpa16(&As[rr*136 + q*8], &A[(m0+rr)*KD + kc*128 + q*8]);
#pragma unroll
            for (int rr = r; rr < 128; rr += 16)
                cpa16(&Bs[rr*136 + q*8], &Bw[rr*KD + kc*128 + q*8]);
        }
        asm volatile("cp.async.commit_group;\n");
        asm volatile("cp.async.wait_group 0;\n");
        __syncthreads();
#pragma unroll
        for (int ks = 0; ks < 8; ks++) {
            int k0 = ks*16;
            uint32_t a[2][4];
#pragma unroll
            for (int i = 0; i < 2; i++) {
                int mb = wm + i*16;
                a[i][0] = *reinterpret_cast<const uint32_t*>(&As[(mb+g  )*136 + k0+tg  ]);
                a[i][1] = *reinterpret_cast<const uint32_t*>(&As[(mb+8+g)*136 + k0+tg  ]);
                a[i][2] = *reinterpret_cast<const uint32_t*>(&As[(mb+g  )*136 + k0+8+tg]);
                a[i][3] = *reinterpret_cast<const uint32_t*>(&As[(mb+8+g)*136 + k0+8+tg]);
            }
#pragma unroll
            for (int j = 0; j < 4; j++) {
                uint32_t b0 = *reinterpret_cast<const uint32_t*>(&Bs[(wn+j*8+g)*136 + k0+tg  ]);
                uint32_t b1 = *reinterpret_cast<const uint32_t*>(&Bs[(wn+j*8+g)*136 + k0+8+tg]);
                mma16816(acc[0][j], a[0], b0, b1);
                mma16816(acc[1][j], a[1], b0, b1);
            }
        }
        __syncthreads();
    }

    if (epi <= EPI_GELU) {
#pragma unroll
        for (int i = 0; i < 2; i++)
#pragma unroll
        for (int j = 0; j < 4; j++) {
            int n = wn + j*8 + tg;
            float b0 = bias[n], b1 = bias[n+1];
            int r0 = m0 + wm + i*16 + g, r1 = r0 + 8;
            float v0 = acc[i][j][0]+b0, v1 = acc[i][j][1]+b1;
            float v2 = acc[i][j][2]+b0, v3 = acc[i][j][3]+b1;
            if (epi == EPI_GELU) {
                v0 = geluf(v0); v1 = geluf(v1); v2 = geluf(v2); v3 = geluf(v3);
            } else {
                v0 *= scale; v1 *= scale; v2 *= scale; v3 *= scale;
            }
            *reinterpret_cast<uint32_t*>(&oh[r0*ldC + n]) = packh2(v0, v1);
            *reinterpret_cast<uint32_t*>(&oh[r1*ldC + n]) = packh2(v2, v3);
        }
    } else {
#pragma unroll
        for (int i = 0; i < 2; i++)
#pragma unroll
        for (int j = 0; j < 4; j++) {
            int n = wn + j*8 + tg;
            int r0 = m0 + wm + i*16 + g, r1 = r0 + 8;
            if (bias) {
                float b0 = bias[n], b1 = bias[n+1];
                acc[i][j][0] += b0; acc[i][j][1] += b1;
                acc[i][j][2] += b0; acc[i][j][3] += b1;
            }
            if (auxh) {
                acc[i][j][0] += __half2float(auxh[r0*D_ + n]);
                acc[i][j][1] += __half2float(auxh[r0*D_ + n+1]);
                acc[i][j][2] += __half2float(auxh[r1*D_ + n]);
                acc[i][j][3] += __half2float(auxh[r1*D_ + n+1]);
            }
            if (aux) {
                if (epi == EPI_SKLN0) {
                    int ba = r0 >> 12, pa = r0 & 4095;
                    int bb_ = r1 >> 12, pb = r1 & 4095;
                    acc[i][j][0] += aux[(ba*D_ + n  )*4096 + pa];
                    acc[i][j][1] += aux[(ba*D_ + n+1)*4096 + pa];
                    acc[i][j][2] += aux[(bb_*D_ + n  )*4096 + pb];
                    acc[i][j][3] += aux[(bb_*D_ + n+1)*4096 + pb];
                } else {
                    acc[i][j][0] += aux[r0*D_ + n];
                    acc[i][j][1] += aux[r0*D_ + n+1];
                    acc[i][j][2] += aux[r1*D_ + n];
                    acc[i][j][3] += aux[r1*D_ + n+1];
                }
            }
            if (of) {
                of[r0*D_ + n]   = acc[i][j][0];
                of[r0*D_ + n+1] = acc[i][j][1];
                of[r1*D_ + n]   = acc[i][j][2];
                of[r1*D_ + n+1] = acc[i][j][3];
            }
        }
        float sum[2][2] = {{0,0},{0,0}}, sq[2][2] = {{0,0},{0,0}};
#pragma unroll
        for (int i = 0; i < 2; i++)
#pragma unroll
        for (int j = 0; j < 4; j++) {
            float a0 = acc[i][j][0], a1 = acc[i][j][1];
            float a2 = acc[i][j][2], a3 = acc[i][j][3];
            sum[i][0] += a0 + a1; sq[i][0] += a0*a0 + a1*a1;
            sum[i][1] += a2 + a3; sq[i][1] += a2*a2 + a3*a3;
        }
#pragma unroll
        for (int o = 1; o <= 2; o <<= 1) {
#pragma unroll
            for (int i = 0; i < 2; i++)
#pragma unroll
            for (int rh = 0; rh < 2; rh++) {
                sum[i][rh] += __shfl_xor_sync(0xffffffffu, sum[i][rh], o);
                sq[i][rh]  += __shfl_xor_sync(0xffffffffu, sq[i][rh], o);
            }
        }
        float* sred = reinterpret_cast<float*>(shh);   // [64][8]
        if ((lane & 3) == 0) {
#pragma unroll
            for (int i = 0; i < 2; i++)
#pragma unroll
            for (int rh = 0; rh < 2; rh++) {
                int row = wm + i*16 + rh*8 + g;
                sred[row*8 + (warp >> 1)*2 + 0] = sum[i][rh];
                sred[row*8 + (warp >> 1)*2 + 1] = sq[i][rh];
            }
        }
        __syncthreads();
#pragma unroll
        for (int i = 0; i < 2; i++)
#pragma unroll
        for (int rh = 0; rh < 2; rh++) {
            int row = wm + i*16 + rh*8 + g;
            float s = sred[row*8+0] + sred[row*8+2] + sred[row*8+4] + sred[row*8+6];
            float qq = sred[row*8+1] + sred[row*8+3] + sred[row*8+5] + sred[row*8+7];
            float mean = s*(1.0f/128.0f);
            float var = fmaxf(qq*(1.0f/128.0f) - mean*mean, 0.f);
            float rstd = rsqrtf(var + 1e-5f);
            if (epi == EPI_FIN) {
                int grow = m0 + row;
                int b = grow >> 12, p = grow & 4095;
#pragma unroll
                for (int j = 0; j < 4; j++) {
                    int n = wn + j*8 + tg;
                    extout[(b*D_ + n  )*4096 + p] =
                        (acc[i][j][rh*2+0]-mean)*rstd*extg[n]   + extbt[n];
                    extout[(b*D_ + n+1)*4096 + p] =
                        (acc[i][j][rh*2+1]-mean)*rstd*extg[n+1] + extbt[n+1];
                }
            } else {
#pragma unroll
                for (int j = 0; j < 4; j++) {
                    int n = wn + j*8 + tg;
                    float v0 = (acc[i][j][rh*2+0]-mean)*rstd;
                    float v1 = (acc[i][j][rh*2+1]-mean)*rstd;
                    *reinterpret_cast<uint32_t*>(&oh[(m0+row)*D_ + n]) = packh2(v0, v1);
                }
            }
        }
    }
}

// ---------------- tensor-core flash attention (fp16 in / fp16 out) -----------
template<int MT, int NW>
__global__ void __launch_bounds__(NW*32) k_attn_mma(int stage) {
    const int NQ = MT*16*NW;
    extern __shared__ __half sha[];
    __half* Qs = sha;                  // [NQ][40]
    __half* Ks = Qs + NQ*40;           // [264][40]
    __half* Vt = Ks + 264*40;          // [32][274]
    int bl = blockIdx.x, hh = blockIdx.y, tid = threadIdx.x;
    int b = bl >> 6, l = bl & 63;
    const __half* qsrc; const __half* ksrc; const __half* vsrc;
    if (stage == 0) { qsrc = g_qh1; ksrc = g_kh1; vsrc = g_vh1; }
    else            { qsrc = g_qh2; ksrc = g_kh2; vsrc = g_vh2; }
    for (int idx = tid; idx < NQ*16; idx += NW*32) {
        int row = idx >> 4, c2 = idx & 15;
        int pix;
        if (stage == 0) {
            int n = row >> 6, ij = row & 63;
            pix = (b*N_+n)*4096 + ((l>>3)*8 + (ij>>3))*64 + (l&7)*8 + (ij&7);
        } else {
            pix = b*4096 + ((l>>3)*8 + (row>>3))*64 + (l&7)*8 + (row&7);
        }
        *reinterpret_cast<uint32_t*>(&Qs[row*40 + 2*c2]) =
            *reinterpret_cast<const uint32_t*>(&qsrc[pix*D_ + hh*32 + 2*c2]);
    }
    for (int idx = tid; idx < NKV*16; idx += NW*32) {
        int kv = idx >> 4, c2 = idx & 15;
        int n = kv/44, f = kv%44, f1 = f/11, f2 = f%11;
        int h, w;
        if (stage == 0) { h = (l>>3)*4 + f1; w = (l&7)*11 + f2; }
        else            { h = f1*8 + (l>>3); w = f2*8 + (l&7); }
        int pix = (b*N_+n)*PIX + h*FW_ + w;
        *reinterpret_cast<uint32_t*>(&Ks[kv*40 + 2*c2]) =
            *reinterpret_cast<const uint32_t*>(&ksrc[pix*D_ + hh*32 + 2*c2]);
    }
    for (int idx = tid; idx < NKV*32; idx += NW*32) {
        int kv = idx >> 5, ch = idx & 31;
        int n = kv/44, f = kv%44, f1 = f/11, f2 = f%11;
        int h, w;
        if (stage == 0) { h = (l>>3)*4 + f1; w = (l&7)*11 + f2; }
        else            { h = f1*8 + (l>>3); w = f2*8 + (l&7); }
        int pix = (b*N_+n)*PIX + h*FW_ + w;
        Vt[ch*274 + kv] = vsrc[pix*D_ + hh*32 + ch];
    }
    for (int idx = tid; idx < 32*10; idx += NW*32) {
        int ch = idx / 10, c = idx % 10;
        Vt[ch*274 + 264 + c] = __half(0.f);
    }
    __syncthreads();

    int warp = tid >> 5, lane = tid & 31;
    int g = lane >> 2, t4 = lane & 3;
    int row0 = warp * MT * 16;

    uint32_t af[MT][2][4];
#pragma unroll
    for (int mt = 0; mt < MT; mt++)
#pragma unroll
        for (int ks = 0; ks < 2; ks++) {
            int r = row0 + mt*16, k0 = ks*16;
            af[mt][ks][0] = *reinterpret_cast<const uint32_t*>(&Qs[(r+g  )*40 + k0 + 2*t4    ]);
            af[mt][ks][1] = *reinterpret_cast<const uint32_t*>(&Qs[(r+8+g)*40 + k0 + 2*t4    ]);
            af[mt][ks][2] = *reinterpret_cast<const uint32_t*>(&Qs[(r+g  )*40 + k0 + 8 + 2*t4]);
            af[mt][ks][3] = *reinterpret_cast<const uint32_t*>(&Qs[(r+8+g)*40 + k0 + 8 + 2*t4]);
        }

    float m[MT][2], lsum[MT][2], O[MT][4][4];
#pragma unroll
    for (int mt = 0; mt < MT; mt++) {
        m[mt][0] = -1e30f; m[mt][1] = -1e30f;
        lsum[mt][0] = 0.f; lsum[mt][1] = 0.f;
#pragma unroll
        for (int j = 0; j < 4; j++)
#pragma unroll
            for (int r = 0; r < 4; r++) O[mt][j][r] = 0.f;
    }

    for (int c = 0; c < 17; c++) {
        int kv0 = c*16;
        int nt = (c == 16) ? 1 : 2;
        uint32_t bf[2][2][2];
#pragma unroll
        for (int n = 0; n < 2; n++) {
            if (n < nt) {
#pragma unroll
                for (int ks = 0; ks < 2; ks++) {
                    bf[n][ks][0] = *reinterpret_cast<const uint32_t*>(&Ks[(kv0+n*8+g)*40 + ks*16 + 2*t4    ]);
                    bf[n][ks][1] = *reinterpret_cast<const uint32_t*>(&Ks[(kv0+n*8+g)*40 + ks*16 + 8 + 2*t4]);
                }
            }
        }
        float S[MT][2][4];
#pragma unroll
        for (int mt = 0; mt < MT; mt++)
#pragma unroll
            for (int n = 0; n < 2; n++)
#pragma unroll
                for (int r = 0; r < 4; r++) S[mt][n][r] = 0.f;
#pragma unroll
        for (int mt = 0; mt < MT; mt++)
#pragma unroll
            for (int n = 0; n < 2; n++) {
                if (n < nt) {
                    mma16816(S[mt][n], af[mt][0], bf[n][0][0], bf[n][0][1]);
                    mma16816(S[mt][n], af[mt][1], bf[n][1][0], bf[n][1][1]);
                }
            }
#pragma unroll
        for (int mt = 0; mt < MT; mt++) {
            float mx0 = fmaxf(S[mt][0][0], S[mt][0][1]);
            float mx8 = fmaxf(S[mt][0][2], S[mt][0][3]);
            if (nt == 2) {
                mx0 = fmaxf(mx0, fmaxf(S[mt][1][0], S[mt][1][1]));
                mx8 = fmaxf(mx8, fmaxf(S[mt][1][2], S[mt][1][3]));
            }
            mx0 = fmaxf(mx0, __shfl_xor_sync(0xffffffffu, mx0, 1));
            mx0 = fmaxf(mx0, __shfl_xor_sync(0xffffffffu, mx0, 2));
            mx8 = fmaxf(mx8, __shfl_xor_sync(0xffffffffu, mx8, 1));
            mx8 = fmaxf(mx8, __shfl_xor_sync(0xffffffffu, mx8, 2));
            float mn0 = fmaxf(m[mt][0], mx0), mn8 = fmaxf(m[mt][1], mx8);
            float cr0 = __expf(m[mt][0] - mn0), cr8 = __expf(m[mt][1] - mn8);
            m[mt][0] = mn0; m[mt][1] = mn8;
            uint32_t pa[4];
            float p00 = __expf(S[mt][0][0] - mn0), p01 = __expf(S[mt][0][1] - mn0);
            float p02 = __expf(S[mt][0][2] - mn8), p03 = __expf(S[mt][0][3] - mn8);
            float rs0 = p00 + p01, rs8 = p02 + p03;
            pa[0] = packh2(p00, p01);
            pa[1] = packh2(p02, p03);
            if (nt == 2) {
                float p10 = __expf(S[mt][1][0] - mn0), p11 = __expf(S[mt][1][1] - mn0);
                float p12 = __expf(S[mt][1][2] - mn8), p13 = __expf(S[mt][1][3] - mn8);
                rs0 += p10 + p11; rs8 += p12 + p13;
                pa[2] = packh2(p10, p11);
                pa[3] = packh2(p12, p13);
            } else { pa[2] = 0u; pa[3] = 0u; }
            rs0 += __shfl_xor_sync(0xffffffffu, rs0, 1);
            rs0 += __shfl_xor_sync(0xffffffffu, rs0, 2);
            rs8 += __shfl_xor_sync(0xffffffffu, rs8, 1);
            rs8 += __shfl_xor_sync(0xffffffffu, rs8, 2);
            lsum[mt][0] = lsum[mt][0]*cr0 + rs0;
            lsum[mt][1] = lsum[mt][1]*cr8 + rs8;
#pragma unroll
            for (int j = 0; j < 4; j++) {
                O[mt][j][0] *= cr0; O[mt][j][1] *= cr0;
                O[mt][j][2] *= cr8; O[mt][j][3] *= cr8;
                uint32_t vb0 = *reinterpret_cast<const uint32_t*>(&Vt[(j*8+g)*274 + kv0 + 2*t4    ]);
                uint32_t vb1 = *reinterpret_cast<const uint32_t*>(&Vt[(j*8+g)*274 + kv0 + 8 + 2*t4]);
                mma16816(O[mt][j], pa, vb0, vb1);
            }
        }
    }
#pragma unroll
    for (int mt = 0; mt < MT; mt++) {
        float i0 = 1.0f / lsum[mt][0], i8 = 1.0f / lsum[mt][1];
        int r0 = row0 + mt*16 + g;
        int r1 = r0 + 8;
        int out0, out1;
        if (stage == 0) {
            out0 = bl*NQ + r0;
            out1 = bl*NQ + r1;
        } else {
            out0 = b*4096 + ((l>>3)*8 + (r0>>3))*64 + (l&7)*8 + (r0&7);
            out1 = b*4096 + ((l>>3)*8 + (r1>>3))*64 + (l&7)*8 + (r1&7);
        }
        __half* Od = (stage == 0) ? g_otok : g_o2;
#pragma unroll
        for (int j = 0; j < 4; j++) {
            int chn = hh*32 + j*8 + 2*t4;
            *reinterpret_cast<uint32_t*>(&Od[out0*D_ + chn]) = packh2(O[mt][j][0]*i0, O[mt][j][1]*i0);
            *reinterpret_cast<uint32_t*>(&Od[out1*D_ + chn]) = packh2(O[mt][j][2]*i8, O[mt][j][3]*i8);
        }
    }
}

// ---------------------------------------------------------------------------
extern "C" void kernel_launch(void* const* d_in, const int* in_sizes, int n_in,
                              void* d_out, int out_size) {
    (void)in_sizes; (void)n_in; (void)out_size;
    const float* x        = (const float*)d_in[1];
    const float* grid     = (const float*)d_in[2];
    const float* feature  = (const float*)d_in[3];
    const float* I_inv    = (const float*)d_in[4];
    const float* E_inv    = (const float*)d_in[5];
    const float* bn_fl_g  = (const float*)d_in[6];
    const float* bn_fl_b  = (const float*)d_in[7];
    const float* W_fl     = (const float*)d_in[8];
    const float* bn_fp_g  = (const float*)d_in[9];
    const float* bn_fp_b  = (const float*)d_in[10];
    const float* W_fp     = (const float*)d_in[11];
    const float* W_bev    = (const float*)d_in[12];
    const float* b_bev    = (const float*)d_in[13];
    const float* W_img    = (const float*)d_in[14];
    const float* W_cam    = (const float*)d_in[15];
    const float* aln_g    = (const float*)d_in[16];
    const float* aln_b    = (const float*)d_in[17];
    const float* aWqkv    = (const float*)d_in[18];
    const float* abqkv    = (const float*)d_in[19];
    const float* aWp      = (const float*)d_in[20];
    const float* abp      = (const float*)d_in[21];
    const float* pn_g     = (const float*)d_in[22];
    const float* pn_b     = (const float*)d_in[23];
    const float* Wma      = (const float*)d_in[24];
    const float* bma      = (const float*)d_in[25];
    const float* Wmb      = (const float*)d_in[26];
    const float* bmb      = (const float*)d_in[27];
    const float* post_g   = (const float*)d_in[28];
    const float* post_b   = (const float*)d_in[29];
    float* out = (float*)d_out;

    const int GSM = (64*136 + 128*136) * 2;  // 52224
    const int PSM = 2*128*33*4 + 32*128*4;   // 50176
    const int A1SM = (384*40 + 264*40 + 32*274) * 2;   // 69376
    const int A2SM = (64*40 + 264*40 + 32*274) * 2;    // 43776
    cudaFuncSetAttribute(k_prep, cudaFuncAttributeMaxDynamicSharedMemorySize, PSM);
    cudaFuncSetAttribute(k_gemm_ep<1>, cudaFuncAttributeMaxDynamicSharedMemorySize, GSM);
    cudaFuncSetAttribute(k_gemm_ep<2>, cudaFuncAttributeMaxDynamicSharedMemorySize, GSM);
    cudaFuncSetAttribute(k_attn_mma<3,8>, cudaFuncAttributeMaxDynamicSharedMemorySize, A1SM);
    cudaFuncSetAttribute(k_attn_mma<1,4>, cudaFuncAttributeMaxDynamicSharedMemorySize, A2SM);

    // prep (weights + activations)
    k_wprep<<<304, 256>>>(aln_g, aln_b, aWqkv, abqkv, pn_g, pn_b, Wma, bma,
                          aWp, Wmb, W_fp, W_fl);
    k_prep<<<B_*N_*88, 128, PSM>>>(feature, I_inv, E_inv, W_img, W_cam,
                                   bn_fp_g, bn_fp_b, bn_fl_g, bn_fl_b);
    k_query<<<NQP/8, 256>>>(grid, x, W_bev, b_bev, E_inv, W_cam);

    // conv GEMMs (jobs 0,1) then Q1 + merged K/V projections
    k_gemm_ep<1><<<1056, 256, GSM>>>(100, nullptr, nullptr, nullptr, nullptr, nullptr);
    k_gemm_ep<1><<<1824, 256, GSM>>>(101, nullptr, nullptr, nullptr, nullptr, nullptr);

    // stage 1
    k_attn_mma<3,8><<<dim3(B_*64, 4), 256, A1SM>>>(0);
    k_gemm_ep<1><<<128, 256, GSM>>>(7, abp, nullptr, nullptr, x, nullptr);      // mean+proj+skip+LN
    k_gemm_ep<1><<<256, 256, GSM>>>(102, nullptr, nullptr, nullptr, nullptr, nullptr);  // gelu a,b
    k_gemm_ep<2><<<128, 256, GSM>>>(10, bmb, nullptr, nullptr, nullptr, nullptr);       // res+LN -> xq1

    // stage 2
    k_gemm_ep<1><<<128, 256, GSM>>>(11, nullptr, nullptr, nullptr, nullptr, nullptr);   // Q2
    k_attn_mma<1,4><<<dim3(B_*64, 4), 128, A2SM>>>(1);
    k_gemm_ep<1><<<128, 256, GSM>>>(12, abp + 128, nullptr, nullptr, nullptr, nullptr); // proj+skip+LN
    k_gemm_ep<1><<<256, 256, GSM>>>(103, nullptr, nullptr, nullptr, nullptr, nullptr);  // gelu a,b
    k_gemm_ep<2><<<128, 256, GSM>>>(15, bmb + 128, post_g, post_b, nullptr, out);       // res+finalLN
}

// round 16
// speedup vs baseline: 1.0437x; 1.0048x over previous
#include <cuda_runtime.h>
#include <cuda_fp16.h>
#include <math.h>
#include <stdint.h>

#define B_   2
#define N_   6
#define FH_  32
#define FW_  88
#define PIX  (FH_*FW_)     // 2816
#define D_   128
#define NKV  264
#define NQ1  384
#define NPX  (B_*N_*PIX)   // 33792
#define NQP  (B_*N_*4096)  // 49152
#define NTK  (B_*4096)     // 8192

// epilogue modes
#define EPI_HALF  0
#define EPI_GELU  1
#define EPI_LN    2
#define EPI_SKLN0 3
#define EPI_SKLN1 4
#define EPI_RESLN 5
#define EPI_FIN   6

// ---------------- scratch globals (no runtime allocation) -------------------
__device__ __align__(16) __half g_fph[NPX*D_];
__device__ __align__(16) __half g_flh[NPX*D_];
__device__ __align__(16) __half g_kimgh[NPX*D_];
__device__ __align__(16) __half g_xq [NQP*D_];
__device__ __align__(16) __half g_xk [NPX*D_];
__device__ __align__(16) __half g_xv [NPX*D_];
__device__ __align__(16) __half g_xq1[NTK*D_];
__device__ __align__(16) __half g_xm [NTK*D_];
__device__ __align__(16) __half g_wfold[6*D_*D_];
__device__ float  g_bfold[6*D_];
__device__ __align__(16) __half g_wafold[2*256*D_];
__device__ float  g_bafold[2*256];
__device__ __align__(16) __half g_wmbT[2*D_*256];
__device__ __align__(16) __half g_wpT[2*D_*D_];
__device__ __align__(16) __half g_wfpH[D_*D_];
__device__ __align__(16) __half g_wflH[D_*D_];
__device__ __align__(16) __half g_qh1[NQP*D_];
__device__ __align__(16) __half g_kh1[NPX*D_];
__device__ __align__(16) __half g_vh1[NPX*D_];
__device__ __align__(16) __half g_qh2[NTK*D_];
__device__ __align__(16) __half g_kh2[NPX*D_];
__device__ __align__(16) __half g_vh2[NPX*D_];
__device__ __align__(16) __half g_otok[B_*64*NQ1*D_];
__device__ __align__(16) __half g_o2[NTK*D_];
__device__ __align__(16) __half g_h[NTK*256];
__device__ __align__(16) float  g_q1[NTK*D_];
__device__ __align__(16) float  g_q2[NTK*D_];

__device__ __forceinline__ void warpRed2(float& s, float& q) {
#pragma unroll
    for (int o = 16; o; o >>= 1) {
        s += __shfl_xor_sync(0xffffffffu, s, o);
        q += __shfl_xor_sync(0xffffffffu, q, o);
    }
}

__device__ __forceinline__ void st_half4(__half* dst, float a, float b, float c, float d) {
    __half2* p = reinterpret_cast<__half2*>(dst);
    p[0] = __floats2half2_rn(a, b);
    p[1] = __floats2half2_rn(c, d);
}

__device__ __forceinline__ uint32_t packh2(float a, float b) {
    __half2 h = __floats2half2_rn(a, b);
    return *reinterpret_cast<uint32_t*>(&h);
}

__device__ __forceinline__ float geluf(float h) {
    return h * 0.5f * (1.0f + erff(h * 0.70710678118654752f));
}

__device__ __forceinline__ void mma16816(float* c, const uint32_t* a,
                                         uint32_t b0, uint32_t b1) {
    asm volatile(
        "mma.sync.aligned.m16n8k16.row.col.f32.f16.f16.f32 "
        "{%0,%1,%2,%3}, {%4,%5,%6,%7}, {%8,%9}, {%0,%1,%2,%3};\n"
        : "+f"(c[0]), "+f"(c[1]), "+f"(c[2]), "+f"(c[3])
        : "r"(a[0]), "r"(a[1]), "r"(a[2]), "r"(a[3]), "r"(b0), "r"(b1));
}

__device__ __forceinline__ void cpa16(void* smem, const void* gmem) {
    uint32_t sa = (uint32_t)__cvta_generic_to_shared(smem);
    asm volatile("cp.async.cg.shared.global [%0], [%1], 16;\n" :: "r"(sa), "l"(gmem));
}

// ---------------- merged weight prep (one launch, block-range dispatch) ------
__global__ void __launch_bounds__(256) k_wprep(
        const float* __restrict__ aln_g, const float* __restrict__ aln_b,
        const float* __restrict__ aWqkv, const float* __restrict__ abqkv,
        const float* __restrict__ pn_g, const float* __restrict__ pn_b,
        const float* __restrict__ Wma, const float* __restrict__ bma,
        const float* __restrict__ aWp, const float* __restrict__ Wmb,
        const float* __restrict__ W_fp, const float* __restrict__ W_fl) {
    __shared__ float sm[16][129];
    __shared__ float bred[16][17];
    int blk = blockIdx.x, tid = threadIdx.x;
    if (blk < 48) {
        int idx = blk >> 3, o0 = (blk & 7) * 16;
        const float* W = aWqkv + idx*16384;
        const float* g = aln_g + idx*128;
        const float* bb = aln_b + idx*128;
        for (int k = tid; k < 2048; k += 256) {
            int c = k >> 4, o = k & 15;
            sm[o][c] = g[c] * W[c*128 + o0 + o];
        }
        {
            int o = tid & 15, cg = tid >> 4;
            float part = 0.f;
#pragma unroll
            for (int cc = 0; cc < 8; cc++) {
                int c = cg*8 + cc;
                part += bb[c] * W[c*128 + o0 + o];
            }
            bred[o][cg] = part;
        }
        __syncthreads();
        for (int k = tid; k < 1024; k += 256) {
            int o = k >> 6, c2 = (k & 63)*2;
            *reinterpret_cast<__half2*>(&g_wfold[idx*16384 + (o0+o)*128 + c2]) =
                __floats2half2_rn(sm[o][c2], sm[o][c2+1]);
        }
        if (tid < 16) {
            float a = 0.f;
#pragma unroll
            for (int cg = 0; cg < 16; cg++) a += bred[tid][cg];
            g_bfold[idx*128 + o0 + tid] = a + abqkv[idx*128 + o0 + tid];
        }
    } else if (blk < 80) {
        int t = blk - 48;
        int s = t >> 4, o0 = (t & 15) * 16;
        const float* W = Wma + s*128*256;
        const float* g = pn_g + s*128;
        const float* bb = pn_b + s*128;
        for (int k = tid; k < 2048; k += 256) {
            int c = k >> 4, o = k & 15;
            sm[o][c] = g[c] * W[c*256 + o0 + o];
        }
        {
            int o = tid & 15, cg = tid >> 4;
            float part = 0.f;
#pragma unroll
            for (int cc = 0; cc < 8; cc++) {
                int c = cg*8 + cc;
                part += bb[c] * W[c*256 + o0 + o];
            }
            bred[o][cg] = part;
        }
        __syncthreads();
        for (int k = tid; k < 1024; k += 256) {
            int o = k >> 6, c2 = (k & 63)*2;
            *reinterpret_cast<__half2*>(&g_wafold[s*32768 + (o0+o)*128 + c2]) =
                __floats2half2_rn(sm[o][c2], sm[o][c2+1]);
        }
        if (tid < 16) {
            float a = 0.f;
#pragma unroll
            for (int cg = 0; cg < 16; cg++) a += bred[tid][cg];
            g_bafold[s*256 + o0 + tid] = a + bma[s*256 + o0 + tid];
        }
    } else if (blk < 176) {
        int t = blk - 80;
        const float* src; __half* dst; int R, C, bx, by;
        if (t < 16)      { src = aWp;          dst = g_wpT;          R=128; C=128; bx=t&3;      by=t>>2; }
        else if (t < 32) { src = aWp+16384;    dst = g_wpT+16384;    R=128; C=128; bx=(t-16)&3; by=(t-16)>>2; }
        else if (t < 64) { src = Wmb;          dst = g_wmbT;         R=256; C=128; bx=(t-32)&3; by=(t-32)>>2; }
        else             { src = Wmb+32768;    dst = g_wmbT+32768;   R=256; C=128; bx=(t-64)&3; by=(t-64)>>2; }
        float (*tb)[33] = reinterpret_cast<float(*)[33]>(&sm[0][0]);
        int c0 = bx*32, r0 = by*32;
        int cx = tid & 31, ry = tid >> 5;
        for (int rr = ry; rr < 32; rr += 8)
            tb[rr][cx] = src[(r0+rr)*C + c0 + cx];
        __syncthreads();
        for (int cc = ry; cc < 32; cc += 8)
            dst[(c0+cc)*R + r0 + cx] = __float2half(tb[cx][cc]);
    } else {
        int t = blk - 176;
        const float* src = (t < 64) ? W_fp : W_fl;
        __half* dst = (t < 64) ? g_wfpH : g_wflH;
        int i = (t & 63)*256 + tid;
        dst[i] = __float2half(src[i]);
    }
}

// ---------------- prep: BN-ReLU fp16 feats + image embedding -----------------
__global__ void __launch_bounds__(128) k_prep(
        const float* __restrict__ feat,
        const float* __restrict__ I_inv, const float* __restrict__ E_inv,
        const float* __restrict__ W_img, const float* __restrict__ W_cam,
        const float* __restrict__ fp_g, const float* __restrict__ fp_b,
        const float* __restrict__ fl_g, const float* __restrict__ fl_b) {
    extern __shared__ float sh[];
    float* sfp  = sh;                 // [128][33]
    float* sfl  = sh + 128*33;
    float* kimg = sh + 2*128*33;      // [32][128]
    int blk = blockIdx.x, tid = threadIdx.x;
    int bn = blk / 88, p0 = (blk % 88) * 32;
    int warp = tid >> 5, lane = tid & 31;

    const float invs = rsqrtf(1.0f + 1e-5f);
    for (int k = tid; k < 4096; k += 128) {
        int c = k >> 5, pp = k & 31;
        float f = feat[(bn*D_ + c)*PIX + p0 + pp];
        sfp[c*33+pp] = fmaxf(f * invs * fp_g[c] + fp_b[c], 0.f);
        sfl[c*33+pp] = fmaxf(f * invs * fl_g[c] + fl_b[c], 0.f);
    }
    float e3[4];
#pragma unroll
    for (int i = 0; i < 4; i++) e3[i] = E_inv[bn*16 + i*4 + 3];
    for (int it = 0; it < 8; it++) {
        int tt = it*4 + warp;
        int p = p0 + tt, fh = p / FW_, fw = p % FW_;
        float px = (float)fw * (480.0f / 87.0f);
        float py = (float)fh * (224.0f / 31.0f);
        float cam[4];
#pragma unroll
        for (int i = 0; i < 3; i++)
            cam[i] = I_inv[bn*9+i*3+0]*px + I_inv[bn*9+i*3+1]*py + I_inv[bn*9+i*3+2];
        cam[3] = 1.0f;
        float dd[4];
#pragma unroll
        for (int i = 0; i < 4; i++)
            dd[i] = E_inv[bn*16+i*4+0]*cam[0] + E_inv[bn*16+i*4+1]*cam[1]
                  + E_inv[bn*16+i*4+2]*cam[2] + E_inv[bn*16+i*4+3]*cam[3];
        int c0 = lane*4;
        float t[4]; float ssum = 0.f, dum = 0.f;
#pragma unroll
        for (int i = 0; i < 4; i++) {
            int c = c0+i;
            float de = W_img[c*4+0]*dd[0] + W_img[c*4+1]*dd[1]
                     + W_img[c*4+2]*dd[2] + W_img[c*4+3]*dd[3];
            float ce = W_cam[c*4+0]*e3[0] + W_cam[c*4+1]*e3[1]
                     + W_cam[c*4+2]*e3[2] + W_cam[c*4+3]*e3[3];
            t[i] = de - ce;
            ssum += t[i]*t[i];
        }
        warpRed2(ssum, dum);
        float inv = 1.0f / fmaxf(sqrtf(ssum), 1e-12f);
#pragma unroll
        for (int i = 0; i < 4; i++) kimg[tt*128 + c0 + i] = t[i]*inv;
    }
    __syncthreads();
    for (int pp = 0; pp < 32; pp++) {
        int row = bn*PIX + p0 + pp;
        g_fph[row*D_ + tid] = __float2half(sfp[tid*33 + pp]);
        g_flh[row*D_ + tid] = __float2half(sfl[tid*33 + pp]);
        g_kimgh[row*D_ + tid] = __float2half(kimg[pp*128 + tid]);
    }
}

// ---------------- query -> LN'd fp16 xhat, warp per pixel --------------------
__global__ void __launch_bounds__(256) k_query(
        const float* __restrict__ grid, const float* __restrict__ x,
        const float* __restrict__ W_bev, const float* __restrict__ b_bev,
        const float* __restrict__ E_inv, const float* __restrict__ W_cam) {
    int tid = threadIdx.x, warp = tid >> 5, lane = tid & 31;
    int u = blockIdx.x*8 + warp;
    int bn = u >> 12, p = u & 4095;
    int b = bn / N_;
    int c0 = lane*4;
    float e3[4];
#pragma unroll
    for (int i = 0; i < 4; i++) e3[i] = E_inv[bn*16 + i*4 + 3];
    float gx = grid[p], gy = grid[4096 + p];
    float t[4]; float ss = 0.f, dum = 0.f;
#pragma unroll
    for (int i = 0; i < 4; i++) {
        int c = c0 + i;
        float we = W_bev[c*2+0]*gx + W_bev[c*2+1]*gy + b_bev[c];
        float ce = W_cam[c*4+0]*e3[0] + W_cam[c*4+1]*e3[1]
                 + W_cam[c*4+2]*e3[2] + W_cam[c*4+3]*e3[3];
        t[i] = we - ce;
        ss += t[i]*t[i];
    }
    warpRed2(ss, dum);
    float inv = 1.0f / fmaxf(sqrtf(ss), 1e-12f);
    float q[4]; float s = 0.f, q2 = 0.f;
#pragma unroll
    for (int i = 0; i < 4; i++) {
        q[i] = t[i]*inv + x[(b*D_ + c0 + i)*4096 + p];
        s += q[i]; q2 += q[i]*q[i];
    }
    warpRed2(s, q2);
    float mean = s*(1.0f/128.0f);
    float var = fmaxf(q2*(1.0f/128.0f) - mean*mean, 0.f);
    float rstd = rsqrtf(var + 1e-5f);
    st_half4(&g_xq[u*D_ + c0],
             (q[0]-mean)*rstd, (q[1]-mean)*rstd, (q[2]-mean)*rstd, (q[3]-mean)*rstd);
}

// ---------------- device-side job table for the unified GEMM -----------------
__device__ __forceinline__ void gemm_job(
        int job, const float* extb,
        const __half*& A, const __half*& B, const float*& bias,
        __half*& oh, float*& of, const float*& aux, const __half*& auxh,
        int& epi, float& scale, int& ldC) {
    const float QS = 0.17677669529663687f;
    scale = 1.f; ldC = 128; aux = nullptr; auxh = nullptr;
    bias = nullptr; oh = nullptr; of = nullptr;
    switch (job) {
    case 0:  A=g_fph; B=g_wfpH; oh=g_xk; auxh=g_kimgh; epi=EPI_LN; break;
    case 1:  A=g_flh; B=g_wflH; oh=g_xv; epi=EPI_LN; break;
    case 2:  A=g_xq;  B=g_wfold;          bias=g_bfold;     oh=g_qh1; epi=EPI_HALF; scale=QS; break;
    case 3:  A=g_xk;  B=g_wfold+16384;    bias=g_bfold+128; oh=g_kh1; epi=EPI_HALF; break;
    case 4:  A=g_xv;  B=g_wfold+2*16384;  bias=g_bfold+256; oh=g_vh1; epi=EPI_HALF; break;
    case 5:  A=g_xk;  B=g_wfold+4*16384;  bias=g_bfold+512; oh=g_kh2; epi=EPI_HALF; break;
    case 6:  A=g_xv;  B=g_wfold+5*16384;  bias=g_bfold+640; oh=g_vh2; epi=EPI_HALF; break;
    case 7:  A=nullptr; B=g_wpT; bias=extb; of=g_q1; oh=g_xm; epi=EPI_SKLN0; break;
    case 8:  A=g_xm;  B=g_wafold;         bias=g_bafold;     oh=g_h;     epi=EPI_GELU; ldC=256; break;
    case 9:  A=g_xm;  B=g_wafold+16384;   bias=g_bafold+128; oh=g_h+128; epi=EPI_GELU; ldC=256; break;
    case 10: A=g_h;   B=g_wmbT; bias=extb; of=g_q1; oh=g_xq1; aux=g_q1; epi=EPI_RESLN; break;
    case 11: A=g_xq1; B=g_wfold+3*16384;  bias=g_bfold+384; oh=g_qh2; epi=EPI_HALF; scale=QS; break;
    case 12: A=g_o2;  B=g_wpT+16384; bias=extb; of=g_q2; oh=g_xm; aux=g_q1; epi=EPI_SKLN1; break;
    case 13: A=g_xm;  B=g_wafold+32768;        bias=g_bafold+256; oh=g_h;     epi=EPI_GELU; ldC=256; break;
    case 14: A=g_xm;  B=g_wafold+32768+16384;  bias=g_bafold+384; oh=g_h+128; epi=EPI_GELU; ldC=256; break;
    default: A=g_h;   B=g_wmbT+32768; bias=extb; aux=g_q2; epi=EPI_FIN; break;
    }
}

// ---------------- unified HMMA GEMM with fused epilogues ---------------------
// C[64][128] per tile = A[64][KT*128] @ B[128][KT*128]^T (+ epilogue).
// 256 thr, 8 warps as 2(m) x 4(n); warp tile 32x32.
// Big launches (jobsel 100/101): 4 tiles per block, B resident, A double-buffered.
template<int KT>
__global__ void __launch_bounds__(256, 3) k_gemm_ep(
        int jobsel, const float* __restrict__ extb,
        const float* __restrict__ extg, const float* __restrict__ extbt,
        const float* __restrict__ extaux, float* __restrict__ extout) {
    extern __shared__ __half shh[];
    int tid = threadIdx.x;
    int warp = tid >> 5, lane = tid & 31;
    int wm = (warp & 1) * 32, wn = (warp >> 1) * 32;
    int g = lane >> 2, tg = (lane & 3) * 2;

    if (jobsel == 100 || jobsel == 101) {
        // ---- multi-tile path: B resident, A double-buffered, 4 tiles/block ----
        int job, tile0;
        if (jobsel == 100) { job = blockIdx.x / 132; tile0 = (blockIdx.x % 132) * 4; }
        else {
            int bx = blockIdx.x;
            if (bx < 192) { job = 2; tile0 = bx * 4; }
            else { int r2 = bx - 192; job = 3 + r2/132; tile0 = (r2 % 132) * 4; }
        }
        const __half* A; const __half* Bw; const float* bias;
        __half* oh; float* of; const float* aux; const __half* auxh;
        int epi; float scale; int ldC;
        gemm_job(job, nullptr, A, Bw, bias, oh, of, aux, auxh, epi, scale, ldC);

        __half* AsB[2] = { shh, shh + 8704 };
        __half* Bs = shh + 17408;                 // [128][136]
        float* sred = reinterpret_cast<float*>(shh + 34816);  // [64][8]
        int r = tid >> 4, q = tid & 15;
#pragma unroll
        for (int rr = r; rr < 128; rr += 16)
            cpa16(&Bs[rr*136 + q*8], &Bw[rr*128 + q*8]);
#pragma unroll
        for (int rr = r; rr < 64; rr += 16)
            cpa16(&AsB[0][rr*136 + q*8], &A[(tile0*64+rr)*128 + q*8]);
        asm volatile("cp.async.commit_group;\n");
        asm volatile("cp.async.wait_group 0;\n");
        __syncthreads();
#pragma unroll
        for (int t = 0; t < 4; t++) {
            __half* Ac = AsB[t & 1];
            if (t < 3) {
                __half* An = AsB[(t+1) & 1];
#pragma unroll
                for (int rr = r; rr < 64; rr += 16)
                    cpa16(&An[rr*136 + q*8], &A[((tile0+t+1)*64+rr)*128 + q*8]);
                asm volatile("cp.async.commit_group;\n");
            }
            float acc[2][4][4];
#pragma unroll
            for (int i = 0; i < 2; i++)
#pragma unroll
                for (int j = 0; j < 4; j++)
#pragma unroll
                    for (int rr2 = 0; rr2 < 4; rr2++) acc[i][j][rr2] = 0.f;
#pragma unroll
            for (int ks = 0; ks < 8; ks++) {
                int k0 = ks*16;
                uint32_t a[2][4];
#pragma unroll
                for (int i = 0; i < 2; i++) {
                    int mb = wm + i*16;
                    a[i][0] = *reinterpret_cast<const uint32_t*>(&Ac[(mb+g  )*136 + k0+tg  ]);
                    a[i][1] = *reinterpret_cast<const uint32_t*>(&Ac[(mb+8+g)*136 + k0+tg  ]);
                    a[i][2] = *reinterpret_cast<const uint32_t*>(&Ac[(mb+g  )*136 + k0+8+tg]);
                    a[i][3] = *reinterpret_cast<const uint32_t*>(&Ac[(mb+8+g)*136 + k0+8+tg]);
                }
#pragma unroll
                for (int j = 0; j < 4; j++) {
                    uint32_t b0 = *reinterpret_cast<const uint32_t*>(&Bs[(wn+j*8+g)*136 + k0+tg  ]);
                    uint32_t b1 = *reinterpret_cast<const uint32_t*>(&Bs[(wn+j*8+g)*136 + k0+8+tg]);
                    mma16816(acc[0][j], a[0], b0, b1);
                    mma16816(acc[1][j], a[1], b0, b1);
                }
            }
            int m0 = (tile0 + t) * 64;
            if (epi == EPI_HALF) {
#pragma unroll
                for (int i = 0; i < 2; i++)
#pragma unroll
                for (int j = 0; j < 4; j++) {
                    int n = wn + j*8 + tg;
                    float b0 = bias[n], b1 = bias[n+1];
                    int r0 = m0 + wm + i*16 + g, r1 = r0 + 8;
                    *reinterpret_cast<uint32_t*>(&oh[r0*128 + n]) =
                        packh2((acc[i][j][0]+b0)*scale, (acc[i][j][1]+b1)*scale);
                    *reinterpret_cast<uint32_t*>(&oh[r1*128 + n]) =
                        packh2((acc[i][j][2]+b0)*scale, (acc[i][j][3]+b1)*scale);
                }
            } else {
                // EPI_LN (conv): add auxh, row-LN, fp16 out
#pragma unroll
                for (int i = 0; i < 2; i++)
#pragma unroll
                for (int j = 0; j < 4; j++) {
                    int n = wn + j*8 + tg;
                    int r0 = m0 + wm + i*16 + g, r1 = r0 + 8;
                    if (auxh) {
                        acc[i][j][0] += __half2float(auxh[r0*D_ + n]);
                        acc[i][j][1] += __half2float(auxh[r0*D_ + n+1]);
                        acc[i][j][2] += __half2float(auxh[r1*D_ + n]);
                        acc[i][j][3] += __half2float(auxh[r1*D_ + n+1]);
                    }
                }
                float sum[2][2] = {{0,0},{0,0}}, sq[2][2] = {{0,0},{0,0}};
#pragma unroll
                for (int i = 0; i < 2; i++)
#pragma unroll
                for (int j = 0; j < 4; j++) {
                    float a0 = acc[i][j][0], a1 = acc[i][j][1];
                    float a2 = acc[i][j][2], a3 = acc[i][j][3];
                    sum[i][0] += a0 + a1; sq[i][0] += a0*a0 + a1*a1;
                    sum[i][1] += a2 + a3; sq[i][1] += a2*a2 + a3*a3;
                }
#pragma unroll
                for (int o = 1; o <= 2; o <<= 1) {
#pragma unroll
                    for (int i = 0; i < 2; i++)
#pragma unroll
                    for (int rh = 0; rh < 2; rh++) {
                        sum[i][rh] += __shfl_xor_sync(0xffffffffu, sum[i][rh], o);
                        sq[i][rh]  += __shfl_xor_sync(0xffffffffu, sq[i][rh], o);
                    }
                }
                if ((lane & 3) == 0) {
#pragma unroll
                    for (int i = 0; i < 2; i++)
#pragma unroll
                    for (int rh = 0; rh < 2; rh++) {
                        int row = wm + i*16 + rh*8 + g;
                        sred[row*8 + (warp >> 1)*2 + 0] = sum[i][rh];
                        sred[row*8 + (warp >> 1)*2 + 1] = sq[i][rh];
                    }
                }
                __syncthreads();
#pragma unroll
                for (int i = 0; i < 2; i++)
#pragma unroll
                for (int rh = 0; rh < 2; rh++) {
                    int row = wm + i*16 + rh*8 + g;
                    float s = sred[row*8+0] + sred[row*8+2] + sred[row*8+4] + sred[row*8+6];
                    float qq = sred[row*8+1] + sred[row*8+3] + sred[row*8+5] + sred[row*8+7];
                    float mean = s*(1.0f/128.0f);
                    float var = fmaxf(qq*(1.0f/128.0f) - mean*mean, 0.f);
                    float rstd = rsqrtf(var + 1e-5f);
#pragma unroll
                    for (int j = 0; j < 4; j++) {
                        int n = wn + j*8 + tg;
                        float v0 = (acc[i][j][rh*2+0]-mean)*rstd;
                        float v1 = (acc[i][j][rh*2+1]-mean)*rstd;
                        *reinterpret_cast<uint32_t*>(&oh[(m0+row)*D_ + n]) = packh2(v0, v1);
                    }
                }
            }
            if (t < 3) asm volatile("cp.async.wait_group 0;\n");
            __syncthreads();
        }
        return;
    }

    // ---- single-tile path (small jobs) ----
    int job, tile;
    if (jobsel < 100)       { job = jobsel; tile = blockIdx.x; }
    else if (jobsel == 102) { job = 8 + (blockIdx.x >> 7); tile = blockIdx.x & 127; }
    else                    { job = 13 + (blockIdx.x >> 7); tile = blockIdx.x & 127; }

    const __half* A; const __half* Bw; const float* bias;
    __half* oh; float* of; const float* aux; const __half* auxh;
    int epi; float scale; int ldC;
    gemm_job(job, extb, A, Bw, bias, oh, of, aux, auxh, epi, scale, ldC);
    if (epi == EPI_SKLN0) aux = extaux;

    __half* As = shh;                 // [64][136]
    __half* Bs = shh + 64*136;        // [128][136]
    int m0 = tile * 64;
    const int KD = KT*128;
    float acc[2][4][4];
#pragma unroll
    for (int i = 0; i < 2; i++)
#pragma unroll
        for (int j = 0; j < 4; j++)
#pragma unroll
            for (int r = 0; r < 4; r++) acc[i][j][r] = 0.f;

    for (int kc = 0; kc < KT; kc++) {
        int r = tid >> 4, q = tid & 15;
        if (job == 7) {
            for (int rr = r; rr < 64; rr += 16) {
                int row = m0 + rr;
                int b = row >> 12, p = row & 4095;
                int hh_ = p >> 6, ww = p & 63;
                int l = ((hh_ >> 3) << 3) + (ww >> 3);
                const __half* src = g_otok + ((b*64 + l)*NQ1 + (hh_&7)*8 + (ww&7))*D_ + q*8;
                float s[8];
#pragma unroll
                for (int t = 0; t < 8; t++) s[t] = 0.f;
#pragma unroll
                for (int n = 0; n < 6; n++) {
                    const __half2* pp = reinterpret_cast<const __half2*>(src + n*64*D_);
#pragma unroll
                    for (int t = 0; t < 4; t++) {
                        float2 f = __half22float2(pp[t]);
                        s[t*2] += f.x; s[t*2+1] += f.y;
                    }
                }
                __half2 o[4];
#pragma unroll
                for (int t = 0; t < 4; t++)
                    o[t] = __floats2half2_rn(s[t*2]*(1.f/6.f), s[t*2+1]*(1.f/6.f));
                *reinterpret_cast<int4*>(&As[rr*136 + q*8]) = *reinterpret_cast<int4*>(o);
            }
#pragma unroll
            for (int rr = r; rr < 128; rr += 16)
                cpa16(&Bs[rr*136 + q*8], &Bw[rr*KD + q*8]);
        } else {
#pragma unroll
            for (int rr = r; rr < 64; rr += 16)
                cpa16(&As[rr*136 + q*8], &A[(m0+rr)*KD + kc*128 + q*8]);
#pragma unroll
            for (int rr = r; rr < 128; rr += 16)
                cpa16(&Bs[rr*136 + q*8], &Bw[rr*KD + kc*128 + q*8]);
        }
        asm volatile("cp.async.commit_group;\n");
        asm volatile("cp.async.wait_group 0;\n");
        __syncthreads();
#pragma unroll
        for (int ks = 0; ks < 8; ks++) {
            int k0 = ks*16;
            uint32_t a[2][4];
#pragma unroll
            for (int i = 0; i < 2; i++) {
                int mb = wm + i*16;
                a[i][0] = *reinterpret_cast<const uint32_t*>(&As[(mb+g  )*136 + k0+tg  ]);
                a[i][1] = *reinterpret_cast<const uint32_t*>(&As[(mb+8+g)*136 + k0+tg  ]);
                a[i][2] = *reinterpret_cast<const uint32_t*>(&As[(mb+g  )*136 + k0+8+tg]);
                a[i][3] = *reinterpret_cast<const uint32_t*>(&As[(mb+8+g)*136 + k0+8+tg]);
            }
#pragma unroll
            for (int j = 0; j < 4; j++) {
                uint32_t b0 = *reinterpret_cast<const uint32_t*>(&Bs[(wn+j*8+g)*136 + k0+tg  ]);
                uint32_t b1 = *reinterpret_cast<const uint32_t*>(&Bs[(wn+j*8+g)*136 + k0+8+tg]);
                mma16816(acc[0][j], a[0], b0, b1);
                mma16816(acc[1][j], a[1], b0, b1);
            }
        }
        __syncthreads();
    }

    if (epi <= EPI_GELU) {
#pragma unroll
        for (int i = 0; i < 2; i++)
#pragma unroll
        for (int j = 0; j < 4; j++) {
            int n = wn + j*8 + tg;
            float b0 = bias[n], b1 = bias[n+1];
            int r0 = m0 + wm + i*16 + g, r1 = r0 + 8;
            float v0 = acc[i][j][0]+b0, v1 = acc[i][j][1]+b1;
            float v2 = acc[i][j][2]+b0, v3 = acc[i][j][3]+b1;
            if (epi == EPI_GELU) {
                v0 = geluf(v0); v1 = geluf(v1); v2 = geluf(v2); v3 = geluf(v3);
            } else {
                v0 *= scale; v1 *= scale; v2 *= scale; v3 *= scale;
            }
            *reinterpret_cast<uint32_t*>(&oh[r0*ldC + n]) = packh2(v0, v1);
            *reinterpret_cast<uint32_t*>(&oh[r1*ldC + n]) = packh2(v2, v3);
        }
    } else {
#pragma unroll
        for (int i = 0; i < 2; i++)
#pragma unroll
        for (int j = 0; j < 4; j++) {
            int n = wn + j*8 + tg;
            int r0 = m0 + wm + i*16 + g, r1 = r0 + 8;
            if (bias) {
                float b0 = bias[n], b1 = bias[n+1];
                acc[i][j][0] += b0; acc[i][j][1] += b1;
                acc[i][j][2] += b0; acc[i][j][3] += b1;
            }
            if (auxh) {
                acc[i][j][0] += __half2float(auxh[r0*D_ + n]);
                acc[i][j][1] += __half2float(auxh[r0*D_ + n+1]);
                acc[i][j][2] += __half2float(auxh[r1*D_ + n]);
                acc[i][j][3] += __half2float(auxh[r1*D_ + n+1]);
            }
            if (aux) {
                if (epi == EPI_SKLN0) {
                    int ba = r0 >> 12, pa = r0 & 4095;
                    int bb_ = r1 >> 12, pb = r1 & 4095;
                    acc[i][j][0] += aux[(ba*D_ + n  )*4096 + pa];
                    acc[i][j][1] += aux[(ba*D_ + n+1)*4096 + pa];
                    acc[i][j][2] += aux[(bb_*D_ + n  )*4096 + pb];
                    acc[i][j][3] += aux[(bb_*D_ + n+1)*4096 + pb];
                } else {
                    acc[i][j][0] += aux[r0*D_ + n];
                    acc[i][j][1] += aux[r0*D_ + n+1];
                    acc[i][j][2] += aux[r1*D_ + n];
                    acc[i][j][3] += aux[r1*D_ + n+1];
                }
            }
            if (of) {
                of[r0*D_ + n]   = acc[i][j][0];
                of[r0*D_ + n+1] = acc[i][j][1];
                of[r1*D_ + n]   = acc[i][j][2];
                of[r1*D_ + n+1] = acc[i][j][3];
            }
        }
        float sum[2][2] = {{0,0},{0,0}}, sq[2][2] = {{0,0},{0,0}};
#pragma unroll
        for (int i = 0; i < 2; i++)
#pragma unroll
        for (int j = 0; j < 4; j++) {
            float a0 = acc[i][j][0], a1 = acc[i][j][1];
            float a2 = acc[i][j][2], a3 = acc[i][j][3];
            sum[i][0] += a0 + a1; sq[i][0] += a0*a0 + a1*a1;
            sum[i][1] += a2 + a3; sq[i][1] += a2*a2 + a3*a3;
        }
#pragma unroll
        for (int o = 1; o <= 2; o <<= 1) {
#pragma unroll
            for (int i = 0; i < 2; i++)
#pragma unroll
            for (int rh = 0; rh < 2; rh++) {
                sum[i][rh] += __shfl_xor_sync(0xffffffffu, sum[i][rh], o);
                sq[i][rh]  += __shfl_xor_sync(0xffffffffu, sq[i][rh], o);
            }
        }
        float* sred = reinterpret_cast<float*>(shh);   // [64][8]
        if ((lane & 3) == 0) {
#pragma unroll
            for (int i = 0; i < 2; i++)
#pragma unroll
            for (int rh = 0; rh < 2; rh++) {
                int row = wm + i*16 + rh*8 + g;
                sred[row*8 + (warp >> 1)*2 + 0] = sum[i][rh];
                sred[row*8 + (warp >> 1)*2 + 1] = sq[i][rh];
            }
        }
        __syncthreads();
#pragma unroll
        for (int i = 0; i < 2; i++)
#pragma unroll
        for (int rh = 0; rh < 2; rh++) {
            int row = wm + i*16 + rh*8 + g;
            float s = sred[row*8+0] + sred[row*8+2] + sred[row*8+4] + sred[row*8+6];
            float qq = sred[row*8+1] + sred[row*8+3] + sred[row*8+5] + sred[row*8+7];
            float mean = s*(1.0f/128.0f);
            float var = fmaxf(qq*(1.0f/128.0f) - mean*mean, 0.f);
            float rstd = rsqrtf(var + 1e-5f);
            if (epi == EPI_FIN) {
                int grow = m0 + row;
                int b = grow >> 12, p = grow & 4095;
#pragma unroll
                for (int j = 0; j < 4; j++) {
                    int n = wn + j*8 + tg;
                    extout[(b*D_ + n  )*4096 + p] =
                        (acc[i][j][rh*2+0]-mean)*rstd*extg[n]   + extbt[n];
                    extout[(b*D_ + n+1)*4096 + p] =
                        (acc[i][j][rh*2+1]-mean)*rstd*extg[n+1] + extbt[n+1];
                }
            } else {
#pragma unroll
                for (int j = 0; j < 4; j++) {
                    int n = wn + j*8 + tg;
                    float v0 = (acc[i][j][rh*2+0]-mean)*rstd;
                    float v1 = (acc[i][j][rh*2+1]-mean)*rstd;
                    *reinterpret_cast<uint32_t*>(&oh[(m0+row)*D_ + n]) = packh2(v0, v1);
                }
            }
        }
    }
}

// ---------------- tensor-core flash attention (fp16 in / fp16 out) -----------
template<int MT, int NW>
__global__ void __launch_bounds__(NW*32) k_attn_mma(int stage) {
    const int NQ = MT*16*NW;
    extern __shared__ __half sha[];
    __half* Qs = sha;                  // [NQ][40]
    __half* Ks = Qs + NQ*40;           // [264][40]
    __half* Vt = Ks + 264*40;          // [32][274]
    int bl = blockIdx.x, hh = blockIdx.y, tid = threadIdx.x;
    int b = bl >> 6, l = bl & 63;
    const __half* qsrc; const __half* ksrc; const __half* vsrc;
    if (stage == 0) { qsrc = g_qh1; ksrc = g_kh1; vsrc = g_vh1; }
    else            { qsrc = g_qh2; ksrc = g_kh2; vsrc = g_vh2; }
    for (int idx = tid; idx < NQ*16; idx += NW*32) {
        int row = idx >> 4, c2 = idx & 15;
        int pix;
        if (stage == 0) {
            int n = row >> 6, ij = row & 63;
            pix = (b*N_+n)*4096 + ((l>>3)*8 + (ij>>3))*64 + (l&7)*8 + (ij&7);
        } else {
            pix = b*4096 + ((l>>3)*8 + (row>>3))*64 + (l&7)*8 + (row&7);
        }
        *reinterpret_cast<uint32_t*>(&Qs[row*40 + 2*c2]) =
            *reinterpret_cast<const uint32_t*>(&qsrc[pix*D_ + hh*32 + 2*c2]);
    }
    for (int idx = tid; idx < NKV*16; idx += NW*32) {
        int kv = idx >> 4, c2 = idx & 15;
        int n = kv/44, f = kv%44, f1 = f/11, f2 = f%11;
        int h, w;
        if (stage == 0) { h = (l>>3)*4 + f1; w = (l&7)*11 + f2; }
        else            { h = f1*8 + (l>>3); w = f2*8 + (l&7); }
        int pix = (b*N_+n)*PIX + h*FW_ + w;
        *reinterpret_cast<uint32_t*>(&Ks[kv*40 + 2*c2]) =
            *reinterpret_cast<const uint32_t*>(&ksrc[pix*D_ + hh*32 + 2*c2]);
    }
    for (int idx = tid; idx < NKV*32; idx += NW*32) {
        int kv = idx >> 5, ch = idx & 31;
        int n = kv/44, f = kv%44, f1 = f/11, f2 = f%11;
        int h, w;
        if (stage == 0) { h = (l>>3)*4 + f1; w = (l&7)*11 + f2; }
        else            { h = f1*8 + (l>>3); w = f2*8 + (l&7); }
        int pix = (b*N_+n)*PIX + h*FW_ + w;
        Vt[ch*274 + kv] = vsrc[pix*D_ + hh*32 + ch];
    }
    for (int idx = tid; idx < 32*10; idx += NW*32) {
        int ch = idx / 10, c = idx % 10;
        Vt[ch*274 + 264 + c] = __half(0.f);
    }
    __syncthreads();

    int warp = tid >> 5, lane = tid & 31;
    int g = lane >> 2, t4 = lane & 3;
    int row0 = warp * MT * 16;

    uint32_t af[MT][2][4];
#pragma unroll
    for (int mt = 0; mt < MT; mt++)
#pragma unroll
        for (int ks = 0; ks < 2; ks++) {
            int r = row0 + mt*16, k0 = ks*16;
            af[mt][ks][0] = *reinterpret_cast<const uint32_t*>(&Qs[(r+g  )*40 + k0 + 2*t4    ]);
            af[mt][ks][1] = *reinterpret_cast<const uint32_t*>(&Qs[(r+8+g)*40 + k0 + 2*t4    ]);
            af[mt][ks][2] = *reinterpret_cast<const uint32_t*>(&Qs[(r+g  )*40 + k0 + 8 + 2*t4]);
            af[mt][ks][3] = *reinterpret_cast<const uint32_t*>(&Qs[(r+8+g)*40 + k0 + 8 + 2*t4]);
        }

    float m[MT][2], lsum[MT][2], O[MT][4][4];
#pragma unroll
    for (int mt = 0; mt < MT; mt++) {
        m[mt][0] = -1e30f; m[mt][1] = -1e30f;
        lsum[mt][0] = 0.f; lsum[mt][1] = 0.f;
#pragma unroll
        for (int j = 0; j < 4; j++)
#pragma unroll
            for (int r = 0; r < 4; r++) O[mt][j][r] = 0.f;
    }

    for (int c = 0; c < 17; c++) {
        int kv0 = c*16;
        int nt = (c == 16) ? 1 : 2;
        uint32_t bf[2][2][2];
#pragma unroll
        for (int n = 0; n < 2; n++) {
            if (n < nt) {
#pragma unroll
                for (int ks = 0; ks < 2; ks++) {
                    bf[n][ks][0] = *reinterpret_cast<const uint32_t*>(&Ks[(kv0+n*8+g)*40 + ks*16 + 2*t4    ]);
                    bf[n][ks][1] = *reinterpret_cast<const uint32_t*>(&Ks[(kv0+n*8+g)*40 + ks*16 + 8 + 2*t4]);
                }
            }
        }
        float S[MT][2][4];
#pragma unroll
        for (int mt = 0; mt < MT; mt++)
#pragma unroll
            for (int n = 0; n < 2; n++)
#pragma unroll
                for (int r = 0; r < 4; r++) S[mt][n][r] = 0.f;
#pragma unroll
        for (int mt = 0; mt < MT; mt++)
#pragma unroll
            for (int n = 0; n < 2; n++) {
                if (n < nt) {
                    mma16816(S[mt][n], af[mt][0], bf[n][0][0], bf[n][0][1]);
                    mma16816(S[mt][n], af[mt][1], bf[n][1][0], bf[n][1][1]);
                }
            }
#pragma unroll
        for (int mt = 0; mt < MT; mt++) {
            float mx0 = fmaxf(S[mt][0][0], S[mt][0][1]);
            float mx8 = fmaxf(S[mt][0][2], S[mt][0][3]);
            if (nt == 2) {
                mx0 = fmaxf(mx0, fmaxf(S[mt][1][0], S[mt][1][1]));
                mx8 = fmaxf(mx8, fmaxf(S[mt][1][2], S[mt][1][3]));
            }
            mx0 = fmaxf(mx0, __shfl_xor_sync(0xffffffffu, mx0, 1));
            mx0 = fmaxf(mx0, __shfl_xor_sync(0xffffffffu, mx0, 2));
            mx8 = fmaxf(mx8, __shfl_xor_sync(0xffffffffu, mx8, 1));
            mx8 = fmaxf(mx8, __shfl_xor_sync(0xffffffffu, mx8, 2));
            float mn0 = fmaxf(m[mt][0], mx0), mn8 = fmaxf(m[mt][1], mx8);
            float cr0 = __expf(m[mt][0] - mn0), cr8 = __expf(m[mt][1] - mn8);
            m[mt][0] = mn0; m[mt][1] = mn8;
            uint32_t pa[4];
            float p00 = __expf(S[mt][0][0] - mn0), p01 = __expf(S[mt][0][1] - mn0);
            float p02 = __expf(S[mt][0][2] - mn8), p03 = __expf(S[mt][0][3] - mn8);
            float rs0 = p00 + p01, rs8 = p02 + p03;
            pa[0] = packh2(p00, p01);
            pa[1] = packh2(p02, p03);
            if (nt == 2) {
                float p10 = __expf(S[mt][1][0] - mn0), p11 = __expf(S[mt][1][1] - mn0);
                float p12 = __expf(S[mt][1][2] - mn8), p13 = __expf(S[mt][1][3] - mn8);
                rs0 += p10 + p11; rs8 += p12 + p13;
                pa[2] = packh2(p10, p11);
                pa[3] = packh2(p12, p13);
            } else { pa[2] = 0u; pa[3] = 0u; }
            rs0 += __shfl_xor_sync(0xffffffffu, rs0, 1);
            rs0 += __shfl_xor_sync(0xffffffffu, rs0, 2);
            rs8 += __shfl_xor_sync(0xffffffffu, rs8, 1);
            rs8 += __shfl_xor_sync(0xffffffffu, rs8, 2);
            lsum[mt][0] = lsum[mt][0]*cr0 + rs0;
            lsum[mt][1] = lsum[mt][1]*cr8 + rs8;
#pragma unroll
            for (int j = 0; j < 4; j++) {
                O[mt][j][0] *= cr0; O[mt][j][1] *= cr0;
                O[mt][j][2] *= cr8; O[mt][j][3] *= cr8;
                uint32_t vb0 = *reinterpret_cast<const uint32_t*>(&Vt[(j*8+g)*274 + kv0 + 2*t4    ]);
                uint32_t vb1 = *reinterpret_cast<const uint32_t*>(&Vt[(j*8+g)*274 + kv0 + 8 + 2*t4]);
                mma16816(O[mt][j], pa, vb0, vb1);
            }
        }
    }
#pragma unroll
    for (int mt = 0; mt < MT; mt++) {
        float i0 = 1.0f / lsum[mt][0], i8 = 1.0f / lsum[mt][1];
        int r0 = row0 + mt*16 + g;
        int r1 = r0 + 8;
        int out0, out1;
        if (stage == 0) {
            out0 = bl*NQ + r0;
            out1 = bl*NQ + r1;
        } else {
            out0 = b*4096 + ((l>>3)*8 + (r0>>3))*64 + (l&7)*8 + (r0&7);
            out1 = b*4096 + ((l>>3)*8 + (r1>>3))*64 + (l&7)*8 + (r1&7);
        }
        __half* Od = (stage == 0) ? g_otok : g_o2;
#pragma unroll
        for (int j = 0; j < 4; j++) {
            int chn = hh*32 + j*8 + 2*t4;
            *reinterpret_cast<uint32_t*>(&Od[out0*D_ + chn]) = packh2(O[mt][j][0]*i0, O[mt][j][1]*i0);
            *reinterpret_cast<uint32_t*>(&Od[out1*D_ + chn]) = packh2(O[mt][j][2]*i8, O[mt][j][3]*i8);
        }
    }
}

// ---------------------------------------------------------------------------
extern "C" void kernel_launch(void* const* d_in, const int* in_sizes, int n_in,
                              void* d_out, int out_size) {
    (void)in_sizes; (void)n_in; (void)out_size;
    const float* x        = (const float*)d_in[1];
    const float* grid     = (const float*)d_in[2];
    const float* feature  = (const float*)d_in[3];
    const float* I_inv    = (const float*)d_in[4];
    const float* E_inv    = (const float*)d_in[5];
    const float* bn_fl_g  = (const float*)d_in[6];
    const float* bn_fl_b  = (const float*)d_in[7];
    const float* W_fl     = (const float*)d_in[8];
    const float* bn_fp_g  = (const float*)d_in[9];
    const float* bn_fp_b  = (const float*)d_in[10];
    const float* W_fp     = (const float*)d_in[11];
    const float* W_bev    = (const float*)d_in[12];
    const float* b_bev    = (const float*)d_in[13];
    const float* W_img    = (const float*)d_in[14];
    const float* W_cam    = (const float*)d_in[15];
    const float* aln_g    = (const float*)d_in[16];
    const float* aln_b    = (const float*)d_in[17];
    const float* aWqkv    = (const float*)d_in[18];
    const float* abqkv    = (const float*)d_in[19];
    const float* aWp      = (const float*)d_in[20];
    const float* abp      = (const float*)d_in[21];
    const float* pn_g     = (const float*)d_in[22];
    const float* pn_b     = (const float*)d_in[23];
    const float* Wma      = (const float*)d_in[24];
    const float* bma      = (const float*)d_in[25];
    const float* Wmb      = (const float*)d_in[26];
    const float* bmb      = (const float*)d_in[27];
    const float* post_g   = (const float*)d_in[28];
    const float* post_b   = (const float*)d_in[29];
    float* out = (float*)d_out;

    const int GSM = (8704*2 + 17408)*2 + 2048;   // 71680
    const int PSM = 2*128*33*4 + 32*128*4;       // 50176
    const int A1SM = (384*40 + 264*40 + 32*274) * 2;   // 69376
    const int A2SM = (64*40 + 264*40 + 32*274) * 2;    // 43776
    cudaFuncSetAttribute(k_prep, cudaFuncAttributeMaxDynamicSharedMemorySize, PSM);
    cudaFuncSetAttribute(k_gemm_ep<1>, cudaFuncAttributeMaxDynamicSharedMemorySize, GSM);
    cudaFuncSetAttribute(k_gemm_ep<2>, cudaFuncAttributeMaxDynamicSharedMemorySize, GSM);
    cudaFuncSetAttribute(k_attn_mma<3,8>, cudaFuncAttributeMaxDynamicSharedMemorySize, A1SM);
    cudaFuncSetAttribute(k_attn_mma<1,4>, cudaFuncAttributeMaxDynamicSharedMemorySize, A2SM);

    // prep (weights + activations)
    k_wprep<<<304, 256>>>(aln_g, aln_b, aWqkv, abqkv, pn_g, pn_b, Wma, bma,
                          aWp, Wmb, W_fp, W_fl);
    k_prep<<<B_*N_*88, 128, PSM>>>(feature, I_inv, E_inv, W_img, W_cam,
                                   bn_fp_g, bn_fp_b, bn_fl_g, bn_fl_b);
    k_query<<<NQP/8, 256>>>(grid, x, W_bev, b_bev, E_inv, W_cam);

    // conv GEMMs (jobs 0,1; 4 tiles/block) then QKV (jobs 2..6; 4 tiles/block)
    k_gemm_ep<1><<<264, 256, GSM>>>(100, nullptr, nullptr, nullptr, nullptr, nullptr);
    k_gemm_ep<1><<<720, 256, GSM>>>(101, nullptr, nullptr, nullptr, nullptr, nullptr);

    // stage 1
    k_attn_mma<3,8><<<dim3(B_*64, 4), 256, A1SM>>>(0);
    k_gemm_ep<1><<<128, 256, GSM>>>(7, abp, nullptr, nullptr, x, nullptr);      // mean+proj+skip+LN
    k_gemm_ep<1><<<256, 256, GSM>>>(102, nullptr, nullptr, nullptr, nullptr, nullptr);  // gelu a,b
    k_gemm_ep<2><<<128, 256, GSM>>>(10, bmb, nullptr, nullptr, nullptr, nullptr);       // res+LN -> xq1

    // stage 2
    k_gemm_ep<1><<<128, 256, GSM>>>(11, nullptr, nullptr, nullptr, nullptr, nullptr);   // Q2
    k_attn_mma<1,4><<<dim3(B_*64, 4), 128, A2SM>>>(1);
    k_gemm_ep<1><<<128, 256, GSM>>>(12, abp + 128, nullptr, nullptr, nullptr, nullptr); // proj+skip+LN
    k_gemm_ep<1><<<256, 256, GSM>>>(103, nullptr, nullptr, nullptr, nullptr, nullptr);  // gelu a,b
    k_gemm_ep<2><<<128, 256, GSM>>>(15, bmb + 128, post_g, post_b, nullptr, out);       // res+finalLN
}

// round 17
// speedup vs baseline: 1.1147x; 1.0680x over previous
#include <cuda_runtime.h>
#include <cuda_fp16.h>
#include <math.h>
#include <stdint.h>

#define B_   2
#define N_   6
#define FH_  32
#define FW_  88
#define PIX  (FH_*FW_)     // 2816
#define D_   128
#define NKV  264
#define NQ1  384
#define NPX  (B_*N_*PIX)   // 33792
#define NQP  (B_*N_*4096)  // 49152
#define NTK  (B_*4096)     // 8192

#define EPI_HALF  0
#define EPI_LN    2

// ---------------- scratch globals (no runtime allocation) -------------------
__device__ __align__(16) __half g_fph[NPX*D_];
__device__ __align__(16) __half g_flh[NPX*D_];
__device__ __align__(16) __half g_kimgh[NPX*D_];
__device__ __align__(16) __half g_xq [NQP*D_];
__device__ __align__(16) __half g_xk [NPX*D_];
__device__ __align__(16) __half g_xv [NPX*D_];
__device__ __align__(16) __half g_wfold[6*D_*D_];
__device__ float  g_bfold[6*D_];
__device__ __align__(16) __half g_wafold[2*256*D_];
__device__ float  g_bafold[2*256];
__device__ __align__(16) __half g_wmbT[2*D_*256];
__device__ __align__(16) __half g_wpT[2*D_*D_];
__device__ __align__(16) __half g_wfpH[D_*D_];
__device__ __align__(16) __half g_wflH[D_*D_];
__device__ __align__(16) __half g_qh1[NQP*D_];
__device__ __align__(16) __half g_kh1[NPX*D_];
__device__ __align__(16) __half g_vh1[NPX*D_];
__device__ __align__(16) __half g_qh2[NTK*D_];
__device__ __align__(16) __half g_kh2[NPX*D_];
__device__ __align__(16) __half g_vh2[NPX*D_];
__device__ __align__(16) __half g_otok[B_*64*NQ1*D_];
__device__ __align__(16) __half g_o2[NTK*D_];
__device__ __align__(16) float  g_q1[NTK*D_];

__device__ __forceinline__ void warpRed2(float& s, float& q) {
#pragma unroll
    for (int o = 16; o; o >>= 1) {
        s += __shfl_xor_sync(0xffffffffu, s, o);
        q += __shfl_xor_sync(0xffffffffu, q, o);
    }
}

__device__ __forceinline__ void st_half4(__half* dst, float a, float b, float c, float d) {
    __half2* p = reinterpret_cast<__half2*>(dst);
    p[0] = __floats2half2_rn(a, b);
    p[1] = __floats2half2_rn(c, d);
}

__device__ __forceinline__ uint32_t packh2(float a, float b) {
    __half2 h = __floats2half2_rn(a, b);
    return *reinterpret_cast<uint32_t*>(&h);
}

__device__ __forceinline__ float geluf(float h) {
    return h * 0.5f * (1.0f + erff(h * 0.70710678118654752f));
}

__device__ __forceinline__ void mma16816(float* c, const uint32_t* a,
                                         uint32_t b0, uint32_t b1) {
    asm volatile(
        "mma.sync.aligned.m16n8k16.row.col.f32.f16.f16.f32 "
        "{%0,%1,%2,%3}, {%4,%5,%6,%7}, {%8,%9}, {%0,%1,%2,%3};\n"
        : "+f"(c[0]), "+f"(c[1]), "+f"(c[2]), "+f"(c[3])
        : "r"(a[0]), "r"(a[1]), "r"(a[2]), "r"(a[3]), "r"(b0), "r"(b1));
}

__device__ __forceinline__ void cpa16(void* smem, const void* gmem) {
    uint32_t sa = (uint32_t)__cvta_generic_to_shared(smem);
    asm volatile("cp.async.cg.shared.global [%0], [%1], 16;\n" :: "r"(sa), "l"(gmem));
}

// ---------------- merged weight prep ----------------------------------------
__global__ void __launch_bounds__(256) k_wprep(
        const float* __restrict__ aln_g, const float* __restrict__ aln_b,
        const float* __restrict__ aWqkv, const float* __restrict__ abqkv,
        const float* __restrict__ pn_g, const float* __restrict__ pn_b,
        const float* __restrict__ Wma, const float* __restrict__ bma,
        const float* __restrict__ aWp, const float* __restrict__ Wmb,
        const float* __restrict__ W_fp, const float* __restrict__ W_fl) {
    __shared__ float sm[16][129];
    __shared__ float bred[16][17];
    int blk = blockIdx.x, tid = threadIdx.x;
    if (blk < 48) {
        int idx = blk >> 3, o0 = (blk & 7) * 16;
        const float* W = aWqkv + idx*16384;
        const float* g = aln_g + idx*128;
        const float* bb = aln_b + idx*128;
        for (int k = tid; k < 2048; k += 256) {
            int c = k >> 4, o = k & 15;
            sm[o][c] = g[c] * W[c*128 + o0 + o];
        }
        {
            int o = tid & 15, cg = tid >> 4;
            float part = 0.f;
#pragma unroll
            for (int cc = 0; cc < 8; cc++) {
                int c = cg*8 + cc;
                part += bb[c] * W[c*128 + o0 + o];
            }
            bred[o][cg] = part;
        }
        __syncthreads();
        for (int k = tid; k < 1024; k += 256) {
            int o = k >> 6, c2 = (k & 63)*2;
            *reinterpret_cast<__half2*>(&g_wfold[idx*16384 + (o0+o)*128 + c2]) =
                __floats2half2_rn(sm[o][c2], sm[o][c2+1]);
        }
        if (tid < 16) {
            float a = 0.f;
#pragma unroll
            for (int cg = 0; cg < 16; cg++) a += bred[tid][cg];
            g_bfold[idx*128 + o0 + tid] = a + abqkv[idx*128 + o0 + tid];
        }
    } else if (blk < 80) {
        int t = blk - 48;
        int s = t >> 4, o0 = (t & 15) * 16;
        const float* W = Wma + s*128*256;
        const float* g = pn_g + s*128;
        const float* bb = pn_b + s*128;
        for (int k = tid; k < 2048; k += 256) {
            int c = k >> 4, o = k & 15;
            sm[o][c] = g[c] * W[c*256 + o0 + o];
        }
        {
            int o = tid & 15, cg = tid >> 4;
            float part = 0.f;
#pragma unroll
            for (int cc = 0; cc < 8; cc++) {
                int c = cg*8 + cc;
                part += bb[c] * W[c*256 + o0 + o];
            }
            bred[o][cg] = part;
        }
        __syncthreads();
        for (int k = tid; k < 1024; k += 256) {
            int o = k >> 6, c2 = (k & 63)*2;
            *reinterpret_cast<__half2*>(&g_wafold[s*32768 + (o0+o)*128 + c2]) =
                __floats2half2_rn(sm[o][c2], sm[o][c2+1]);
        }
        if (tid < 16) {
            float a = 0.f;
#pragma unroll
            for (int cg = 0; cg < 16; cg++) a += bred[tid][cg];
            g_bafold[s*256 + o0 + tid] = a + bma[s*256 + o0 + tid];
        }
    } else if (blk < 176) {
        int t = blk - 80;
        const float* src; __half* dst; int R, C, bx, by;
        if (t < 16)      { src = aWp;          dst = g_wpT;          R=128; C=128; bx=t&3;      by=t>>2; }
        else if (t < 32) { src = aWp+16384;    dst = g_wpT+16384;    R=128; C=128; bx=(t-16)&3; by=(t-16)>>2; }
        else if (t < 64) { src = Wmb;          dst = g_wmbT;         R=256; C=128; bx=(t-32)&3; by=(t-32)>>2; }
        else             { src = Wmb+32768;    dst = g_wmbT+32768;   R=256; C=128; bx=(t-64)&3; by=(t-64)>>2; }
        float (*tb)[33] = reinterpret_cast<float(*)[33]>(&sm[0][0]);
        int c0 = bx*32, r0 = by*32;
        int cx = tid & 31, ry = tid >> 5;
        for (int rr = ry; rr < 32; rr += 8)
            tb[rr][cx] = src[(r0+rr)*C + c0 + cx];
        __syncthreads();
        for (int cc = ry; cc < 32; cc += 8)
            dst[(c0+cc)*R + r0 + cx] = __float2half(tb[cx][cc]);
    } else {
        int t = blk - 176;
        const float* src = (t < 64) ? W_fp : W_fl;
        __half* dst = (t < 64) ? g_wfpH : g_wflH;
        int i = (t & 63)*256 + tid;
        dst[i] = __float2half(src[i]);
    }
}

// ---------------- prep: BN-ReLU fp16 feats + image embedding -----------------
__global__ void __launch_bounds__(128) k_prep(
        const float* __restrict__ feat,
        const float* __restrict__ I_inv, const float* __restrict__ E_inv,
        const float* __restrict__ W_img, const float* __restrict__ W_cam,
        const float* __restrict__ fp_g, const float* __restrict__ fp_b,
        const float* __restrict__ fl_g, const float* __restrict__ fl_b) {
    extern __shared__ float sh[];
    float* sfp  = sh;                 // [128][33]
    float* sfl  = sh + 128*33;
    float* kimg = sh + 2*128*33;      // [32][128]
    int blk = blockIdx.x, tid = threadIdx.x;
    int bn = blk / 88, p0 = (blk % 88) * 32;
    int warp = tid >> 5, lane = tid & 31;

    const float invs = rsqrtf(1.0f + 1e-5f);
    for (int k = tid; k < 4096; k += 128) {
        int c = k >> 5, pp = k & 31;
        float f = feat[(bn*D_ + c)*PIX + p0 + pp];
        sfp[c*33+pp] = fmaxf(f * invs * fp_g[c] + fp_b[c], 0.f);
        sfl[c*33+pp] = fmaxf(f * invs * fl_g[c] + fl_b[c], 0.f);
    }
    float e3[4];
#pragma unroll
    for (int i = 0; i < 4; i++) e3[i] = E_inv[bn*16 + i*4 + 3];
    for (int it = 0; it < 8; it++) {
        int tt = it*4 + warp;
        int p = p0 + tt, fh = p / FW_, fw = p % FW_;
        float px = (float)fw * (480.0f / 87.0f);
        float py = (float)fh * (224.0f / 31.0f);
        float cam[4];
#pragma unroll
        for (int i = 0; i < 3; i++)
            cam[i] = I_inv[bn*9+i*3+0]*px + I_inv[bn*9+i*3+1]*py + I_inv[bn*9+i*3+2];
        cam[3] = 1.0f;
        float dd[4];
#pragma unroll
        for (int i = 0; i < 4; i++)
            dd[i] = E_inv[bn*16+i*4+0]*cam[0] + E_inv[bn*16+i*4+1]*cam[1]
                  + E_inv[bn*16+i*4+2]*cam[2] + E_inv[bn*16+i*4+3]*cam[3];
        int c0 = lane*4;
        float t[4]; float ssum = 0.f, dum = 0.f;
#pragma unroll
        for (int i = 0; i < 4; i++) {
            int c = c0+i;
            float de = W_img[c*4+0]*dd[0] + W_img[c*4+1]*dd[1]
                     + W_img[c*4+2]*dd[2] + W_img[c*4+3]*dd[3];
            float ce = W_cam[c*4+0]*e3[0] + W_cam[c*4+1]*e3[1]
                     + W_cam[c*4+2]*e3[2] + W_cam[c*4+3]*e3[3];
            t[i] = de - ce;
            ssum += t[i]*t[i];
        }
        warpRed2(ssum, dum);
        float inv = 1.0f / fmaxf(sqrtf(ssum), 1e-12f);
#pragma unroll
        for (int i = 0; i < 4; i++) kimg[tt*128 + c0 + i] = t[i]*inv;
    }
    __syncthreads();
    for (int pp = 0; pp < 32; pp++) {
        int row = bn*PIX + p0 + pp;
        g_fph[row*D_ + tid] = __float2half(sfp[tid*33 + pp]);
        g_flh[row*D_ + tid] = __float2half(sfl[tid*33 + pp]);
        g_kimgh[row*D_ + tid] = __float2half(kimg[pp*128 + tid]);
    }
}

// ---------------- query -> LN'd fp16 xhat ------------------------------------
__global__ void __launch_bounds__(256) k_query(
        const float* __restrict__ grid, const float* __restrict__ x,
        const float* __restrict__ W_bev, const float* __restrict__ b_bev,
        const float* __restrict__ E_inv, const float* __restrict__ W_cam) {
    int tid = threadIdx.x, warp = tid >> 5, lane = tid & 31;
    int u = blockIdx.x*8 + warp;
    int bn = u >> 12, p = u & 4095;
    int b = bn / N_;
    int c0 = lane*4;
    float e3[4];
#pragma unroll
    for (int i = 0; i < 4; i++) e3[i] = E_inv[bn*16 + i*4 + 3];
    float gx = grid[p], gy = grid[4096 + p];
    float t[4]; float ss = 0.f, dum = 0.f;
#pragma unroll
    for (int i = 0; i < 4; i++) {
        int c = c0 + i;
        float we = W_bev[c*2+0]*gx + W_bev[c*2+1]*gy + b_bev[c];
        float ce = W_cam[c*4+0]*e3[0] + W_cam[c*4+1]*e3[1]
                 + W_cam[c*4+2]*e3[2] + W_cam[c*4+3]*e3[3];
        t[i] = we - ce;
        ss += t[i]*t[i];
    }
    warpRed2(ss, dum);
    float inv = 1.0f / fmaxf(sqrtf(ss), 1e-12f);
    float q[4]; float s = 0.f, q2 = 0.f;
#pragma unroll
    for (int i = 0; i < 4; i++) {
        q[i] = t[i]*inv + x[(b*D_ + c0 + i)*4096 + p];
        s += q[i]; q2 += q[i]*q[i];
    }
    warpRed2(s, q2);
    float mean = s*(1.0f/128.0f);
    float var = fmaxf(q2*(1.0f/128.0f) - mean*mean, 0.f);
    float rstd = rsqrtf(var + 1e-5f);
    st_half4(&g_xq[u*D_ + c0],
             (q[0]-mean)*rstd, (q[1]-mean)*rstd, (q[2]-mean)*rstd, (q[3]-mean)*rstd);
}

// ---------------- big GEMMs (conv + QKV), single-tile R12 style --------------
__device__ __forceinline__ void gemm_job(
        int job, const __half*& A, const __half*& B, const float*& bias,
        __half*& oh, const __half*& auxh, int& epi, float& scale) {
    const float QS = 0.17677669529663687f;
    scale = 1.f; auxh = nullptr; bias = nullptr; oh = nullptr;
    switch (job) {
    case 0:  A=g_fph; B=g_wfpH; oh=g_xk; auxh=g_kimgh; epi=EPI_LN; break;
    case 1:  A=g_flh; B=g_wflH; oh=g_xv; epi=EPI_LN; break;
    case 2:  A=g_xq;  B=g_wfold;          bias=g_bfold;     oh=g_qh1; epi=EPI_HALF; scale=QS; break;
    case 3:  A=g_xk;  B=g_wfold+16384;    bias=g_bfold+128; oh=g_kh1; epi=EPI_HALF; break;
    case 4:  A=g_xv;  B=g_wfold+2*16384;  bias=g_bfold+256; oh=g_vh1; epi=EPI_HALF; break;
    case 5:  A=g_xk;  B=g_wfold+4*16384;  bias=g_bfold+512; oh=g_kh2; epi=EPI_HALF; break;
    default: A=g_xv;  B=g_wfold+5*16384;  bias=g_bfold+640; oh=g_vh2; epi=EPI_HALF; break;
    }
}

__global__ void __launch_bounds__(256, 3) k_gemm_ep(int jobsel) {
    int job, tile;
    if (jobsel == 100) { job = blockIdx.x / 528; tile = blockIdx.x % 528; }
    else {
        int bx = blockIdx.x;
        if (bx < 768) { job = 2; tile = bx; }
        else { int r2 = bx - 768; job = 3 + r2/528; tile = r2 % 528; }
    }
    const __half* A; const __half* Bw; const float* bias;
    __half* oh; const __half* auxh; int epi; float scale;
    gemm_job(job, A, Bw, bias, oh, auxh, epi, scale);

    extern __shared__ __half shh[];
    __half* As = shh;                 // [64][136]
    __half* Bs = shh + 64*136;        // [128][136]
    int tid = threadIdx.x;
    int m0 = tile * 64;
    int warp = tid >> 5, lane = tid & 31;
    int wm = (warp & 1) * 32, wn = (warp >> 1) * 32;
    int g = lane >> 2, tg = (lane & 3) * 2;
    float acc[2][4][4];
#pragma unroll
    for (int i = 0; i < 2; i++)
#pragma unroll
        for (int j = 0; j < 4; j++)
#pragma unroll
            for (int r = 0; r < 4; r++) acc[i][j][r] = 0.f;

    {
        int r = tid >> 4, q = tid & 15;
#pragma unroll
        for (int rr = r; rr < 64; rr += 16)
            cpa16(&As[rr*136 + q*8], &A[(m0+rr)*128 + q*8]);
#pragma unroll
        for (int rr = r; rr < 128; rr += 16)
            cpa16(&Bs[rr*136 + q*8], &Bw[rr*128 + q*8]);
        asm volatile("cp.async.commit_group;\n");
        asm volatile("cp.async.wait_group 0;\n");
        __syncthreads();
    }
#pragma unroll
    for (int ks = 0; ks < 8; ks++) {
        int k0 = ks*16;
        uint32_t a[2][4];
#pragma unroll
        for (int i = 0; i < 2; i++) {
            int mb = wm + i*16;
            a[i][0] = *reinterpret_cast<const uint32_t*>(&As[(mb+g  )*136 + k0+tg  ]);
            a[i][1] = *reinterpret_cast<const uint32_t*>(&As[(mb+8+g)*136 + k0+tg  ]);
            a[i][2] = *reinterpret_cast<const uint32_t*>(&As[(mb+g  )*136 + k0+8+tg]);
            a[i][3] = *reinterpret_cast<const uint32_t*>(&As[(mb+8+g)*136 + k0+8+tg]);
        }
#pragma unroll
        for (int j = 0; j < 4; j++) {
            uint32_t b0 = *reinterpret_cast<const uint32_t*>(&Bs[(wn+j*8+g)*136 + k0+tg  ]);
            uint32_t b1 = *reinterpret_cast<const uint32_t*>(&Bs[(wn+j*8+g)*136 + k0+8+tg]);
            mma16816(acc[0][j], a[0], b0, b1);
            mma16816(acc[1][j], a[1], b0, b1);
        }
    }
    __syncthreads();

    if (epi == EPI_HALF) {
#pragma unroll
        for (int i = 0; i < 2; i++)
#pragma unroll
        for (int j = 0; j < 4; j++) {
            int n = wn + j*8 + tg;
            float b0 = bias[n], b1 = bias[n+1];
            int r0 = m0 + wm + i*16 + g, r1 = r0 + 8;
            *reinterpret_cast<uint32_t*>(&oh[r0*128 + n]) =
                packh2((acc[i][j][0]+b0)*scale, (acc[i][j][1]+b1)*scale);
            *reinterpret_cast<uint32_t*>(&oh[r1*128 + n]) =
                packh2((acc[i][j][2]+b0)*scale, (acc[i][j][3]+b1)*scale);
        }
    } else {
        // EPI_LN (conv): add auxh, row-LN, fp16 out
#pragma unroll
        for (int i = 0; i < 2; i++)
#pragma unroll
        for (int j = 0; j < 4; j++) {
            int n = wn + j*8 + tg;
            int r0 = m0 + wm + i*16 + g, r1 = r0 + 8;
            if (auxh) {
                acc[i][j][0] += __half2float(auxh[r0*D_ + n]);
                acc[i][j][1] += __half2float(auxh[r0*D_ + n+1]);
                acc[i][j][2] += __half2float(auxh[r1*D_ + n]);
                acc[i][j][3] += __half2float(auxh[r1*D_ + n+1]);
            }
        }
        float sum[2][2] = {{0,0},{0,0}}, sq[2][2] = {{0,0},{0,0}};
#pragma unroll
        for (int i = 0; i < 2; i++)
#pragma unroll
        for (int j = 0; j < 4; j++) {
            float a0 = acc[i][j][0], a1 = acc[i][j][1];
            float a2 = acc[i][j][2], a3 = acc[i][j][3];
            sum[i][0] += a0 + a1; sq[i][0] += a0*a0 + a1*a1;
            sum[i][1] += a2 + a3; sq[i][1] += a2*a2 + a3*a3;
        }
#pragma unroll
        for (int o = 1; o <= 2; o <<= 1) {
#pragma unroll
            for (int i = 0; i < 2; i++)
#pragma unroll
            for (int rh = 0; rh < 2; rh++) {
                sum[i][rh] += __shfl_xor_sync(0xffffffffu, sum[i][rh], o);
                sq[i][rh]  += __shfl_xor_sync(0xffffffffu, sq[i][rh], o);
            }
        }
        float* sred = reinterpret_cast<float*>(shh);   // [64][8]
        if ((lane & 3) == 0) {
#pragma unroll
            for (int i = 0; i < 2; i++)
#pragma unroll
            for (int rh = 0; rh < 2; rh++) {
                int row = wm + i*16 + rh*8 + g;
                sred[row*8 + (warp >> 1)*2 + 0] = sum[i][rh];
                sred[row*8 + (warp >> 1)*2 + 1] = sq[i][rh];
            }
        }
        __syncthreads();
#pragma unroll
        for (int i = 0; i < 2; i++)
#pragma unroll
        for (int rh = 0; rh < 2; rh++) {
            int row = wm + i*16 + rh*8 + g;
            float s = sred[row*8+0] + sred[row*8+2] + sred[row*8+4] + sred[row*8+6];
            float qq = sred[row*8+1] + sred[row*8+3] + sred[row*8+5] + sred[row*8+7];
            float mean = s*(1.0f/128.0f);
            float var = fmaxf(qq*(1.0f/128.0f) - mean*mean, 0.f);
            float rstd = rsqrtf(var + 1e-5f);
#pragma unroll
            for (int j = 0; j < 4; j++) {
                int n = wn + j*8 + tg;
                float v0 = (acc[i][j][rh*2+0]-mean)*rstd;
                float v1 = (acc[i][j][rh*2+1]-mean)*rstd;
                *reinterpret_cast<uint32_t*>(&oh[(m0+row)*D_ + n]) = packh2(v0, v1);
            }
        }
    }
}

// ---------------- fused per-tile sub-GEMM helper ------------------------------
__device__ __forceinline__ void tile_gemm(
        const __half* Xs, int xst, const __half* __restrict__ Bg, int KD, int nch,
        __half* Bs, float acc[2][4][4],
        int tid, int wm, int wn, int g, int tg) {
#pragma unroll
    for (int i = 0; i < 2; i++)
#pragma unroll
        for (int j = 0; j < 4; j++)
#pragma unroll
            for (int rr = 0; rr < 4; rr++) acc[i][j][rr] = 0.f;
    int r = tid >> 4, q = tid & 15;
    for (int kc = 0; kc < nch; kc++) {
#pragma unroll
        for (int rr = r; rr < 128; rr += 16)
            cpa16(&Bs[rr*136 + q*8], &Bg[rr*KD + kc*128 + q*8]);
        asm volatile("cp.async.commit_group;\n");
        asm volatile("cp.async.wait_group 0;\n");
        __syncthreads();
#pragma unroll
        for (int ks = 0; ks < 8; ks++) {
            int kx = kc*128 + ks*16;
            int kb = ks*16;
            uint32_t a[2][4];
#pragma unroll
            for (int i = 0; i < 2; i++) {
                int mb = wm + i*16;
                a[i][0] = *reinterpret_cast<const uint32_t*>(&Xs[(mb+g  )*xst + kx+tg  ]);
                a[i][1] = *reinterpret_cast<const uint32_t*>(&Xs[(mb+8+g)*xst + kx+tg  ]);
                a[i][2] = *reinterpret_cast<const uint32_t*>(&Xs[(mb+g  )*xst + kx+8+tg]);
                a[i][3] = *reinterpret_cast<const uint32_t*>(&Xs[(mb+8+g)*xst + kx+8+tg]);
            }
#pragma unroll
            for (int j = 0; j < 4; j++) {
                uint32_t b0 = *reinterpret_cast<const uint32_t*>(&Bs[(wn+j*8+g)*136 + kb+tg  ]);
                uint32_t b1 = *reinterpret_cast<const uint32_t*>(&Bs[(wn+j*8+g)*136 + kb+8+tg]);
                mma16816(acc[0][j], a[0], b0, b1);
                mma16816(acc[1][j], a[1], b0, b1);
            }
        }
        __syncthreads();
    }
}

// LN over 64x128 fragment values v -> fp16 Xs (local rows, stride xst)
__device__ __forceinline__ void ln_to_smem(
        float v[2][4][4], __half* Xs, int xst, float* sred,
        int warp, int lane, int wm, int wn, int g, int tg) {
    float sum[2][2] = {{0,0},{0,0}}, sq[2][2] = {{0,0},{0,0}};
#pragma unroll
    for (int i = 0; i < 2; i++)
#pragma unroll
    for (int j = 0; j < 4; j++) {
        float a0 = v[i][j][0], a1 = v[i][j][1];
        float a2 = v[i][j][2], a3 = v[i][j][3];
        sum[i][0] += a0 + a1; sq[i][0] += a0*a0 + a1*a1;
        sum[i][1] += a2 + a3; sq[i][1] += a2*a2 + a3*a3;
    }
#pragma unroll
    for (int o = 1; o <= 2; o <<= 1) {
#pragma unroll
        for (int i = 0; i < 2; i++)
#pragma unroll
        for (int rh = 0; rh < 2; rh++) {
            sum[i][rh] += __shfl_xor_sync(0xffffffffu, sum[i][rh], o);
            sq[i][rh]  += __shfl_xor_sync(0xffffffffu, sq[i][rh], o);
        }
    }
    if ((lane & 3) == 0) {
#pragma unroll
        for (int i = 0; i < 2; i++)
#pragma unroll
        for (int rh = 0; rh < 2; rh++) {
            int row = wm + i*16 + rh*8 + g;
            sred[row*8 + (warp >> 1)*2 + 0] = sum[i][rh];
            sred[row*8 + (warp >> 1)*2 + 1] = sq[i][rh];
        }
    }
    __syncthreads();
#pragma unroll
    for (int i = 0; i < 2; i++)
#pragma unroll
    for (int rh = 0; rh < 2; rh++) {
        int row = wm + i*16 + rh*8 + g;
        float s = sred[row*8+0] + sred[row*8+2] + sred[row*8+4] + sred[row*8+6];
        float qq = sred[row*8+1] + sred[row*8+3] + sred[row*8+5] + sred[row*8+7];
        float mean = s*(1.0f/128.0f);
        float var = fmaxf(qq*(1.0f/128.0f) - mean*mean, 0.f);
        float rstd = rsqrtf(var + 1e-5f);
#pragma unroll
        for (int j = 0; j < 4; j++) {
            int n = wn + j*8 + tg;
            *reinterpret_cast<uint32_t*>(&Xs[row*xst + n]) =
                packh2((v[i][j][rh*2+0]-mean)*rstd, (v[i][j][rh*2+1]-mean)*rstd);
        }
    }
}

// ---------------- fused stage kernel: proj+skip+LN -> MLP -> (Q2 | final) ----
template<int STAGE>
__global__ void __launch_bounds__(256) k_stage(
        const float* __restrict__ x,
        const float* __restrict__ abp_s,
        const float* __restrict__ bmb_s,
        const float* __restrict__ postg, const float* __restrict__ postb,
        float* __restrict__ out) {
    extern __shared__ __half shh[];
    __half* Xs = shh;                       // [64][136]
    __half* Bs = shh + 8704;                // [128][136]
    __half* Hs = shh + 8704 + 17408;        // [64][264]
    float* sred = reinterpret_cast<float*>(shh + 8704 + 17408 + 16896);  // [64][8]
    int tid = threadIdx.x;
    int warp = tid >> 5, lane = tid & 31;
    int wm = (warp & 1) * 32, wn = (warp >> 1) * 32;
    int g = lane >> 2, tg = (lane & 3) * 2;
    int m0 = blockIdx.x * 64;
    int r = tid >> 4, q = tid & 15;

    // ---- Phase 0: A tile into Xs ----
    if (STAGE == 0) {
        for (int rr = r; rr < 64; rr += 16) {
            int row = m0 + rr;
            int b = row >> 12, p = row & 4095;
            int hh_ = p >> 6, ww = p & 63;
            int l = ((hh_ >> 3) << 3) + (ww >> 3);
            const __half* src = g_otok + ((b*64 + l)*NQ1 + (hh_&7)*8 + (ww&7))*D_ + q*8;
            float s[8];
#pragma unroll
            for (int t = 0; t < 8; t++) s[t] = 0.f;
#pragma unroll
            for (int n = 0; n < 6; n++) {
                const __half2* pp = reinterpret_cast<const __half2*>(src + n*64*D_);
#pragma unroll
                for (int t = 0; t < 4; t++) {
                    float2 f = __half22float2(pp[t]);
                    s[t*2] += f.x; s[t*2+1] += f.y;
                }
            }
            __half2 o[4];
#pragma unroll
            for (int t = 0; t < 4; t++)
                o[t] = __floats2half2_rn(s[t*2]*(1.f/6.f), s[t*2+1]*(1.f/6.f));
            *reinterpret_cast<int4*>(&Xs[rr*136 + q*8]) = *reinterpret_cast<int4*>(o);
        }
    } else {
        for (int rr = r; rr < 64; rr += 16)
            cpa16(&Xs[rr*136 + q*8], &g_o2[(m0+rr)*128 + q*8]);
        asm volatile("cp.async.commit_group;\n");
        asm volatile("cp.async.wait_group 0;\n");
    }
    __syncthreads();

    float acc[2][4][4], res[2][4][4];

    // ---- Phase 1: attn-out projection + bias + skip -> res; LN -> Xs ----
    tile_gemm(Xs, 136, (STAGE == 0) ? g_wpT : g_wpT + 16384, 128, 1,
              Bs, acc, tid, wm, wn, g, tg);
#pragma unroll
    for (int i = 0; i < 2; i++)
#pragma unroll
    for (int j = 0; j < 4; j++) {
        int n = wn + j*8 + tg;
        int r0 = m0 + wm + i*16 + g, r1 = r0 + 8;
        float b0 = abp_s[n], b1 = abp_s[n+1];
        float s00, s01, s10, s11;
        if (STAGE == 0) {
            int ba = r0 >> 12, pa = r0 & 4095;
            int bb_ = r1 >> 12, pb = r1 & 4095;
            s00 = x[(ba*D_ + n  )*4096 + pa];
            s01 = x[(ba*D_ + n+1)*4096 + pa];
            s10 = x[(bb_*D_ + n  )*4096 + pb];
            s11 = x[(bb_*D_ + n+1)*4096 + pb];
        } else {
            s00 = g_q1[r0*D_ + n];   s01 = g_q1[r0*D_ + n+1];
            s10 = g_q1[r1*D_ + n];   s11 = g_q1[r1*D_ + n+1];
        }
        res[i][j][0] = acc[i][j][0] + b0 + s00;
        res[i][j][1] = acc[i][j][1] + b1 + s01;
        res[i][j][2] = acc[i][j][2] + b0 + s10;
        res[i][j][3] = acc[i][j][3] + b1 + s11;
    }
    ln_to_smem(res, Xs, 136, sred, warp, lane, wm, wn, g, tg);
    __syncthreads();

    // ---- Phase 2: GELU GEMMs -> Hs (64x256) ----
    const __half* wa = g_wafold + STAGE*32768;
    const float* bafo = g_bafold + STAGE*256;
#pragma unroll
    for (int half = 0; half < 2; half++) {
        tile_gemm(Xs, 136, wa + half*16384, 128, 1, Bs, acc, tid, wm, wn, g, tg);
#pragma unroll
        for (int i = 0; i < 2; i++)
#pragma unroll
        for (int j = 0; j < 4; j++) {
            int n = wn + j*8 + tg;
            float b0 = bafo[half*128 + n], b1 = bafo[half*128 + n+1];
            int lr0 = wm + i*16 + g, lr1 = lr0 + 8;
            *reinterpret_cast<uint32_t*>(&Hs[lr0*264 + half*128 + n]) =
                packh2(geluf(acc[i][j][0]+b0), geluf(acc[i][j][1]+b1));
            *reinterpret_cast<uint32_t*>(&Hs[lr1*264 + half*128 + n]) =
                packh2(geluf(acc[i][j][2]+b0), geluf(acc[i][j][3]+b1));
        }
    }
    __syncthreads();

    // ---- Phase 3: K=256 GEMM + bias + residual ----
    tile_gemm(Hs, 264, g_wmbT + STAGE*32768, 256, 2, Bs, acc, tid, wm, wn, g, tg);
#pragma unroll
    for (int i = 0; i < 2; i++)
#pragma unroll
    for (int j = 0; j < 4; j++) {
        int n = wn + j*8 + tg;
        float b0 = bmb_s[n], b1 = bmb_s[n+1];
        acc[i][j][0] += b0 + res[i][j][0];
        acc[i][j][1] += b1 + res[i][j][1];
        acc[i][j][2] += b0 + res[i][j][2];
        acc[i][j][3] += b1 + res[i][j][3];
    }
    if (STAGE == 0) {
        // store q1 fp32 (skip for stage 2), LN -> Xs (xq1)
#pragma unroll
        for (int i = 0; i < 2; i++)
#pragma unroll
        for (int j = 0; j < 4; j++) {
            int n = wn + j*8 + tg;
            int r0 = m0 + wm + i*16 + g, r1 = r0 + 8;
            g_q1[r0*D_ + n]   = acc[i][j][0];
            g_q1[r0*D_ + n+1] = acc[i][j][1];
            g_q1[r1*D_ + n]   = acc[i][j][2];
            g_q1[r1*D_ + n+1] = acc[i][j][3];
        }
        ln_to_smem(acc, Xs, 136, sred, warp, lane, wm, wn, g, tg);
        __syncthreads();
        // ---- Phase 4: Q2 projection -> g_qh2 ----
        tile_gemm(Xs, 136, g_wfold + 3*16384, 128, 1, Bs, acc, tid, wm, wn, g, tg);
        const float QS = 0.17677669529663687f;
#pragma unroll
        for (int i = 0; i < 2; i++)
#pragma unroll
        for (int j = 0; j < 4; j++) {
            int n = wn + j*8 + tg;
            float b0 = g_bfold[384 + n], b1 = g_bfold[384 + n+1];
            int r0 = m0 + wm + i*16 + g, r1 = r0 + 8;
            *reinterpret_cast<uint32_t*>(&g_qh2[r0*128 + n]) =
                packh2((acc[i][j][0]+b0)*QS, (acc[i][j][1]+b1)*QS);
            *reinterpret_cast<uint32_t*>(&g_qh2[r1*128 + n]) =
                packh2((acc[i][j][2]+b0)*QS, (acc[i][j][3]+b1)*QS);
        }
    } else {
        // final LN + gamma/beta + transposed store to out
        float sum[2][2] = {{0,0},{0,0}}, sq[2][2] = {{0,0},{0,0}};
#pragma unroll
        for (int i = 0; i < 2; i++)
#pragma unroll
        for (int j = 0; j < 4; j++) {
            float a0 = acc[i][j][0], a1 = acc[i][j][1];
            float a2 = acc[i][j][2], a3 = acc[i][j][3];
            sum[i][0] += a0 + a1; sq[i][0] += a0*a0 + a1*a1;
            sum[i][1] += a2 + a3; sq[i][1] += a2*a2 + a3*a3;
        }
#pragma unroll
        for (int o = 1; o <= 2; o <<= 1) {
#pragma unroll
            for (int i = 0; i < 2; i++)
#pragma unroll
            for (int rh = 0; rh < 2; rh++) {
                sum[i][rh] += __shfl_xor_sync(0xffffffffu, sum[i][rh], o);
                sq[i][rh]  += __shfl_xor_sync(0xffffffffu, sq[i][rh], o);
            }
        }
        if ((lane & 3) == 0) {
#pragma unroll
            for (int i = 0; i < 2; i++)
#pragma unroll
            for (int rh = 0; rh < 2; rh++) {
                int row = wm + i*16 + rh*8 + g;
                sred[row*8 + (warp >> 1)*2 + 0] = sum[i][rh];
                sred[row*8 + (warp >> 1)*2 + 1] = sq[i][rh];
            }
        }
        __syncthreads();
#pragma unroll
        for (int i = 0; i < 2; i++)
#pragma unroll
        for (int rh = 0; rh < 2; rh++) {
            int row = wm + i*16 + rh*8 + g;
            float s = sred[row*8+0] + sred[row*8+2] + sred[row*8+4] + sred[row*8+6];
            float qq = sred[row*8+1] + sred[row*8+3] + sred[row*8+5] + sred[row*8+7];
            float mean = s*(1.0f/128.0f);
            float var = fmaxf(qq*(1.0f/128.0f) - mean*mean, 0.f);
            float rstd = rsqrtf(var + 1e-5f);
            int grow = m0 + row;
            int b = grow >> 12, p = grow & 4095;
#pragma unroll
            for (int j = 0; j < 4; j++) {
                int n = wn + j*8 + tg;
                out[(b*D_ + n  )*4096 + p] =
                    (acc[i][j][rh*2+0]-mean)*rstd*postg[n]   + postb[n];
                out[(b*D_ + n+1)*4096 + p] =
                    (acc[i][j][rh*2+1]-mean)*rstd*postg[n+1] + postb[n+1];
            }
        }
    }
}

// ---------------- tensor-core flash attention (fp16 in / fp16 out) -----------
template<int MT, int NW>
__global__ void __launch_bounds__(NW*32) k_attn_mma(int stage) {
    const int NQ = MT*16*NW;
    extern __shared__ __half sha[];
    __half* Qs = sha;                  // [NQ][40]
    __half* Ks = Qs + NQ*40;           // [264][40]
    __half* Vt = Ks + 264*40;          // [32][274]
    int bl = blockIdx.x, hh = blockIdx.y, tid = threadIdx.x;
    int b = bl >> 6, l = bl & 63;
    const __half* qsrc; const __half* ksrc; const __half* vsrc;
    if (stage == 0) { qsrc = g_qh1; ksrc = g_kh1; vsrc = g_vh1; }
    else            { qsrc = g_qh2; ksrc = g_kh2; vsrc = g_vh2; }
    for (int idx = tid; idx < NQ*16; idx += NW*32) {
        int row = idx >> 4, c2 = idx & 15;
        int pix;
        if (stage == 0) {
            int n = row >> 6, ij = row & 63;
            pix = (b*N_+n)*4096 + ((l>>3)*8 + (ij>>3))*64 + (l&7)*8 + (ij&7);
        } else {
            pix = b*4096 + ((l>>3)*8 + (row>>3))*64 + (l&7)*8 + (row&7);
        }
        *reinterpret_cast<uint32_t*>(&Qs[row*40 + 2*c2]) =
            *reinterpret_cast<const uint32_t*>(&qsrc[pix*D_ + hh*32 + 2*c2]);
    }
    for (int idx = tid; idx < NKV*16; idx += NW*32) {
        int kv = idx >> 4, c2 = idx & 15;
        int n = kv/44, f = kv%44, f1 = f/11, f2 = f%11;
        int h, w;
        if (stage == 0) { h = (l>>3)*4 + f1; w = (l&7)*11 + f2; }
        else            { h = f1*8 + (l>>3); w = f2*8 + (l&7); }
        int pix = (b*N_+n)*PIX + h*FW_ + w;
        *reinterpret_cast<uint32_t*>(&Ks[kv*40 + 2*c2]) =
            *reinterpret_cast<const uint32_t*>(&ksrc[pix*D_ + hh*32 + 2*c2]);
    }
    for (int idx = tid; idx < NKV*32; idx += NW*32) {
        int kv = idx >> 5, ch = idx & 31;
        int n = kv/44, f = kv%44, f1 = f/11, f2 = f%11;
        int h, w;
        if (stage == 0) { h = (l>>3)*4 + f1; w = (l&7)*11 + f2; }
        else            { h = f1*8 + (l>>3); w = f2*8 + (l&7); }
        int pix = (b*N_+n)*PIX + h*FW_ + w;
        Vt[ch*274 + kv] = vsrc[pix*D_ + hh*32 + ch];
    }
    for (int idx = tid; idx < 32*10; idx += NW*32) {
        int ch = idx / 10, c = idx % 10;
        Vt[ch*274 + 264 + c] = __half(0.f);
    }
    __syncthreads();

    int warp = tid >> 5, lane = tid & 31;
    int g = lane >> 2, t4 = lane & 3;
    int row0 = warp * MT * 16;

    uint32_t af[MT][2][4];
#pragma unroll
    for (int mt = 0; mt < MT; mt++)
#pragma unroll
        for (int ks = 0; ks < 2; ks++) {
            int r = row0 + mt*16, k0 = ks*16;
            af[mt][ks][0] = *reinterpret_cast<const uint32_t*>(&Qs[(r+g  )*40 + k0 + 2*t4    ]);
            af[mt][ks][1] = *reinterpret_cast<const uint32_t*>(&Qs[(r+8+g)*40 + k0 + 2*t4    ]);
            af[mt][ks][2] = *reinterpret_cast<const uint32_t*>(&Qs[(r+g  )*40 + k0 + 8 + 2*t4]);
            af[mt][ks][3] = *reinterpret_cast<const uint32_t*>(&Qs[(r+8+g)*40 + k0 + 8 + 2*t4]);
        }

    float m[MT][2], lsum[MT][2], O[MT][4][4];
#pragma unroll
    for (int mt = 0; mt < MT; mt++) {
        m[mt][0] = -1e30f; m[mt][1] = -1e30f;
        lsum[mt][0] = 0.f; lsum[mt][1] = 0.f;
#pragma unroll
        for (int j = 0; j < 4; j++)
#pragma unroll
            for (int r = 0; r < 4; r++) O[mt][j][r] = 0.f;
    }

    for (int c = 0; c < 17; c++) {
        int kv0 = c*16;
        int nt = (c == 16) ? 1 : 2;
        uint32_t bf[2][2][2];
#pragma unroll
        for (int n = 0; n < 2; n++) {
            if (n < nt) {
#pragma unroll
                for (int ks = 0; ks < 2; ks++) {
                    bf[n][ks][0] = *reinterpret_cast<const uint32_t*>(&Ks[(kv0+n*8+g)*40 + ks*16 + 2*t4    ]);
                    bf[n][ks][1] = *reinterpret_cast<const uint32_t*>(&Ks[(kv0+n*8+g)*40 + ks*16 + 8 + 2*t4]);
                }
            }
        }
        float S[MT][2][4];
#pragma unroll
        for (int mt = 0; mt < MT; mt++)
#pragma unroll
            for (int n = 0; n < 2; n++)
#pragma unroll
                for (int r = 0; r < 4; r++) S[mt][n][r] = 0.f;
#pragma unroll
        for (int mt = 0; mt < MT; mt++)
#pragma unroll
            for (int n = 0; n < 2; n++) {
                if (n < nt) {
                    mma16816(S[mt][n], af[mt][0], bf[n][0][0], bf[n][0][1]);
                    mma16816(S[mt][n], af[mt][1], bf[n][1][0], bf[n][1][1]);
                }
            }
#pragma unroll
        for (int mt = 0; mt < MT; mt++) {
            float mx0 = fmaxf(S[mt][0][0], S[mt][0][1]);
            float mx8 = fmaxf(S[mt][0][2], S[mt][0][3]);
            if (nt == 2) {
                mx0 = fmaxf(mx0, fmaxf(S[mt][1][0], S[mt][1][1]));
                mx8 = fmaxf(mx8, fmaxf(S[mt][1][2], S[mt][1][3]));
            }
            mx0 = fmaxf(mx0, __shfl_xor_sync(0xffffffffu, mx0, 1));
            mx0 = fmaxf(mx0, __shfl_xor_sync(0xffffffffu, mx0, 2));
            mx8 = fmaxf(mx8, __shfl_xor_sync(0xffffffffu, mx8, 1));
            mx8 = fmaxf(mx8, __shfl_xor_sync(0xffffffffu, mx8, 2));
            float mn0 = fmaxf(m[mt][0], mx0), mn8 = fmaxf(m[mt][1], mx8);
            float cr0 = __expf(m[mt][0] - mn0), cr8 = __expf(m[mt][1] - mn8);
            m[mt][0] = mn0; m[mt][1] = mn8;
            uint32_t pa[4];
            float p00 = __expf(S[mt][0][0] - mn0), p01 = __expf(S[mt][0][1] - mn0);
            float p02 = __expf(S[mt][0][2] - mn8), p03 = __expf(S[mt][0][3] - mn8);
            float rs0 = p00 + p01, rs8 = p02 + p03;
            pa[0] = packh2(p00, p01);
            pa[1] = packh2(p02, p03);
            if (nt == 2) {
                float p10 = __expf(S[mt][1][0] - mn0), p11 = __expf(S[mt][1][1] - mn0);
                float p12 = __expf(S[mt][1][2] - mn8), p13 = __expf(S[mt][1][3] - mn8);
                rs0 += p10 + p11; rs8 += p12 + p13;
                pa[2] = packh2(p10, p11);
                pa[3] = packh2(p12, p13);
            } else { pa[2] = 0u; pa[3] = 0u; }
            rs0 += __shfl_xor_sync(0xffffffffu, rs0, 1);
            rs0 += __shfl_xor_sync(0xffffffffu, rs0, 2);
            rs8 += __shfl_xor_sync(0xffffffffu, rs8, 1);
            rs8 += __shfl_xor_sync(0xffffffffu, rs8, 2);
            lsum[mt][0] = lsum[mt][0]*cr0 + rs0;
            lsum[mt][1] = lsum[mt][1]*cr8 + rs8;
#pragma unroll
            for (int j = 0; j < 4; j++) {
                O[mt][j][0] *= cr0; O[mt][j][1] *= cr0;
                O[mt][j][2] *= cr8; O[mt][j][3] *= cr8;
                uint32_t vb0 = *reinterpret_cast<const uint32_t*>(&Vt[(j*8+g)*274 + kv0 + 2*t4    ]);
                uint32_t vb1 = *reinterpret_cast<const uint32_t*>(&Vt[(j*8+g)*274 + kv0 + 8 + 2*t4]);
                mma16816(O[mt][j], pa, vb0, vb1);
            }
        }
    }
#pragma unroll
    for (int mt = 0; mt < MT; mt++) {
        float i0 = 1.0f / lsum[mt][0], i8 = 1.0f / lsum[mt][1];
        int r0 = row0 + mt*16 + g;
        int r1 = r0 + 8;
        int out0, out1;
        if (stage == 0) {
            out0 = bl*NQ + r0;
            out1 = bl*NQ + r1;
        } else {
            out0 = b*4096 + ((l>>3)*8 + (r0>>3))*64 + (l&7)*8 + (r0&7);
            out1 = b*4096 + ((l>>3)*8 + (r1>>3))*64 + (l&7)*8 + (r1&7);
        }
        __half* Od = (stage == 0) ? g_otok : g_o2;
#pragma unroll
        for (int j = 0; j < 4; j++) {
            int chn = hh*32 + j*8 + 2*t4;
            *reinterpret_cast<uint32_t*>(&Od[out0*D_ + chn]) = packh2(O[mt][j][0]*i0, O[mt][j][1]*i0);
            *reinterpret_cast<uint32_t*>(&Od[out1*D_ + chn]) = packh2(O[mt][j][2]*i8, O[mt][j][3]*i8);
        }
    }
}

// ---------------------------------------------------------------------------
extern "C" void kernel_launch(void* const* d_in, const int* in_sizes, int n_in,
                              void* d_out, int out_size) {
    (void)in_sizes; (void)n_in; (void)out_size;
    const float* x        = (const float*)d_in[1];
    const float* grid     = (const float*)d_in[2];
    const float* feature  = (const float*)d_in[3];
    const float* I_inv    = (const float*)d_in[4];
    const float* E_inv    = (const float*)d_in[5];
    const float* bn_fl_g  = (const float*)d_in[6];
    const float* bn_fl_b  = (const float*)d_in[7];
    const float* W_fl     = (const float*)d_in[8];
    const float* bn_fp_g  = (const float*)d_in[9];
    const float* bn_fp_b  = (const float*)d_in[10];
    const float* W_fp     = (const float*)d_in[11];
    const float* W_bev    = (const float*)d_in[12];
    const float* b_bev    = (const float*)d_in[13];
    const float* W_img    = (const float*)d_in[14];
    const float* W_cam    = (const float*)d_in[15];
    const float* aln_g    = (const float*)d_in[16];
    const float* aln_b    = (const float*)d_in[17];
    const float* aWqkv    = (const float*)d_in[18];
    const float* abqkv    = (const float*)d_in[19];
    const float* aWp      = (const float*)d_in[20];
    const float* abp      = (const float*)d_in[21];
    const float* pn_g     = (const float*)d_in[22];
    const float* pn_b     = (const float*)d_in[23];
    const float* Wma      = (const float*)d_in[24];
    const float* bma      = (const float*)d_in[25];
    const float* Wmb      = (const float*)d_in[26];
    const float* bmb      = (const float*)d_in[27];
    const float* post_g   = (const float*)d_in[28];
    const float* post_b   = (const float*)d_in[29];
    float* out = (float*)d_out;

    const int GSM = (64*136 + 128*136) * 2;              // 52224
    const int SSM = (8704 + 17408 + 16896) * 2 + 2048;   // 88064
    const int PSM = 2*128*33*4 + 32*128*4;               // 50176
    const int A1SM = (384*40 + 264*40 + 32*274) * 2;     // 69376
    const int A2SM = (64*40 + 264*40 + 32*274) * 2;      // 43776
    cudaFuncSetAttribute(k_prep, cudaFuncAttributeMaxDynamicSharedMemorySize, PSM);
    cudaFuncSetAttribute(k_gemm_ep, cudaFuncAttributeMaxDynamicSharedMemorySize, GSM);
    cudaFuncSetAttribute(k_stage<0>, cudaFuncAttributeMaxDynamicSharedMemorySize, SSM);
    cudaFuncSetAttribute(k_stage<1>, cudaFuncAttributeMaxDynamicSharedMemorySize, SSM);
    cudaFuncSetAttribute(k_attn_mma<3,8>, cudaFuncAttributeMaxDynamicSharedMemorySize, A1SM);
    cudaFuncSetAttribute(k_attn_mma<1,4>, cudaFuncAttributeMaxDynamicSharedMemorySize, A2SM);

    // prep (weights + activations)
    k_wprep<<<304, 256>>>(aln_g, aln_b, aWqkv, abqkv, pn_g, pn_b, Wma, bma,
                          aWp, Wmb, W_fp, W_fl);
    k_prep<<<B_*N_*88, 128, PSM>>>(feature, I_inv, E_inv, W_img, W_cam,
                                   bn_fp_g, bn_fp_b, bn_fl_g, bn_fl_b);
    k_query<<<NQP/8, 256>>>(grid, x, W_bev, b_bev, E_inv, W_cam);

    // conv GEMMs (jobs 0,1) then all 5 QKV projections (jobs 2..6)
    k_gemm_ep<<<1056, 256, GSM>>>(100);
    k_gemm_ep<<<2880, 256, GSM>>>(101);

    // stage 1: attention + fused (mean+proj+skip+LN -> MLP -> Q2 proj)
    k_attn_mma<3,8><<<dim3(B_*64, 4), 256, A1SM>>>(0);
    k_stage<0><<<NTK/64, 256, SSM>>>(x, abp, bmb, nullptr, nullptr, nullptr);

    // stage 2: attention + fused (proj+skip+LN -> MLP -> final LN -> out)
    k_attn_mma<1,4><<<dim3(B_*64, 4), 128, A2SM>>>(1);
    k_stage<1><<<NTK/64, 256, SSM>>>(nullptr, abp + 128, bmb + 128,
                                     post_g, post_b, out);
}